// round 2
// baseline (speedup 1.0000x reference)
#include <cuda_runtime.h>
#include <math.h>

#define B_   16
#define L_   1024
#define IN_  32
#define D_   256
#define H_   8
#define NL_  2
#define DFF_ 1024
#define DH_  32
#define BL_  (B_*L_)

// ---------------- scratch (device globals; no allocation) ----------------
__device__ float g_x[BL_*D_];        // activations [B*L, D]
__device__ float g_qkv[BL_*3*D_];    // qkv [B*L, 768]
__device__ float g_o[BL_*D_];        // attention out
__device__ float g_p[BL_*D_];        // projection / ff2 out (residual source)
__device__ float g_h[BL_*DFF_];      // ff hidden
__device__ float g_t[BL_];           // cumsum times
__device__ int g_mask_mode;          // 0 = 1-byte elements, 1 = 4-byte elements
__device__ unsigned char g_mask[BL_];// normalized 0/1 mask

// ---------------- mask dtype detection ----------------
// Scans words covering bytes [0, 16384) — in-bounds for any candidate dtype
// (bool: 16384B total; int32/float32: 65536B total).
// 4-byte storage of a 0/1 mask only ever yields words {0, 1, 0x3F800000}.
// 1-byte storage yields words with multiple nonzero bytes (mask rows end in
// runs of 1-bytes => 0x01010101 etc.), flagged here.
__global__ void mask_detect_kernel(const unsigned int* __restrict__ mraw) {
  __shared__ int bad;
  if (threadIdx.x == 0) bad = 0;
  __syncthreads();
  for (int k = threadIdx.x; k < BL_/4; k += blockDim.x) {
    unsigned int v = mraw[k];
    if (v != 0u && v != 1u && v != 0x3F800000u) atomicOr(&bad, 1);
  }
  __syncthreads();
  if (threadIdx.x == 0) g_mask_mode = bad ? 0 : 1;
}

__global__ void mask_convert_kernel(const void* __restrict__ mraw) {
  int j = blockIdx.x * blockDim.x + threadIdx.x;
  if (j >= BL_) return;
  unsigned char m;
  if (g_mask_mode == 1) {
    m = (((const unsigned int*)mraw)[j] != 0u) ? 1 : 0;   // int32 or float32 bits
  } else {
    m = (((const unsigned char*)mraw)[j] != 0) ? 1 : 0;   // bool bytes
  }
  g_mask[j] = m;
}

// ---------------- embed: x = feat @ in_w^T + in_b + pe ----------------
__global__ __launch_bounds__(256) void embed_kernel(
    const float* __restrict__ feat, const float* __restrict__ pe,
    const float* __restrict__ in_w, const float* __restrict__ in_b) {
  int row = blockIdx.x;           // b*L + l
  int l = row & (L_-1);
  int d = threadIdx.x;
  __shared__ float fs[IN_];
  if (d < IN_) fs[d] = feat[row*IN_ + d];
  __syncthreads();
  const float4* w4 = (const float4*)(in_w + d*IN_);
  float s = in_b[d];
#pragma unroll
  for (int k4 = 0; k4 < IN_/4; k4++) {
    float4 w = w4[k4];
    s += fs[k4*4+0]*w.x + fs[k4*4+1]*w.y + fs[k4*4+2]*w.z + fs[k4*4+3]*w.w;
  }
  g_x[row*D_ + d] = s + pe[l*D_ + d];
}

// ---------------- cumsum of delta_t (features[:,:,IN-2]) ----------------
__global__ void cumsum_kernel(const float* __restrict__ feat) {
  int b = blockIdx.x;
  __shared__ float sd[L_];
  for (int l = threadIdx.x; l < L_; l += blockDim.x)
    sd[l] = feat[(b*L_ + l)*IN_ + (IN_-2)];
  __syncthreads();
  if (threadIdx.x == 0) {
    float s = 0.f;
    for (int l = 0; l < L_; l++) { s += sd[l]; sd[l] = s; }
  }
  __syncthreads();
  for (int l = threadIdx.x; l < L_; l += blockDim.x)
    g_t[b*L_ + l] = sd[l];
}

// ---------------- generic GEMM: C[M,N] = A[M,K] @ W[N,K]^T + bias, opt relu
// BM=BN=64, BK=16, 256 threads, 4x4 microtile
template<bool RELU>
__global__ __launch_bounds__(256) void gemm_kernel(
    const float* __restrict__ A, const float* __restrict__ W,
    const float* __restrict__ bias, float* __restrict__ C,
    int N, int K) {
  __shared__ float As[16][64];
  __shared__ float Ws[16][64];
  int tid = threadIdx.x;
  int tx = tid & 15, ty = tid >> 4;
  int m0 = blockIdx.y * 64, n0 = blockIdx.x * 64;
  int lr = tid >> 2;               // 0..63
  int lk = (tid & 3) * 4;          // 0,4,8,12
  const float* Ap = A + (m0+lr)*K + lk;
  const float* Wp = W + (n0+lr)*K + lk;
  float acc[4][4] = {};
  for (int k0 = 0; k0 < K; k0 += 16) {
    float4 av = *(const float4*)(Ap + k0);
    float4 wv = *(const float4*)(Wp + k0);
    As[lk+0][lr]=av.x; As[lk+1][lr]=av.y; As[lk+2][lr]=av.z; As[lk+3][lr]=av.w;
    Ws[lk+0][lr]=wv.x; Ws[lk+1][lr]=wv.y; Ws[lk+2][lr]=wv.z; Ws[lk+3][lr]=wv.w;
    __syncthreads();
#pragma unroll
    for (int kk = 0; kk < 16; kk++) {
      float4 a = *(const float4*)&As[kk][ty*4];
      float4 w = *(const float4*)&Ws[kk][tx*4];
      float am0=a.x, am1=a.y, am2=a.z, am3=a.w;
      float wm0=w.x, wm1=w.y, wm2=w.z, wm3=w.w;
      acc[0][0]+=am0*wm0; acc[0][1]+=am0*wm1; acc[0][2]+=am0*wm2; acc[0][3]+=am0*wm3;
      acc[1][0]+=am1*wm0; acc[1][1]+=am1*wm1; acc[1][2]+=am1*wm2; acc[1][3]+=am1*wm3;
      acc[2][0]+=am2*wm0; acc[2][1]+=am2*wm1; acc[2][2]+=am2*wm2; acc[2][3]+=am2*wm3;
      acc[3][0]+=am3*wm0; acc[3][1]+=am3*wm1; acc[3][2]+=am3*wm2; acc[3][3]+=am3*wm3;
    }
    __syncthreads();
  }
#pragma unroll
  for (int i = 0; i < 4; i++) {
    int m = m0 + ty*4 + i;
#pragma unroll
    for (int j = 0; j < 4; j++) {
      int n = n0 + tx*4 + j;
      float v = acc[i][j] + bias[n];
      if (RELU) v = fmaxf(v, 0.f);
      C[m*N + n] = v;
    }
  }
}

// ---------------- attention: warp-per-row, two-pass, time bias + mask ----
// grid (L/16, B*H), 512 threads = 16 warps
#define AT_JC 128
__global__ __launch_bounds__(512) void attn_kernel(
    const float* __restrict__ tw_p, const float* __restrict__ tb_p) {
  __shared__ float kv[AT_JC][44];      // padded: stride 44 floats (conflict-free f4)
  __shared__ float ts[AT_JC];
  __shared__ unsigned char ms[AT_JC];
  int bh = blockIdx.y;
  int b = bh >> 3, h = bh & 7;
  int warp = threadIdx.x >> 5, lane = threadIdx.x & 31;
  int i = blockIdx.x * 16 + warp;
  int row = b*L_ + i;
  float tw = -fabsf(tw_p[0]);
  float tb = tb_p[0];
  float ti = g_t[row];
  const float scale = 0.17677669529663687f;   // 1/sqrt(32)

  float4 q[8];
  const float4* qp = (const float4*)(g_qkv + row*(3*D_) + h*DH_);
#pragma unroll
  for (int d4 = 0; d4 < 8; d4++) q[d4] = qp[d4];

  float sc[32];

  // ---- pass 1: scores ----
  for (int c = 0; c < L_/AT_JC; c++) {
    int j0 = c*AT_JC;
    {
      int idx = threadIdx.x * 2;
#pragma unroll
      for (int r = 0; r < 2; r++, idx++) {
        int jr = idx >> 3, c4 = idx & 7;
        float4 v = *(const float4*)(g_qkv + (b*L_ + j0 + jr)*(3*D_) + D_ + h*DH_ + c4*4);
        *(float4*)&kv[jr][c4*4] = v;
      }
      if (threadIdx.x < AT_JC) {
        ts[threadIdx.x] = g_t[b*L_ + j0 + threadIdx.x];
        ms[threadIdx.x] = g_mask[b*L_ + j0 + threadIdx.x];
      }
    }
    __syncthreads();
#pragma unroll
    for (int sub = 0; sub < 4; sub++) {
      int jj = sub*32 + lane;
      float dot = 0.f;
#pragma unroll
      for (int d4 = 0; d4 < 8; d4++) {
        float4 kk = *(const float4*)&kv[jj][d4*4];
        dot += q[d4].x*kk.x + q[d4].y*kk.y + q[d4].z*kk.z + q[d4].w*kk.w;
      }
      float gap = ti - ts[jj];
      float s = dot*scale + tw*log1pf(fabsf(gap)) + tb;
      if (ms[jj]) s = -INFINITY;
      sc[c*4 + sub] = s;
    }
    __syncthreads();
  }

  // ---- softmax over the row (32 values/lane * 32 lanes) ----
  float m = -INFINITY;
#pragma unroll
  for (int k = 0; k < 32; k++) m = fmaxf(m, sc[k]);
#pragma unroll
  for (int off = 16; off; off >>= 1) m = fmaxf(m, __shfl_xor_sync(~0u, m, off));
  float sum = 0.f;
#pragma unroll
  for (int k = 0; k < 32; k++) { float e = __expf(sc[k] - m); sc[k] = e; sum += e; }
#pragma unroll
  for (int off = 16; off; off >>= 1) sum += __shfl_xor_sync(~0u, sum, off);
  float inv = 1.f / sum;

  // ---- pass 2: o = P @ V ----
  float acc[32] = {};
  for (int c = 0; c < L_/AT_JC; c++) {
    int j0 = c*AT_JC;
    {
      int idx = threadIdx.x * 2;
#pragma unroll
      for (int r = 0; r < 2; r++, idx++) {
        int jr = idx >> 3, c4 = idx & 7;
        float4 v = *(const float4*)(g_qkv + (b*L_ + j0 + jr)*(3*D_) + 2*D_ + h*DH_ + c4*4);
        *(float4*)&kv[jr][c4*4] = v;
      }
    }
    __syncthreads();
#pragma unroll
    for (int sub = 0; sub < 4; sub++) {
      int jj = sub*32 + lane;
      float p = sc[c*4 + sub];
#pragma unroll
      for (int d4 = 0; d4 < 8; d4++) {
        float4 vv = *(const float4*)&kv[jj][d4*4];
        acc[d4*4+0] += p*vv.x; acc[d4*4+1] += p*vv.y;
        acc[d4*4+2] += p*vv.z; acc[d4*4+3] += p*vv.w;
      }
    }
    __syncthreads();
  }
  // reduce across lanes (each d summed over the 32 j-owners)
#pragma unroll
  for (int d = 0; d < 32; d++) {
#pragma unroll
    for (int off = 16; off; off >>= 1)
      acc[d] += __shfl_xor_sync(~0u, acc[d], off);
  }
  float val = 0.f;
#pragma unroll
  for (int d = 0; d < 32; d++) if (lane == d) val = acc[d];
  g_o[row*D_ + h*DH_ + lane] = val * inv;
}

// ---------------- x = LN(x + r) * g + b ----------------
__global__ __launch_bounds__(256) void add_ln_kernel(
    float* __restrict__ x, const float* __restrict__ r,
    const float* __restrict__ g, const float* __restrict__ bt) {
  int row = blockIdx.x, d = threadIdx.x;
  int lane = d & 31, warp = d >> 5;
  float v = x[row*D_+d] + r[row*D_+d];
  __shared__ float red[8];
  float s = v;
#pragma unroll
  for (int off = 16; off; off >>= 1) s += __shfl_xor_sync(~0u, s, off);
  if (lane == 0) red[warp] = s;
  __syncthreads();
  float tot = 0.f;
#pragma unroll
  for (int w = 0; w < 8; w++) tot += red[w];
  float mean = tot * (1.f/D_);
  float c = v - mean;
  __syncthreads();
  float s2 = c*c;
#pragma unroll
  for (int off = 16; off; off >>= 1) s2 += __shfl_xor_sync(~0u, s2, off);
  if (lane == 0) red[warp] = s2;
  __syncthreads();
  float tot2 = 0.f;
#pragma unroll
  for (int w = 0; w < 8; w++) tot2 += red[w];
  float var = tot2 * (1.f/D_);
  x[row*D_+d] = c * rsqrtf(var + 1e-5f) * g[d] + bt[d];
}

// ---------------- final head: gather last state, 2-layer MLP ----------------
__global__ __launch_bounds__(256) void head_kernel(
    const float* __restrict__ w1, const float* __restrict__ b1,
    const float* __restrict__ w2, const float* __restrict__ b2,
    float* __restrict__ out, int out_size) {
  int b = blockIdx.x, tid = threadIdx.x;
  int lane = tid & 31, warp = tid >> 5;
  __shared__ int cred[8];
  int cnt = 0;
  for (int l = tid; l < L_; l += 256) cnt += (g_mask[b*L_+l] ? 0 : 1);
#pragma unroll
  for (int off = 16; off; off >>= 1) cnt += __shfl_xor_sync(~0u, cnt, off);
  if (lane == 0) cred[warp] = cnt;
  __syncthreads();
  int len = 0;
#pragma unroll
  for (int w = 0; w < 8; w++) len += cred[w];
  int idx = len - 1;
  __shared__ float ls[D_];
  float xv = g_x[(b*L_+idx)*D_ + tid];
  ls[tid] = xv;
  if (16 + b*D_ + tid < out_size)
    out[16 + b*D_ + tid] = xv;        // last_state
  __syncthreads();
  __shared__ float hh[128];
  if (tid < 128) {
    float s = b1[tid];
    const float4* wp = (const float4*)(w1 + tid*D_);
#pragma unroll 8
    for (int k4 = 0; k4 < D_/4; k4++) {
      float4 w = wp[k4];
      s += ls[k4*4+0]*w.x + ls[k4*4+1]*w.y + ls[k4*4+2]*w.z + ls[k4*4+3]*w.w;
    }
    hh[tid] = fmaxf(s, 0.f);
  }
  __syncthreads();
  if (tid < 32) {
    float s = 0.f;
    for (int j = tid; j < 128; j += 32) s += hh[j]*w2[j];
#pragma unroll
    for (int off = 16; off; off >>= 1) s += __shfl_xor_sync(~0u, s, off);
    if (tid == 0) out[b] = s + b2[0];   // predicted_gap
  }
}

// ---------------- host ----------------
extern "C" void kernel_launch(void* const* d_in, const int* in_sizes, int n_in,
                              void* d_out, int out_size) {
  const float* feat  = (const float*)d_in[0];
  const void*  maskraw = d_in[1];
  const float* pe    = (const float*)d_in[2];
  const float* in_w  = (const float*)d_in[3];
  const float* in_b  = (const float*)d_in[4];
  const float* time_w= (const float*)d_in[5];
  const float* time_b= (const float*)d_in[6];
  const float* qkv_w = (const float*)d_in[7];
  const float* qkv_b = (const float*)d_in[8];
  const float* out_w = (const float*)d_in[9];
  const float* out_b = (const float*)d_in[10];
  const float* ln1_g = (const float*)d_in[11];
  const float* ln1_b = (const float*)d_in[12];
  const float* ff1_w = (const float*)d_in[13];
  const float* ff1_b = (const float*)d_in[14];
  const float* ff2_w = (const float*)d_in[15];
  const float* ff2_b = (const float*)d_in[16];
  const float* ln2_g = (const float*)d_in[17];
  const float* ln2_b = (const float*)d_in[18];
  const float* reg1_w= (const float*)d_in[19];
  const float* reg1_b= (const float*)d_in[20];
  const float* reg2_w= (const float*)d_in[21];
  const float* reg2_b= (const float*)d_in[22];
  float* out = (float*)d_out;

  float *px, *pqkv, *po, *pp, *ph;
  cudaGetSymbolAddress((void**)&px,  g_x);
  cudaGetSymbolAddress((void**)&pqkv,g_qkv);
  cudaGetSymbolAddress((void**)&po,  g_o);
  cudaGetSymbolAddress((void**)&pp,  g_p);
  cudaGetSymbolAddress((void**)&ph,  g_h);

  mask_detect_kernel<<<1, 256>>>((const unsigned int*)maskraw);
  mask_convert_kernel<<<BL_/256, 256>>>(maskraw);
  embed_kernel<<<BL_, 256>>>(feat, pe, in_w, in_b);
  cumsum_kernel<<<B_, 256>>>(feat);

  for (int layer = 0; layer < NL_; layer++) {
    // QKV
    gemm_kernel<false><<<dim3(3*D_/64, BL_/64), 256>>>(
        px, qkv_w + layer*3*D_*D_, qkv_b + layer*3*D_, pqkv, 3*D_, D_);
    // attention
    attn_kernel<<<dim3(L_/16, B_*H_), 512>>>(time_w, time_b);
    // out projection
    gemm_kernel<false><<<dim3(D_/64, BL_/64), 256>>>(
        po, out_w + layer*D_*D_, out_b + layer*D_, pp, D_, D_);
    add_ln_kernel<<<BL_, 256>>>(px, pp, ln1_g + layer*D_, ln1_b + layer*D_);
    // FF
    gemm_kernel<true><<<dim3(DFF_/64, BL_/64), 256>>>(
        px, ff1_w + layer*DFF_*D_, ff1_b + layer*DFF_, ph, DFF_, D_);
    gemm_kernel<false><<<dim3(D_/64, BL_/64), 256>>>(
        ph, ff2_w + layer*D_*DFF_, ff2_b + layer*D_, pp, D_, DFF_);
    add_ln_kernel<<<BL_, 256>>>(px, pp, ln2_g + layer*D_, ln2_b + layer*D_);
  }

  head_kernel<<<B_, 256>>>(reg1_w, reg1_b, reg2_w, reg2_b, out, out_size);
}

// round 3
// speedup vs baseline: 3.8971x; 3.8971x over previous
#include <cuda_runtime.h>
#include <math.h>

#define B_   16
#define L_   1024
#define IN_  32
#define D_   256
#define H_   8
#define NL_  2
#define DFF_ 1024
#define DH_  32
#define BL_  (B_*L_)

// ---------------- scratch (device globals; no allocation) ----------------
__device__ float g_x[BL_*D_];        // activations fp32 [B*L, D]
__device__ float g_qkv[BL_*3*D_];    // qkv [B*L, 768]
__device__ float g_o[BL_*D_];        // attention out
__device__ float g_p[BL_*D_];        // residual source
__device__ float g_h[BL_*DFF_];      // ff hidden
__device__ float g_t[BL_];           // cumsum times
__device__ int g_mask_mode;
__device__ unsigned char g_mask[BL_];

// ---------------- tf32 helpers ----------------
__device__ __forceinline__ unsigned tf32c(float f) {
  unsigned u; asm("cvt.rna.tf32.f32 %0, %1;" : "=r"(u) : "f"(f)); return u;
}
__device__ __forceinline__ void mma_tf32(float* d, const unsigned* a,
                                         const unsigned* b, const float* c) {
  asm volatile(
    "mma.sync.aligned.m16n8k8.row.col.f32.tf32.tf32.f32 "
    "{%0,%1,%2,%3},{%4,%5,%6,%7},{%8,%9},{%10,%11,%12,%13};"
    : "=f"(d[0]),"=f"(d[1]),"=f"(d[2]),"=f"(d[3])
    : "r"(a[0]),"r"(a[1]),"r"(a[2]),"r"(a[3]),
      "r"(b[0]),"r"(b[1]),
      "f"(c[0]),"f"(c[1]),"f"(c[2]),"f"(c[3]));
}

// ---------------- mask dtype detection + convert ----------------
__global__ void mask_detect_kernel(const unsigned int* __restrict__ mraw) {
  __shared__ int bad;
  if (threadIdx.x == 0) bad = 0;
  __syncthreads();
  for (int k = threadIdx.x; k < BL_/4; k += blockDim.x) {
    unsigned int v = mraw[k];
    if (v != 0u && v != 1u && v != 0x3F800000u) atomicOr(&bad, 1);
  }
  __syncthreads();
  if (threadIdx.x == 0) g_mask_mode = bad ? 0 : 1;
}
__global__ void mask_convert_kernel(const void* __restrict__ mraw) {
  int j = blockIdx.x * blockDim.x + threadIdx.x;
  if (j >= BL_) return;
  unsigned char m;
  if (g_mask_mode == 1) m = (((const unsigned int*)mraw)[j] != 0u) ? 1 : 0;
  else                  m = (((const unsigned char*)mraw)[j] != 0) ? 1 : 0;
  g_mask[j] = m;
}

// ---------------- embed ----------------
__global__ __launch_bounds__(256) void embed_kernel(
    const float* __restrict__ feat, const float* __restrict__ pe,
    const float* __restrict__ in_w, const float* __restrict__ in_b) {
  int row = blockIdx.x;
  int l = row & (L_-1);
  int d = threadIdx.x;
  __shared__ float fs[IN_];
  if (d < IN_) fs[d] = feat[row*IN_ + d];
  __syncthreads();
  const float4* w4 = (const float4*)(in_w + d*IN_);
  float s = in_b[d];
#pragma unroll
  for (int k4 = 0; k4 < IN_/4; k4++) {
    float4 w = w4[k4];
    s += fs[k4*4+0]*w.x + fs[k4*4+1]*w.y + fs[k4*4+2]*w.z + fs[k4*4+3]*w.w;
  }
  g_x[row*D_ + d] = s + pe[l*D_ + d];
}

// ---------------- cumsum ----------------
__global__ void cumsum_kernel(const float* __restrict__ feat) {
  int b = blockIdx.x;
  __shared__ float sd[L_];
  for (int l = threadIdx.x; l < L_; l += blockDim.x)
    sd[l] = feat[(b*L_ + l)*IN_ + (IN_-2)];
  __syncthreads();
  if (threadIdx.x == 0) {
    float s = 0.f;
    for (int l = 0; l < L_; l++) { s += sd[l]; sd[l] = s; }
  }
  __syncthreads();
  for (int l = threadIdx.x; l < L_; l += blockDim.x)
    g_t[b*L_ + l] = sd[l];
}

// ---------------- TF32 tensor-core GEMM: C[M,N] = A[M,K] @ W[N,K]^T + bias
// BM=128, BN=64, BK=32; 256 threads = 8 warps (4m x 2n), warp tile 32x32
template<bool RELU>
__global__ __launch_bounds__(256) void gemm_tc(
    const float* __restrict__ A, const float* __restrict__ W,
    const float* __restrict__ bias, float* __restrict__ C,
    int N, int K) {
  __shared__ unsigned As[128][40];   // stride 40 (mod 32 == 8): conflict-free frags
  __shared__ unsigned Bs[64][40];
  int tid = threadIdx.x, lane = tid & 31, warp = tid >> 5;
  int wm = warp >> 1, wn = warp & 1;
  int m_blk = blockIdx.y * 128, n_blk = blockIdx.x * 64;
  float acc[2][4][4] = {};
  int lr = tid >> 3, lc = (tid & 7) * 4;

  for (int k0 = 0; k0 < K; k0 += 32) {
#pragma unroll
    for (int p = 0; p < 4; p++) {
      float4 v = *(const float4*)(A + (long)(m_blk + lr + p*32)*K + k0 + lc);
      uint4 u = make_uint4(tf32c(v.x), tf32c(v.y), tf32c(v.z), tf32c(v.w));
      *(uint4*)&As[lr + p*32][lc] = u;
    }
#pragma unroll
    for (int p = 0; p < 2; p++) {
      float4 v = *(const float4*)(W + (long)(n_blk + lr + p*32)*K + k0 + lc);
      uint4 u = make_uint4(tf32c(v.x), tf32c(v.y), tf32c(v.z), tf32c(v.w));
      *(uint4*)&Bs[lr + p*32][lc] = u;
    }
    __syncthreads();
#pragma unroll
    for (int kk = 0; kk < 4; kk++) {
      int ar = lane >> 2, ac = kk*8 + (lane & 3);
      unsigned a[2][4], b[4][2];
#pragma unroll
      for (int mt = 0; mt < 2; mt++) {
        int r = wm*32 + mt*16 + ar;
        a[mt][0] = As[r][ac];     a[mt][1] = As[r+8][ac];
        a[mt][2] = As[r][ac+4];   a[mt][3] = As[r+8][ac+4];
      }
#pragma unroll
      for (int nt = 0; nt < 4; nt++) {
        int r = wn*32 + nt*8 + (lane >> 2);
        b[nt][0] = Bs[r][ac];     b[nt][1] = Bs[r][ac+4];
      }
#pragma unroll
      for (int mt = 0; mt < 2; mt++)
#pragma unroll
        for (int nt = 0; nt < 4; nt++)
          mma_tf32(acc[mt][nt], a[mt], b[nt], acc[mt][nt]);
    }
    __syncthreads();
  }
#pragma unroll
  for (int mt = 0; mt < 2; mt++) {
    int r0 = m_blk + wm*32 + mt*16 + (lane >> 2);
#pragma unroll
    for (int nt = 0; nt < 4; nt++) {
      int c0 = n_blk + wn*32 + nt*8 + 2*(lane & 3);
      float b0v = bias[c0], b1v = bias[c0+1];
      float v0 = acc[mt][nt][0] + b0v, v1 = acc[mt][nt][1] + b1v;
      float v2 = acc[mt][nt][2] + b0v, v3 = acc[mt][nt][3] + b1v;
      if (RELU) { v0=fmaxf(v0,0.f); v1=fmaxf(v1,0.f); v2=fmaxf(v2,0.f); v3=fmaxf(v3,0.f); }
      *(float2*)(C + (long)r0*N + c0)     = make_float2(v0, v1);
      *(float2*)(C + (long)(r0+8)*N + c0) = make_float2(v2, v3);
    }
  }
}

// ---------------- flash attention with TF32 mma ----------------
// grid (L/64, B*H), 128 threads = 4 warps; warp owns 16 query rows
__global__ __launch_bounds__(128) void attn_mma(
    const float* __restrict__ tw_p, const float* __restrict__ tb_p) {
  __shared__ unsigned SB[64][72];     // Q tile first, then reused as P (warp-private rows)
  __shared__ unsigned Ks[64][40];
  __shared__ unsigned Vs[64][40];
  __shared__ float tq[64];
  __shared__ float ts[64];
  __shared__ unsigned char ms[64];

  int bh = blockIdx.y, b = bh >> 3, h = bh & 7;
  int tid = threadIdx.x, lane = tid & 31, warp = tid >> 5;
  int i0 = blockIdx.x * 64;
  float tw = -fabsf(tw_p[0]);
  float tb = tb_p[0];
  const float scale = 0.17677669529663687f;   // 1/sqrt(32)

  // load Q tile (tf32) + query times
#pragma unroll
  for (int p = 0; p < 4; p++) {
    int fid = p*128 + tid, row = fid >> 3, c4 = (fid & 7) * 4;
    float4 v = *(const float4*)(g_qkv + (long)(b*L_ + i0 + row)*(3*D_) + h*DH_ + c4);
    uint4 u = make_uint4(tf32c(v.x), tf32c(v.y), tf32c(v.z), tf32c(v.w));
    *(uint4*)&SB[row][c4] = u;
  }
  if (tid < 64) tq[tid] = g_t[b*L_ + i0 + tid];
  __syncthreads();

  // Q fragments into registers (warp-private rows [warp*16, warp*16+16))
  unsigned qa[4][4];
  {
    int ar = warp*16 + (lane >> 2);
#pragma unroll
    for (int kk = 0; kk < 4; kk++) {
      int ac = kk*8 + (lane & 3);
      qa[kk][0] = SB[ar][ac];   qa[kk][1] = SB[ar+8][ac];
      qa[kk][2] = SB[ar][ac+4]; qa[kk][3] = SB[ar+8][ac+4];
    }
  }
  float ti0 = tq[warp*16 + (lane >> 2)];
  float ti1 = tq[warp*16 + (lane >> 2) + 8];

  float mrow0 = -1e30f, mrow1 = -1e30f, lrow0 = 0.f, lrow1 = 0.f;
  float oacc[4][4] = {};

  for (int jt = 0; jt < L_/64; jt++) {
    int j0g = jt * 64;
    // load K,V tiles (tf32), key times + mask
#pragma unroll
    for (int p = 0; p < 4; p++) {
      int fid = p*128 + tid, row = fid >> 3, c4 = (fid & 7) * 4;
      long base = (long)(b*L_ + j0g + row)*(3*D_) + h*DH_ + c4;
      float4 kv = *(const float4*)(g_qkv + base + D_);
      float4 vv = *(const float4*)(g_qkv + base + 2*D_);
      *(uint4*)&Ks[row][c4] = make_uint4(tf32c(kv.x), tf32c(kv.y), tf32c(kv.z), tf32c(kv.w));
      *(uint4*)&Vs[row][c4] = make_uint4(tf32c(vv.x), tf32c(vv.y), tf32c(vv.z), tf32c(vv.w));
    }
    if (tid < 64) {
      ts[tid] = g_t[b*L_ + j0g + tid];
      ms[tid] = g_mask[b*L_ + j0g + tid];
    }
    __syncthreads();

    // S = Q K^T
    float sA[8][4];
#pragma unroll
    for (int nt = 0; nt < 8; nt++) { sA[nt][0]=0.f; sA[nt][1]=0.f; sA[nt][2]=0.f; sA[nt][3]=0.f; }
#pragma unroll
    for (int kk = 0; kk < 4; kk++) {
      int ac = kk*8 + (lane & 3);
#pragma unroll
      for (int nt = 0; nt < 8; nt++) {
        unsigned bb[2];
        int r = nt*8 + (lane >> 2);
        bb[0] = Ks[r][ac]; bb[1] = Ks[r][ac+4];
        mma_tf32(sA[nt], qa[kk], bb, sA[nt]);
      }
    }

    // epilogue: scale + time bias + mask
    float tmax0 = -1e30f, tmax1 = -1e30f;
#pragma unroll
    for (int nt = 0; nt < 8; nt++) {
      int jc = nt*8 + 2*(lane & 3);
      float tj0 = ts[jc], tj1 = ts[jc+1];
      bool m0 = ms[jc], m1 = ms[jc+1];
      float b00 = tw*__logf(1.f + fabsf(ti0 - tj0)) + tb;
      float b01 = tw*__logf(1.f + fabsf(ti0 - tj1)) + tb;
      float b10 = tw*__logf(1.f + fabsf(ti1 - tj0)) + tb;
      float b11 = tw*__logf(1.f + fabsf(ti1 - tj1)) + tb;
      sA[nt][0] = m0 ? -1e30f : sA[nt][0]*scale + b00;
      sA[nt][1] = m1 ? -1e30f : sA[nt][1]*scale + b01;
      sA[nt][2] = m0 ? -1e30f : sA[nt][2]*scale + b10;
      sA[nt][3] = m1 ? -1e30f : sA[nt][3]*scale + b11;
      tmax0 = fmaxf(tmax0, fmaxf(sA[nt][0], sA[nt][1]));
      tmax1 = fmaxf(tmax1, fmaxf(sA[nt][2], sA[nt][3]));
    }
    // row max across quad (lanes sharing a row differ in bits 0,1)
    tmax0 = fmaxf(tmax0, __shfl_xor_sync(~0u, tmax0, 1));
    tmax0 = fmaxf(tmax0, __shfl_xor_sync(~0u, tmax0, 2));
    tmax1 = fmaxf(tmax1, __shfl_xor_sync(~0u, tmax1, 1));
    tmax1 = fmaxf(tmax1, __shfl_xor_sync(~0u, tmax1, 2));
    float mn0 = fmaxf(mrow0, tmax0), mn1 = fmaxf(mrow1, tmax1);
    float al0 = __expf(mrow0 - mn0), al1 = __expf(mrow1 - mn1);
    mrow0 = mn0; mrow1 = mn1;

    float rs0 = 0.f, rs1 = 0.f;
    int pr = warp*16 + (lane >> 2);
#pragma unroll
    for (int nt = 0; nt < 8; nt++) {
      int jc = nt*8 + 2*(lane & 3);
      float p0 = __expf(sA[nt][0] - mn0), p1 = __expf(sA[nt][1] - mn0);
      float p2 = __expf(sA[nt][2] - mn1), p3 = __expf(sA[nt][3] - mn1);
      rs0 += p0 + p1; rs1 += p2 + p3;
      SB[pr][jc]     = tf32c(p0); SB[pr][jc+1]   = tf32c(p1);
      SB[pr+8][jc]   = tf32c(p2); SB[pr+8][jc+1] = tf32c(p3);
    }
    rs0 += __shfl_xor_sync(~0u, rs0, 1); rs0 += __shfl_xor_sync(~0u, rs0, 2);
    rs1 += __shfl_xor_sync(~0u, rs1, 1); rs1 += __shfl_xor_sync(~0u, rs1, 2);
    lrow0 = lrow0*al0 + rs0; lrow1 = lrow1*al1 + rs1;
#pragma unroll
    for (int nt = 0; nt < 4; nt++) {
      oacc[nt][0] *= al0; oacc[nt][1] *= al0;
      oacc[nt][2] *= al1; oacc[nt][3] *= al1;
    }
    __syncwarp();

    // O += P V
#pragma unroll
    for (int kk = 0; kk < 8; kk++) {
      unsigned pa[4];
      int ac = kk*8 + (lane & 3);
      pa[0] = SB[pr][ac];   pa[1] = SB[pr+8][ac];
      pa[2] = SB[pr][ac+4]; pa[3] = SB[pr+8][ac+4];
#pragma unroll
      for (int nt = 0; nt < 4; nt++) {
        unsigned vb[2];
        int kr = kk*8 + (lane & 3);
        int nc = nt*8 + (lane >> 2);
        vb[0] = Vs[kr][nc]; vb[1] = Vs[kr+4][nc];
        mma_tf32(oacc[nt], pa, vb, oacc[nt]);
      }
    }
    __syncthreads();
  }

  float inv0 = 1.f / lrow0, inv1 = 1.f / lrow1;
  int rr = i0 + warp*16 + (lane >> 2);
#pragma unroll
  for (int nt = 0; nt < 4; nt++) {
    int c = h*DH_ + nt*8 + 2*(lane & 3);
    *(float2*)(g_o + (long)(b*L_ + rr)*D_ + c) =
        make_float2(oacc[nt][0]*inv0, oacc[nt][1]*inv0);
    *(float2*)(g_o + (long)(b*L_ + rr + 8)*D_ + c) =
        make_float2(oacc[nt][2]*inv1, oacc[nt][3]*inv1);
  }
}

// ---------------- x = LN(x + r) * g + b ----------------
__global__ __launch_bounds__(256) void add_ln_kernel(
    float* __restrict__ x, const float* __restrict__ r,
    const float* __restrict__ g, const float* __restrict__ bt) {
  int row = blockIdx.x, d = threadIdx.x;
  int lane = d & 31, warp = d >> 5;
  float v = x[row*D_+d] + r[row*D_+d];
  __shared__ float red[8];
  float s = v;
#pragma unroll
  for (int off = 16; off; off >>= 1) s += __shfl_xor_sync(~0u, s, off);
  if (lane == 0) red[warp] = s;
  __syncthreads();
  float tot = 0.f;
#pragma unroll
  for (int w = 0; w < 8; w++) tot += red[w];
  float mean = tot * (1.f/D_);
  float c = v - mean;
  __syncthreads();
  float s2 = c*c;
#pragma unroll
  for (int off = 16; off; off >>= 1) s2 += __shfl_xor_sync(~0u, s2, off);
  if (lane == 0) red[warp] = s2;
  __syncthreads();
  float tot2 = 0.f;
#pragma unroll
  for (int w = 0; w < 8; w++) tot2 += red[w];
  float var = tot2 * (1.f/D_);
  x[row*D_+d] = c * rsqrtf(var + 1e-5f) * g[d] + bt[d];
}

// ---------------- final head ----------------
__global__ __launch_bounds__(256) void head_kernel(
    const float* __restrict__ w1, const float* __restrict__ b1,
    const float* __restrict__ w2, const float* __restrict__ b2,
    float* __restrict__ out, int out_size) {
  int b = blockIdx.x, tid = threadIdx.x;
  int lane = tid & 31, warp = tid >> 5;
  __shared__ int cred[8];
  int cnt = 0;
  for (int l = tid; l < L_; l += 256) cnt += (g_mask[b*L_+l] ? 0 : 1);
#pragma unroll
  for (int off = 16; off; off >>= 1) cnt += __shfl_xor_sync(~0u, cnt, off);
  if (lane == 0) cred[warp] = cnt;
  __syncthreads();
  int len = 0;
#pragma unroll
  for (int w = 0; w < 8; w++) len += cred[w];
  int idx = len - 1;
  __shared__ float ls[D_];
  float xv = g_x[(b*L_+idx)*D_ + tid];
  ls[tid] = xv;
  if (16 + b*D_ + tid < out_size)
    out[16 + b*D_ + tid] = xv;
  __syncthreads();
  __shared__ float hh[128];
  if (tid < 128) {
    float s = b1[tid];
    const float4* wp = (const float4*)(w1 + tid*D_);
#pragma unroll 8
    for (int k4 = 0; k4 < D_/4; k4++) {
      float4 w = wp[k4];
      s += ls[k4*4+0]*w.x + ls[k4*4+1]*w.y + ls[k4*4+2]*w.z + ls[k4*4+3]*w.w;
    }
    hh[tid] = fmaxf(s, 0.f);
  }
  __syncthreads();
  if (tid < 32) {
    float s = 0.f;
    for (int j = tid; j < 128; j += 32) s += hh[j]*w2[j];
#pragma unroll
    for (int off = 16; off; off >>= 1) s += __shfl_xor_sync(~0u, s, off);
    if (tid == 0) out[b] = s + b2[0];
  }
}

// ---------------- host ----------------
extern "C" void kernel_launch(void* const* d_in, const int* in_sizes, int n_in,
                              void* d_out, int out_size) {
  const float* feat  = (const float*)d_in[0];
  const void*  maskraw = d_in[1];
  const float* pe    = (const float*)d_in[2];
  const float* in_w  = (const float*)d_in[3];
  const float* in_b  = (const float*)d_in[4];
  const float* time_w= (const float*)d_in[5];
  const float* time_b= (const float*)d_in[6];
  const float* qkv_w = (const float*)d_in[7];
  const float* qkv_b = (const float*)d_in[8];
  const float* out_w = (const float*)d_in[9];
  const float* out_b = (const float*)d_in[10];
  const float* ln1_g = (const float*)d_in[11];
  const float* ln1_b = (const float*)d_in[12];
  const float* ff1_w = (const float*)d_in[13];
  const float* ff1_b = (const float*)d_in[14];
  const float* ff2_w = (const float*)d_in[15];
  const float* ff2_b = (const float*)d_in[16];
  const float* ln2_g = (const float*)d_in[17];
  const float* ln2_b = (const float*)d_in[18];
  const float* reg1_w= (const float*)d_in[19];
  const float* reg1_b= (const float*)d_in[20];
  const float* reg2_w= (const float*)d_in[21];
  const float* reg2_b= (const float*)d_in[22];
  float* out = (float*)d_out;

  float *px, *pqkv, *po, *pp, *ph;
  cudaGetSymbolAddress((void**)&px,  g_x);
  cudaGetSymbolAddress((void**)&pqkv,g_qkv);
  cudaGetSymbolAddress((void**)&po,  g_o);
  cudaGetSymbolAddress((void**)&pp,  g_p);
  cudaGetSymbolAddress((void**)&ph,  g_h);

  mask_detect_kernel<<<1, 256>>>((const unsigned int*)maskraw);
  mask_convert_kernel<<<BL_/256, 256>>>(maskraw);
  embed_kernel<<<BL_, 256>>>(feat, pe, in_w, in_b);
  cumsum_kernel<<<B_, 256>>>(feat);

  for (int layer = 0; layer < NL_; layer++) {
    gemm_tc<false><<<dim3(3*D_/64, BL_/128), 256>>>(
        px, qkv_w + layer*3*D_*D_, qkv_b + layer*3*D_, pqkv, 3*D_, D_);
    attn_mma<<<dim3(L_/64, B_*H_), 128>>>(time_w, time_b);
    gemm_tc<false><<<dim3(D_/64, BL_/128), 256>>>(
        po, out_w + layer*D_*D_, out_b + layer*D_, pp, D_, D_);
    add_ln_kernel<<<BL_, 256>>>(px, pp, ln1_g + layer*D_, ln1_b + layer*D_);
    gemm_tc<true><<<dim3(DFF_/64, BL_/128), 256>>>(
        px, ff1_w + layer*DFF_*D_, ff1_b + layer*DFF_, ph, DFF_, D_);
    gemm_tc<false><<<dim3(D_/64, BL_/128), 256>>>(
        ph, ff2_w + layer*D_*DFF_, ff2_b + layer*D_, pp, D_, DFF_);
    add_ln_kernel<<<BL_, 256>>>(px, pp, ln2_g + layer*D_, ln2_b + layer*D_);
  }

  head_kernel<<<B_, 256>>>(reg1_w, reg1_b, reg2_w, reg2_b, out, out_size);
}

// round 4
// speedup vs baseline: 4.8186x; 1.2364x over previous
#include <cuda_runtime.h>
#include <math.h>

#define B_   16
#define L_   1024
#define IN_  32
#define D_   256
#define H_   8
#define NL_  2
#define DFF_ 1024
#define DH_  32
#define BL_  (B_*L_)

// ---------------- scratch (device globals; zero-initialized) ----------------
__device__ float g_x[BL_*D_];
__device__ float g_qkv[BL_*3*D_];
__device__ float g_o[BL_*D_];
__device__ float g_p[BL_*D_];
__device__ float g_h[BL_*DFF_];
__device__ float g_t[BL_];
__device__ int g_mask_mode;
__device__ unsigned char g_mask[BL_];
__device__ int g_len[B_];

// ---------------- tf32 helpers ----------------
__device__ __forceinline__ unsigned tf32c(float f) {
  unsigned u; asm("cvt.rna.tf32.f32 %0, %1;" : "=r"(u) : "f"(f)); return u;
}
__device__ __forceinline__ void mma_tf32(float* d, const unsigned* a,
                                         const unsigned* b, const float* c) {
  asm volatile(
    "mma.sync.aligned.m16n8k8.row.col.f32.tf32.tf32.f32 "
    "{%0,%1,%2,%3},{%4,%5,%6,%7},{%8,%9},{%10,%11,%12,%13};"
    : "=f"(d[0]),"=f"(d[1]),"=f"(d[2]),"=f"(d[3])
    : "r"(a[0]),"r"(a[1]),"r"(a[2]),"r"(a[3]),
      "r"(b[0]),"r"(b[1]),
      "f"(c[0]),"f"(c[1]),"f"(c[2]),"f"(c[3]));
}

// ---------------- mask dtype detection + convert + lengths ----------------
__global__ void mask_detect_kernel(const unsigned int* __restrict__ mraw) {
  __shared__ int bad;
  if (threadIdx.x == 0) bad = 0;
  __syncthreads();
  for (int k = threadIdx.x; k < BL_/4; k += blockDim.x) {
    unsigned int v = mraw[k];
    if (v != 0u && v != 1u && v != 0x3F800000u) atomicOr(&bad, 1);
  }
  __syncthreads();
  if (threadIdx.x == 0) g_mask_mode = bad ? 0 : 1;
}
__global__ void mask_convert_kernel(const void* __restrict__ mraw) {
  int j = blockIdx.x * blockDim.x + threadIdx.x;
  if (j >= BL_) return;
  unsigned char m;
  if (g_mask_mode == 1) m = (((const unsigned int*)mraw)[j] != 0u) ? 1 : 0;
  else                  m = (((const unsigned char*)mraw)[j] != 0) ? 1 : 0;
  g_mask[j] = m;
}
__global__ void len_kernel() {
  int b = blockIdx.x, tid = threadIdx.x;
  int lane = tid & 31, warp = tid >> 5;
  __shared__ int red[8];
  int cnt = 0;
  for (int l = tid; l < L_; l += blockDim.x) cnt += (g_mask[b*L_+l] ? 0 : 1);
#pragma unroll
  for (int off = 16; off; off >>= 1) cnt += __shfl_xor_sync(~0u, cnt, off);
  if (lane == 0) red[warp] = cnt;
  __syncthreads();
  if (tid == 0) {
    int s = 0;
#pragma unroll
    for (int w = 0; w < 8; w++) s += red[w];
    g_len[b] = s;
  }
}

// ---------------- embed ----------------
__global__ __launch_bounds__(256) void embed_kernel(
    const float* __restrict__ feat, const float* __restrict__ pe,
    const float* __restrict__ in_w, const float* __restrict__ in_b) {
  int row = blockIdx.x;
  int l = row & (L_-1);
  int d = threadIdx.x;
  __shared__ float fs[IN_];
  if (d < IN_) fs[d] = feat[row*IN_ + d];
  __syncthreads();
  const float4* w4 = (const float4*)(in_w + d*IN_);
  float s = in_b[d];
#pragma unroll
  for (int k4 = 0; k4 < IN_/4; k4++) {
    float4 w = w4[k4];
    s += fs[k4*4+0]*w.x + fs[k4*4+1]*w.y + fs[k4*4+2]*w.z + fs[k4*4+3]*w.w;
  }
  g_x[row*D_ + d] = s + pe[l*D_ + d];
}

// ---------------- cumsum ----------------
__global__ void cumsum_kernel(const float* __restrict__ feat) {
  int b = blockIdx.x;
  __shared__ float sd[L_];
  for (int l = threadIdx.x; l < L_; l += blockDim.x)
    sd[l] = feat[(b*L_ + l)*IN_ + (IN_-2)];
  __syncthreads();
  if (threadIdx.x == 0) {
    float s = 0.f;
    for (int l = 0; l < L_; l++) { s += sd[l]; sd[l] = s; }
  }
  __syncthreads();
  for (int l = threadIdx.x; l < L_; l += blockDim.x)
    g_t[b*L_ + l] = sd[l];
}

// ---------------- TF32 tensor-core GEMM (M rows are b-major, skip padded blocks)
template<bool RELU>
__global__ __launch_bounds__(256) void gemm_tc(
    const float* __restrict__ A, const float* __restrict__ W,
    const float* __restrict__ bias, float* __restrict__ C,
    int N, int K) {
  int m_blk = blockIdx.y * 128, n_blk = blockIdx.x * 64;
  if ((m_blk & (L_-1)) >= g_len[m_blk >> 10]) return;   // fully padded rows
  __shared__ unsigned As[128][40];
  __shared__ unsigned Bs[64][40];
  int tid = threadIdx.x, lane = tid & 31, warp = tid >> 5;
  int wm = warp >> 1, wn = warp & 1;
  float acc[2][4][4] = {};
  int lr = tid >> 3, lc = (tid & 7) * 4;

  for (int k0 = 0; k0 < K; k0 += 32) {
#pragma unroll
    for (int p = 0; p < 4; p++) {
      float4 v = *(const float4*)(A + (long)(m_blk + lr + p*32)*K + k0 + lc);
      uint4 u = make_uint4(tf32c(v.x), tf32c(v.y), tf32c(v.z), tf32c(v.w));
      *(uint4*)&As[lr + p*32][lc] = u;
    }
#pragma unroll
    for (int p = 0; p < 2; p++) {
      float4 v = *(const float4*)(W + (long)(n_blk + lr + p*32)*K + k0 + lc);
      uint4 u = make_uint4(tf32c(v.x), tf32c(v.y), tf32c(v.z), tf32c(v.w));
      *(uint4*)&Bs[lr + p*32][lc] = u;
    }
    __syncthreads();
#pragma unroll
    for (int kk = 0; kk < 4; kk++) {
      int ar = lane >> 2, ac = kk*8 + (lane & 3);
      unsigned a[2][4], b[4][2];
#pragma unroll
      for (int mt = 0; mt < 2; mt++) {
        int r = wm*32 + mt*16 + ar;
        a[mt][0] = As[r][ac];     a[mt][1] = As[r+8][ac];
        a[mt][2] = As[r][ac+4];   a[mt][3] = As[r+8][ac+4];
      }
#pragma unroll
      for (int nt = 0; nt < 4; nt++) {
        int r = wn*32 + nt*8 + (lane >> 2);
        b[nt][0] = Bs[r][ac];     b[nt][1] = Bs[r][ac+4];
      }
#pragma unroll
      for (int mt = 0; mt < 2; mt++)
#pragma unroll
        for (int nt = 0; nt < 4; nt++)
          mma_tf32(acc[mt][nt], a[mt], b[nt], acc[mt][nt]);
    }
    __syncthreads();
  }
#pragma unroll
  for (int mt = 0; mt < 2; mt++) {
    int r0 = m_blk + wm*32 + mt*16 + (lane >> 2);
#pragma unroll
    for (int nt = 0; nt < 4; nt++) {
      int c0 = n_blk + wn*32 + nt*8 + 2*(lane & 3);
      float b0v = bias[c0], b1v = bias[c0+1];
      float v0 = acc[mt][nt][0] + b0v, v1 = acc[mt][nt][1] + b1v;
      float v2 = acc[mt][nt][2] + b0v, v3 = acc[mt][nt][3] + b1v;
      if (RELU) { v0=fmaxf(v0,0.f); v1=fmaxf(v1,0.f); v2=fmaxf(v2,0.f); v3=fmaxf(v3,0.f); }
      *(float2*)(C + (long)r0*N + c0)     = make_float2(v0, v1);
      *(float2*)(C + (long)(r0+8)*N + c0) = make_float2(v2, v3);
    }
  }
}

// ---------------- flash attention, TF32 mma, 8 warps / 128 queries per CTA ----
// dyn smem layout (u32 units):
//   Ks[64][40] @0, Vs[64][40] @2560, SB[128][72] @5120,
//   tq[128] @14336, ts[64] @14464, ms bytes @14528*4
#define ATTN_SMEM_BYTES ((14528 + 16) * 4)
__global__ __launch_bounds__(256) void attn_mma(
    const float* __restrict__ tw_p, const float* __restrict__ tb_p) {
  extern __shared__ unsigned smem[];
  unsigned (*Ks)[40] = (unsigned(*)[40])(smem);
  unsigned (*Vs)[40] = (unsigned(*)[40])(smem + 2560);
  unsigned (*SB)[72] = (unsigned(*)[72])(smem + 5120);
  float* tq = (float*)(smem + 14336);
  float* ts = (float*)(smem + 14464);
  unsigned char* ms = (unsigned char*)(smem + 14528);

  int bh = blockIdx.y, b = bh >> 3, h = bh & 7;
  int tid = threadIdx.x, lane = tid & 31, warp = tid >> 5;
  int i0 = blockIdx.x * 128;
  int len = g_len[b];
  if (i0 >= len) return;                    // fully padded query block
  int njt = (len + 63) >> 6;                // key tiles with any valid key

  float tw = -fabsf(tw_p[0]);
  float tb = tb_p[0];
  const float scale = 0.17677669529663687f; // 1/sqrt(32)

  // Q tile (128 rows x 32) -> SB, + query times
#pragma unroll
  for (int p = 0; p < 4; p++) {
    int fid = p*256 + tid, row = fid >> 3, c4 = (fid & 7) * 4;
    float4 v = *(const float4*)(g_qkv + (long)(b*L_ + i0 + row)*(3*D_) + h*DH_ + c4);
    *(uint4*)&SB[row][c4] = make_uint4(tf32c(v.x), tf32c(v.y), tf32c(v.z), tf32c(v.w));
  }
  if (tid < 128) tq[tid] = g_t[b*L_ + i0 + tid];
  __syncthreads();

  unsigned qa[4][4];
  {
    int ar = warp*16 + (lane >> 2);
#pragma unroll
    for (int kk = 0; kk < 4; kk++) {
      int ac = kk*8 + (lane & 3);
      qa[kk][0] = SB[ar][ac];   qa[kk][1] = SB[ar+8][ac];
      qa[kk][2] = SB[ar][ac+4]; qa[kk][3] = SB[ar+8][ac+4];
    }
  }
  float ti0 = tq[warp*16 + (lane >> 2)];
  float ti1 = tq[warp*16 + (lane >> 2) + 8];
  __syncthreads();   // SB about to be reused for P

  float mrow0 = -1e30f, mrow1 = -1e30f, lrow0 = 0.f, lrow1 = 0.f;
  float oacc[4][4] = {};

  for (int jt = 0; jt < njt; jt++) {
    int j0g = jt * 64;
    // K,V tiles (64 x 32 each) + key times + mask
#pragma unroll
    for (int p = 0; p < 2; p++) {
      int fid = p*256 + tid, row = fid >> 3, c4 = (fid & 7) * 4;
      long base = (long)(b*L_ + j0g + row)*(3*D_) + h*DH_ + c4;
      float4 kv = *(const float4*)(g_qkv + base + D_);
      float4 vv = *(const float4*)(g_qkv + base + 2*D_);
      *(uint4*)&Ks[row][c4] = make_uint4(tf32c(kv.x), tf32c(kv.y), tf32c(kv.z), tf32c(kv.w));
      *(uint4*)&Vs[row][c4] = make_uint4(tf32c(vv.x), tf32c(vv.y), tf32c(vv.z), tf32c(vv.w));
    }
    if (tid < 64) {
      ts[tid] = g_t[b*L_ + j0g + tid];
      ms[tid] = g_mask[b*L_ + j0g + tid];
    }
    __syncthreads();

    // S = Q K^T (16 x 64 per warp)
    float sA[8][4];
#pragma unroll
    for (int nt = 0; nt < 8; nt++) { sA[nt][0]=0.f; sA[nt][1]=0.f; sA[nt][2]=0.f; sA[nt][3]=0.f; }
#pragma unroll
    for (int kk = 0; kk < 4; kk++) {
      int ac = kk*8 + (lane & 3);
#pragma unroll
      for (int nt = 0; nt < 8; nt++) {
        unsigned bb[2];
        int r = nt*8 + (lane >> 2);
        bb[0] = Ks[r][ac]; bb[1] = Ks[r][ac+4];
        mma_tf32(sA[nt], qa[kk], bb, sA[nt]);
      }
    }

    // epilogue: scale + time bias + mask
    float tmax0 = -1e30f, tmax1 = -1e30f;
#pragma unroll
    for (int nt = 0; nt < 8; nt++) {
      int jc = nt*8 + 2*(lane & 3);
      float tj0 = ts[jc], tj1 = ts[jc+1];
      bool m0 = ms[jc], m1 = ms[jc+1];
      float b00 = tw*__logf(1.f + fabsf(ti0 - tj0)) + tb;
      float b01 = tw*__logf(1.f + fabsf(ti0 - tj1)) + tb;
      float b10 = tw*__logf(1.f + fabsf(ti1 - tj0)) + tb;
      float b11 = tw*__logf(1.f + fabsf(ti1 - tj1)) + tb;
      sA[nt][0] = m0 ? -1e30f : sA[nt][0]*scale + b00;
      sA[nt][1] = m1 ? -1e30f : sA[nt][1]*scale + b01;
      sA[nt][2] = m0 ? -1e30f : sA[nt][2]*scale + b10;
      sA[nt][3] = m1 ? -1e30f : sA[nt][3]*scale + b11;
      tmax0 = fmaxf(tmax0, fmaxf(sA[nt][0], sA[nt][1]));
      tmax1 = fmaxf(tmax1, fmaxf(sA[nt][2], sA[nt][3]));
    }
    tmax0 = fmaxf(tmax0, __shfl_xor_sync(~0u, tmax0, 1));
    tmax0 = fmaxf(tmax0, __shfl_xor_sync(~0u, tmax0, 2));
    tmax1 = fmaxf(tmax1, __shfl_xor_sync(~0u, tmax1, 1));
    tmax1 = fmaxf(tmax1, __shfl_xor_sync(~0u, tmax1, 2));
    float mn0 = fmaxf(mrow0, tmax0), mn1 = fmaxf(mrow1, tmax1);
    float al0 = __expf(mrow0 - mn0), al1 = __expf(mrow1 - mn1);
    mrow0 = mn0; mrow1 = mn1;

    float rs0 = 0.f, rs1 = 0.f;
    int pr = warp*16 + (lane >> 2);
#pragma unroll
    for (int nt = 0; nt < 8; nt++) {
      int jc = nt*8 + 2*(lane & 3);
      float p0 = __expf(sA[nt][0] - mn0), p1 = __expf(sA[nt][1] - mn0);
      float p2 = __expf(sA[nt][2] - mn1), p3 = __expf(sA[nt][3] - mn1);
      rs0 += p0 + p1; rs1 += p2 + p3;
      SB[pr][jc]     = tf32c(p0); SB[pr][jc+1]   = tf32c(p1);
      SB[pr+8][jc]   = tf32c(p2); SB[pr+8][jc+1] = tf32c(p3);
    }
    rs0 += __shfl_xor_sync(~0u, rs0, 1); rs0 += __shfl_xor_sync(~0u, rs0, 2);
    rs1 += __shfl_xor_sync(~0u, rs1, 1); rs1 += __shfl_xor_sync(~0u, rs1, 2);
    lrow0 = lrow0*al0 + rs0; lrow1 = lrow1*al1 + rs1;
#pragma unroll
    for (int nt = 0; nt < 4; nt++) {
      oacc[nt][0] *= al0; oacc[nt][1] *= al0;
      oacc[nt][2] *= al1; oacc[nt][3] *= al1;
    }
    __syncwarp();

    // O += P V
#pragma unroll
    for (int kk = 0; kk < 8; kk++) {
      unsigned pa[4];
      int ac = kk*8 + (lane & 3);
      pa[0] = SB[pr][ac];   pa[1] = SB[pr+8][ac];
      pa[2] = SB[pr][ac+4]; pa[3] = SB[pr+8][ac+4];
#pragma unroll
      for (int nt = 0; nt < 4; nt++) {
        unsigned vb[2];
        int kr = kk*8 + (lane & 3);
        int nc = nt*8 + (lane >> 2);
        vb[0] = Vs[kr][nc]; vb[1] = Vs[kr+4][nc];
        mma_tf32(oacc[nt], pa, vb, oacc[nt]);
      }
    }
    __syncthreads();
  }

  float inv0 = 1.f / lrow0, inv1 = 1.f / lrow1;
  int rr = i0 + warp*16 + (lane >> 2);
#pragma unroll
  for (int nt = 0; nt < 4; nt++) {
    int c = h*DH_ + nt*8 + 2*(lane & 3);
    *(float2*)(g_o + (long)(b*L_ + rr)*D_ + c) =
        make_float2(oacc[nt][0]*inv0, oacc[nt][1]*inv0);
    *(float2*)(g_o + (long)(b*L_ + rr + 8)*D_ + c) =
        make_float2(oacc[nt][2]*inv1, oacc[nt][3]*inv1);
  }
}

// ---------------- x = LN(x + r) * g + b ----------------
__global__ __launch_bounds__(256) void add_ln_kernel(
    float* __restrict__ x, const float* __restrict__ r,
    const float* __restrict__ g, const float* __restrict__ bt) {
  int row = blockIdx.x, d = threadIdx.x;
  if ((row & (L_-1)) >= g_len[row >> 10]) return;   // padded row
  int lane = d & 31, warp = d >> 5;
  float v = x[row*D_+d] + r[row*D_+d];
  __shared__ float red[8];
  float s = v;
#pragma unroll
  for (int off = 16; off; off >>= 1) s += __shfl_xor_sync(~0u, s, off);
  if (lane == 0) red[warp] = s;
  __syncthreads();
  float tot = 0.f;
#pragma unroll
  for (int w = 0; w < 8; w++) tot += red[w];
  float mean = tot * (1.f/D_);
  float c = v - mean;
  __syncthreads();
  float s2 = c*c;
#pragma unroll
  for (int off = 16; off; off >>= 1) s2 += __shfl_xor_sync(~0u, s2, off);
  if (lane == 0) red[warp] = s2;
  __syncthreads();
  float tot2 = 0.f;
#pragma unroll
  for (int w = 0; w < 8; w++) tot2 += red[w];
  float var = tot2 * (1.f/D_);
  x[row*D_+d] = c * rsqrtf(var + 1e-5f) * g[d] + bt[d];
}

// ---------------- final head ----------------
__global__ __launch_bounds__(256) void head_kernel(
    const float* __restrict__ w1, const float* __restrict__ b1,
    const float* __restrict__ w2, const float* __restrict__ b2,
    float* __restrict__ out, int out_size) {
  int b = blockIdx.x, tid = threadIdx.x;
  int idx = g_len[b] - 1;
  __shared__ float ls[D_];
  float xv = g_x[(b*L_+idx)*D_ + tid];
  ls[tid] = xv;
  if (16 + b*D_ + tid < out_size)
    out[16 + b*D_ + tid] = xv;
  __syncthreads();
  __shared__ float hh[128];
  if (tid < 128) {
    float s = b1[tid];
    const float4* wp = (const float4*)(w1 + tid*D_);
#pragma unroll 8
    for (int k4 = 0; k4 < D_/4; k4++) {
      float4 w = wp[k4];
      s += ls[k4*4+0]*w.x + ls[k4*4+1]*w.y + ls[k4*4+2]*w.z + ls[k4*4+3]*w.w;
    }
    hh[tid] = fmaxf(s, 0.f);
  }
  __syncthreads();
  if (tid < 32) {
    float s = 0.f;
    for (int j = tid; j < 128; j += 32) s += hh[j]*w2[j];
#pragma unroll
    for (int off = 16; off; off >>= 1) s += __shfl_xor_sync(~0u, s, off);
    if (tid == 0) out[b] = s + b2[0];
  }
}

// ---------------- host ----------------
extern "C" void kernel_launch(void* const* d_in, const int* in_sizes, int n_in,
                              void* d_out, int out_size) {
  const float* feat  = (const float*)d_in[0];
  const void*  maskraw = d_in[1];
  const float* pe    = (const float*)d_in[2];
  const float* in_w  = (const float*)d_in[3];
  const float* in_b  = (const float*)d_in[4];
  const float* time_w= (const float*)d_in[5];
  const float* time_b= (const float*)d_in[6];
  const float* qkv_w = (const float*)d_in[7];
  const float* qkv_b = (const float*)d_in[8];
  const float* out_w = (const float*)d_in[9];
  const float* out_b = (const float*)d_in[10];
  const float* ln1_g = (const float*)d_in[11];
  const float* ln1_b = (const float*)d_in[12];
  const float* ff1_w = (const float*)d_in[13];
  const float* ff1_b = (const float*)d_in[14];
  const float* ff2_w = (const float*)d_in[15];
  const float* ff2_b = (const float*)d_in[16];
  const float* ln2_g = (const float*)d_in[17];
  const float* ln2_b = (const float*)d_in[18];
  const float* reg1_w= (const float*)d_in[19];
  const float* reg1_b= (const float*)d_in[20];
  const float* reg2_w= (const float*)d_in[21];
  const float* reg2_b= (const float*)d_in[22];
  float* out = (float*)d_out;

  float *px, *pqkv, *po, *pp, *ph;
  cudaGetSymbolAddress((void**)&px,  g_x);
  cudaGetSymbolAddress((void**)&pqkv,g_qkv);
  cudaGetSymbolAddress((void**)&po,  g_o);
  cudaGetSymbolAddress((void**)&pp,  g_p);
  cudaGetSymbolAddress((void**)&ph,  g_h);

  static int smem_set = 0;
  if (!smem_set) {
    cudaFuncSetAttribute(attn_mma, cudaFuncAttributeMaxDynamicSharedMemorySize,
                         ATTN_SMEM_BYTES);
    smem_set = 1;
  }

  mask_detect_kernel<<<1, 256>>>((const unsigned int*)maskraw);
  mask_convert_kernel<<<BL_/256, 256>>>(maskraw);
  len_kernel<<<B_, 256>>>();
  embed_kernel<<<BL_, 256>>>(feat, pe, in_w, in_b);
  cumsum_kernel<<<B_, 256>>>(feat);

  for (int layer = 0; layer < NL_; layer++) {
    gemm_tc<false><<<dim3(3*D_/64, BL_/128), 256>>>(
        px, qkv_w + layer*3*D_*D_, qkv_b + layer*3*D_, pqkv, 3*D_, D_);
    attn_mma<<<dim3(L_/128, B_*H_), 256, ATTN_SMEM_BYTES>>>(time_w, time_b);
    gemm_tc<false><<<dim3(D_/64, BL_/128), 256>>>(
        po, out_w + layer*D_*D_, out_b + layer*D_, pp, D_, D_);
    add_ln_kernel<<<BL_, 256>>>(px, pp, ln1_g + layer*D_, ln1_b + layer*D_);
    gemm_tc<true><<<dim3(DFF_/64, BL_/128), 256>>>(
        px, ff1_w + layer*DFF_*D_, ff1_b + layer*DFF_, ph, DFF_, D_);
    gemm_tc<false><<<dim3(D_/64, BL_/128), 256>>>(
        ph, ff2_w + layer*D_*DFF_, ff2_b + layer*D_, pp, D_, DFF_);
    add_ln_kernel<<<BL_, 256>>>(px, pp, ln2_g + layer*D_, ln2_b + layer*D_);
  }

  head_kernel<<<B_, 256>>>(reg1_w, reg1_b, reg2_w, reg2_b, out, out_size);
}

// round 5
// speedup vs baseline: 5.7589x; 1.1951x over previous
#include <cuda_runtime.h>
#include <math.h>

#define B_   16
#define L_   1024
#define IN_  32
#define D_   256
#define H_   8
#define NL_  2
#define DFF_ 1024
#define DH_  32
#define BL_  (B_*L_)

// ---------------- scratch (device globals; zero-initialized) ----------------
__device__ float g_x[BL_*D_];
__device__ float g_qkv[BL_*3*D_];
__device__ float g_o[BL_*D_];
__device__ float g_p[BL_*D_];
__device__ float g_h[BL_*DFF_];
__device__ float g_t[BL_];
__device__ unsigned char g_mask[BL_];
__device__ int g_len[B_];

// ---------------- tf32 helpers ----------------
__device__ __forceinline__ unsigned tf32c(float f) {
  unsigned u; asm("cvt.rna.tf32.f32 %0, %1;" : "=r"(u) : "f"(f)); return u;
}
__device__ __forceinline__ void mma_tf32(float* d, const unsigned* a,
                                         const unsigned* b, const float* c) {
  asm volatile(
    "mma.sync.aligned.m16n8k8.row.col.f32.tf32.tf32.f32 "
    "{%0,%1,%2,%3},{%4,%5,%6,%7},{%8,%9},{%10,%11,%12,%13};"
    : "=f"(d[0]),"=f"(d[1]),"=f"(d[2]),"=f"(d[3])
    : "r"(a[0]),"r"(a[1]),"r"(a[2]),"r"(a[3]),
      "r"(b[0]),"r"(b[1]),
      "f"(c[0]),"f"(c[1]),"f"(c[2]),"f"(c[3]));
}

// ---------------- fused prep: mask dtype detect + convert + len + time cumsum
// grid B_, 1024 threads (one per sequence position)
__global__ __launch_bounds__(1024) void prep_kernel(
    const unsigned int* __restrict__ mraw, const float* __restrict__ feat) {
  __shared__ int bad;
  __shared__ int slen;
  __shared__ float wsum[32];
  int b = blockIdx.x, tid = threadIdx.x;
  int lane = tid & 31, warp = tid >> 5;
  if (tid == 0) { bad = 0; slen = 0; }
  __syncthreads();
  // dtype detect over bytes [0,16384) — in-bounds for bool or int32 storage.
  // 4-byte 0/1 storage only yields words {0,1,0x3F800000}; byte storage
  // yields words like 0x01010101 at row tails.
  for (int k = tid; k < 4096; k += 1024) {
    unsigned v = mraw[k];
    if (v != 0u && v != 1u && v != 0x3F800000u) atomicOr(&bad, 1);
  }
  __syncthreads();
  int mode4 = !bad;
  int j = b*L_ + tid;
  unsigned char m = mode4 ? (mraw[j] != 0u)
                          : (((const unsigned char*)mraw)[j] != 0);
  g_mask[j] = m;
  if (!m) atomicAdd(&slen, 1);
  // inclusive scan of delta_t
  float v = feat[(long)j*IN_ + (IN_-2)];
#pragma unroll
  for (int off = 1; off < 32; off <<= 1) {
    float n = __shfl_up_sync(~0u, v, off);
    if (lane >= off) v += n;
  }
  if (lane == 31) wsum[warp] = v;
  __syncthreads();
  if (warp == 0) {
    float w = wsum[lane];
#pragma unroll
    for (int off = 1; off < 32; off <<= 1) {
      float n = __shfl_up_sync(~0u, w, off);
      if (lane >= off) w += n;
    }
    wsum[lane] = w;
  }
  __syncthreads();
  float base = warp ? wsum[warp-1] : 0.f;
  g_t[j] = v + base;
  if (tid == 0) g_len[b] = slen;
}

// ---------------- TF32 tensor-core GEMM, register-prefetch pipelined
// C[M,N] = A[M,K] @ W[N,K]^T + bias (+pe[l,n] if PE) (+relu if RELU)
// BM=128, BN=64, BK=32; 256 threads = 8 warps (4m x 2n)
template<bool RELU, bool PE>
__global__ __launch_bounds__(256) void gemm_tc(
    const float* __restrict__ A, const float* __restrict__ W,
    const float* __restrict__ bias, float* __restrict__ C,
    const float* __restrict__ pe, int N, int K) {
  int m_blk = blockIdx.y * 128, n_blk = blockIdx.x * 64;
  if ((m_blk & (L_-1)) >= g_len[m_blk >> 10]) return;   // fully padded rows
  __shared__ unsigned As[128][40];
  __shared__ unsigned Bs[64][40];
  int tid = threadIdx.x, lane = tid & 31, warp = tid >> 5;
  int wm = warp >> 1, wn = warp & 1;
  float acc[2][4][4] = {};
  int lr = tid >> 3, lc = (tid & 7) * 4;
  const float* Ab = A + (long)(m_blk + lr)*K + lc;
  const float* Wb = W + (long)(n_blk + lr)*K + lc;

  float4 pa[4], pb[2];
#pragma unroll
  for (int p = 0; p < 4; p++) pa[p] = *(const float4*)(Ab + (long)p*32*K);
#pragma unroll
  for (int p = 0; p < 2; p++) pb[p] = *(const float4*)(Wb + (long)p*32*K);

  for (int k0 = 0; k0 < K; k0 += 32) {
#pragma unroll
    for (int p = 0; p < 4; p++)
      *(uint4*)&As[lr + p*32][lc] =
        make_uint4(tf32c(pa[p].x), tf32c(pa[p].y), tf32c(pa[p].z), tf32c(pa[p].w));
#pragma unroll
    for (int p = 0; p < 2; p++)
      *(uint4*)&Bs[lr + p*32][lc] =
        make_uint4(tf32c(pb[p].x), tf32c(pb[p].y), tf32c(pb[p].z), tf32c(pb[p].w));
    __syncthreads();
    if (k0 + 32 < K) {     // prefetch next chunk; overlaps with mma below
#pragma unroll
      for (int p = 0; p < 4; p++) pa[p] = *(const float4*)(Ab + k0+32 + (long)p*32*K);
#pragma unroll
      for (int p = 0; p < 2; p++) pb[p] = *(const float4*)(Wb + k0+32 + (long)p*32*K);
    }
#pragma unroll
    for (int kk = 0; kk < 4; kk++) {
      int ar = lane >> 2, ac = kk*8 + (lane & 3);
      unsigned a[2][4], b[4][2];
#pragma unroll
      for (int mt = 0; mt < 2; mt++) {
        int r = wm*32 + mt*16 + ar;
        a[mt][0] = As[r][ac];     a[mt][1] = As[r+8][ac];
        a[mt][2] = As[r][ac+4];   a[mt][3] = As[r+8][ac+4];
      }
#pragma unroll
      for (int nt = 0; nt < 4; nt++) {
        int r = wn*32 + nt*8 + (lane >> 2);
        b[nt][0] = Bs[r][ac];     b[nt][1] = Bs[r][ac+4];
      }
#pragma unroll
      for (int mt = 0; mt < 2; mt++)
#pragma unroll
        for (int nt = 0; nt < 4; nt++)
          mma_tf32(acc[mt][nt], a[mt], b[nt], acc[mt][nt]);
    }
    __syncthreads();
  }
#pragma unroll
  for (int mt = 0; mt < 2; mt++) {
    int r0 = m_blk + wm*32 + mt*16 + (lane >> 2);
#pragma unroll
    for (int nt = 0; nt < 4; nt++) {
      int c0 = n_blk + wn*32 + nt*8 + 2*(lane & 3);
      float b0v = bias[c0], b1v = bias[c0+1];
      float v0 = acc[mt][nt][0] + b0v, v1 = acc[mt][nt][1] + b1v;
      float v2 = acc[mt][nt][2] + b0v, v3 = acc[mt][nt][3] + b1v;
      if (PE) {
        v0 += pe[(long)(r0 & (L_-1))*D_ + c0];
        v1 += pe[(long)(r0 & (L_-1))*D_ + c0 + 1];
        v2 += pe[(long)((r0+8) & (L_-1))*D_ + c0];
        v3 += pe[(long)((r0+8) & (L_-1))*D_ + c0 + 1];
      }
      if (RELU) { v0=fmaxf(v0,0.f); v1=fmaxf(v1,0.f); v2=fmaxf(v2,0.f); v3=fmaxf(v3,0.f); }
      *(float2*)(C + (long)r0*N + c0)     = make_float2(v0, v1);
      *(float2*)(C + (long)(r0+8)*N + c0) = make_float2(v2, v3);
    }
  }
}

// ---------------- flash attention, TF32 mma, 8 warps / 128 queries per CTA ----
#define ATTN_SMEM_BYTES ((14528 + 16) * 4)
__global__ __launch_bounds__(256) void attn_mma(
    const float* __restrict__ tw_p, const float* __restrict__ tb_p) {
  extern __shared__ unsigned smem[];
  unsigned (*Ks)[40] = (unsigned(*)[40])(smem);
  unsigned (*Vs)[40] = (unsigned(*)[40])(smem + 2560);
  unsigned (*SB)[72] = (unsigned(*)[72])(smem + 5120);
  float* tq = (float*)(smem + 14336);
  float* ts = (float*)(smem + 14464);
  unsigned char* ms = (unsigned char*)(smem + 14528);

  int bh = blockIdx.y, b = bh >> 3, h = bh & 7;
  int tid = threadIdx.x, lane = tid & 31, warp = tid >> 5;
  int i0 = blockIdx.x * 128;
  int len = g_len[b];
  if (i0 >= len) return;
  int njt = (len + 63) >> 6;

  float tw = -fabsf(tw_p[0]);
  float tb = tb_p[0];
  const float scale = 0.17677669529663687f; // 1/sqrt(32)

#pragma unroll
  for (int p = 0; p < 4; p++) {
    int fid = p*256 + tid, row = fid >> 3, c4 = (fid & 7) * 4;
    float4 v = *(const float4*)(g_qkv + (long)(b*L_ + i0 + row)*(3*D_) + h*DH_ + c4);
    *(uint4*)&SB[row][c4] = make_uint4(tf32c(v.x), tf32c(v.y), tf32c(v.z), tf32c(v.w));
  }
  if (tid < 128) tq[tid] = g_t[b*L_ + i0 + tid];
  __syncthreads();

  unsigned qa[4][4];
  {
    int ar = warp*16 + (lane >> 2);
#pragma unroll
    for (int kk = 0; kk < 4; kk++) {
      int ac = kk*8 + (lane & 3);
      qa[kk][0] = SB[ar][ac];   qa[kk][1] = SB[ar+8][ac];
      qa[kk][2] = SB[ar][ac+4]; qa[kk][3] = SB[ar+8][ac+4];
    }
  }
  float ti0 = tq[warp*16 + (lane >> 2)];
  float ti1 = tq[warp*16 + (lane >> 2) + 8];
  __syncthreads();

  float mrow0 = -1e30f, mrow1 = -1e30f, lrow0 = 0.f, lrow1 = 0.f;
  float oacc[4][4] = {};

  for (int jt = 0; jt < njt; jt++) {
    int j0g = jt * 64;
#pragma unroll
    for (int p = 0; p < 2; p++) {
      int fid = p*256 + tid, row = fid >> 3, c4 = (fid & 7) * 4;
      long base = (long)(b*L_ + j0g + row)*(3*D_) + h*DH_ + c4;
      float4 kv = *(const float4*)(g_qkv + base + D_);
      float4 vv = *(const float4*)(g_qkv + base + 2*D_);
      *(uint4*)&Ks[row][c4] = make_uint4(tf32c(kv.x), tf32c(kv.y), tf32c(kv.z), tf32c(kv.w));
      *(uint4*)&Vs[row][c4] = make_uint4(tf32c(vv.x), tf32c(vv.y), tf32c(vv.z), tf32c(vv.w));
    }
    if (tid < 64) {
      ts[tid] = g_t[b*L_ + j0g + tid];
      ms[tid] = g_mask[b*L_ + j0g + tid];
    }
    __syncthreads();

    float sA[8][4];
#pragma unroll
    for (int nt = 0; nt < 8; nt++) { sA[nt][0]=0.f; sA[nt][1]=0.f; sA[nt][2]=0.f; sA[nt][3]=0.f; }
#pragma unroll
    for (int kk = 0; kk < 4; kk++) {
      int ac = kk*8 + (lane & 3);
#pragma unroll
      for (int nt = 0; nt < 8; nt++) {
        unsigned bb[2];
        int r = nt*8 + (lane >> 2);
        bb[0] = Ks[r][ac]; bb[1] = Ks[r][ac+4];
        mma_tf32(sA[nt], qa[kk], bb, sA[nt]);
      }
    }

    float tmax0 = -1e30f, tmax1 = -1e30f;
#pragma unroll
    for (int nt = 0; nt < 8; nt++) {
      int jc = nt*8 + 2*(lane & 3);
      float tj0 = ts[jc], tj1 = ts[jc+1];
      bool m0 = ms[jc], m1 = ms[jc+1];
      float b00 = tw*__logf(1.f + fabsf(ti0 - tj0)) + tb;
      float b01 = tw*__logf(1.f + fabsf(ti0 - tj1)) + tb;
      float b10 = tw*__logf(1.f + fabsf(ti1 - tj0)) + tb;
      float b11 = tw*__logf(1.f + fabsf(ti1 - tj1)) + tb;
      sA[nt][0] = m0 ? -1e30f : sA[nt][0]*scale + b00;
      sA[nt][1] = m1 ? -1e30f : sA[nt][1]*scale + b01;
      sA[nt][2] = m0 ? -1e30f : sA[nt][2]*scale + b10;
      sA[nt][3] = m1 ? -1e30f : sA[nt][3]*scale + b11;
      tmax0 = fmaxf(tmax0, fmaxf(sA[nt][0], sA[nt][1]));
      tmax1 = fmaxf(tmax1, fmaxf(sA[nt][2], sA[nt][3]));
    }
    tmax0 = fmaxf(tmax0, __shfl_xor_sync(~0u, tmax0, 1));
    tmax0 = fmaxf(tmax0, __shfl_xor_sync(~0u, tmax0, 2));
    tmax1 = fmaxf(tmax1, __shfl_xor_sync(~0u, tmax1, 1));
    tmax1 = fmaxf(tmax1, __shfl_xor_sync(~0u, tmax1, 2));
    float mn0 = fmaxf(mrow0, tmax0), mn1 = fmaxf(mrow1, tmax1);
    float al0 = __expf(mrow0 - mn0), al1 = __expf(mrow1 - mn1);
    mrow0 = mn0; mrow1 = mn1;

    float rs0 = 0.f, rs1 = 0.f;
    int pr = warp*16 + (lane >> 2);
#pragma unroll
    for (int nt = 0; nt < 8; nt++) {
      int jc = nt*8 + 2*(lane & 3);
      float p0 = __expf(sA[nt][0] - mn0), p1 = __expf(sA[nt][1] - mn0);
      float p2 = __expf(sA[nt][2] - mn1), p3 = __expf(sA[nt][3] - mn1);
      rs0 += p0 + p1; rs1 += p2 + p3;
      SB[pr][jc]     = tf32c(p0); SB[pr][jc+1]   = tf32c(p1);
      SB[pr+8][jc]   = tf32c(p2); SB[pr+8][jc+1] = tf32c(p3);
    }
    rs0 += __shfl_xor_sync(~0u, rs0, 1); rs0 += __shfl_xor_sync(~0u, rs0, 2);
    rs1 += __shfl_xor_sync(~0u, rs1, 1); rs1 += __shfl_xor_sync(~0u, rs1, 2);
    lrow0 = lrow0*al0 + rs0; lrow1 = lrow1*al1 + rs1;
#pragma unroll
    for (int nt = 0; nt < 4; nt++) {
      oacc[nt][0] *= al0; oacc[nt][1] *= al0;
      oacc[nt][2] *= al1; oacc[nt][3] *= al1;
    }
    __syncwarp();

#pragma unroll
    for (int kk = 0; kk < 8; kk++) {
      unsigned pa[4];
      int ac = kk*8 + (lane & 3);
      pa[0] = SB[pr][ac];   pa[1] = SB[pr+8][ac];
      pa[2] = SB[pr][ac+4]; pa[3] = SB[pr+8][ac+4];
#pragma unroll
      for (int nt = 0; nt < 4; nt++) {
        unsigned vb[2];
        int kr = kk*8 + (lane & 3);
        int nc = nt*8 + (lane >> 2);
        vb[0] = Vs[kr][nc]; vb[1] = Vs[kr+4][nc];
        mma_tf32(oacc[nt], pa, vb, oacc[nt]);
      }
    }
    __syncthreads();
  }

  float inv0 = 1.f / lrow0, inv1 = 1.f / lrow1;
  int rr = i0 + warp*16 + (lane >> 2);
#pragma unroll
  for (int nt = 0; nt < 4; nt++) {
    int c = h*DH_ + nt*8 + 2*(lane & 3);
    *(float2*)(g_o + (long)(b*L_ + rr)*D_ + c) =
        make_float2(oacc[nt][0]*inv0, oacc[nt][1]*inv0);
    *(float2*)(g_o + (long)(b*L_ + rr + 8)*D_ + c) =
        make_float2(oacc[nt][2]*inv1, oacc[nt][3]*inv1);
  }
}

// ---------------- x = LN(x + r) * g + b : 4 rows / CTA, float4 lanes ----------
__global__ __launch_bounds__(256) void add_ln_kernel(
    float* __restrict__ x, const float* __restrict__ r,
    const float* __restrict__ g, const float* __restrict__ bt) {
  int row0 = blockIdx.x * 4;
  if ((row0 & (L_-1)) >= g_len[row0 >> 10]) return;   // all 4 rows padded
  int tid = threadIdx.x;
  int sub = tid >> 6, t = tid & 63;          // row-in-block, lane-in-row
  int row = row0 + sub;
  int lane = tid & 31, warp = tid >> 5;
  bool valid = (row & (L_-1)) < g_len[row >> 10];
  __shared__ float red[8];

  float4 xv = *(const float4*)(x + (long)row*D_ + t*4);
  float4 rv = *(const float4*)(r + (long)row*D_ + t*4);
  float4 v = make_float4(xv.x+rv.x, xv.y+rv.y, xv.z+rv.z, xv.w+rv.w);
  float s = v.x + v.y + v.z + v.w;
#pragma unroll
  for (int off = 16; off; off >>= 1) s += __shfl_xor_sync(~0u, s, off);
  if (lane == 0) red[warp] = s;
  __syncthreads();
  float mean = (red[sub*2] + red[sub*2+1]) * (1.f/D_);
  float4 c = make_float4(v.x-mean, v.y-mean, v.z-mean, v.w-mean);
  float s2 = c.x*c.x + c.y*c.y + c.z*c.z + c.w*c.w;
  __syncthreads();
#pragma unroll
  for (int off = 16; off; off >>= 1) s2 += __shfl_xor_sync(~0u, s2, off);
  if (lane == 0) red[warp] = s2;
  __syncthreads();
  float rstd = rsqrtf((red[sub*2] + red[sub*2+1]) * (1.f/D_) + 1e-5f);
  float4 gv = *(const float4*)(g + t*4);
  float4 bv = *(const float4*)(bt + t*4);
  if (valid) {
    *(float4*)(x + (long)row*D_ + t*4) = make_float4(
        c.x*rstd*gv.x + bv.x, c.y*rstd*gv.y + bv.y,
        c.z*rstd*gv.z + bv.z, c.w*rstd*gv.w + bv.w);
  }
}

// ---------------- final head ----------------
__global__ __launch_bounds__(256) void head_kernel(
    const float* __restrict__ w1, const float* __restrict__ b1,
    const float* __restrict__ w2, const float* __restrict__ b2,
    float* __restrict__ out, int out_size) {
  int b = blockIdx.x, tid = threadIdx.x;
  int idx = g_len[b] - 1;
  __shared__ float ls[D_];
  float xv = g_x[(long)(b*L_+idx)*D_ + tid];
  ls[tid] = xv;
  if (16 + b*D_ + tid < out_size)
    out[16 + b*D_ + tid] = xv;
  __syncthreads();
  __shared__ float hh[128];
  if (tid < 128) {
    float s = b1[tid];
    const float4* wp = (const float4*)(w1 + tid*D_);
#pragma unroll 8
    for (int k4 = 0; k4 < D_/4; k4++) {
      float4 w = wp[k4];
      s += ls[k4*4+0]*w.x + ls[k4*4+1]*w.y + ls[k4*4+2]*w.z + ls[k4*4+3]*w.w;
    }
    hh[tid] = fmaxf(s, 0.f);
  }
  __syncthreads();
  if (tid < 32) {
    float s = 0.f;
    for (int j = tid; j < 128; j += 32) s += hh[j]*w2[j];
#pragma unroll
    for (int off = 16; off; off >>= 1) s += __shfl_xor_sync(~0u, s, off);
    if (tid == 0) out[b] = s + b2[0];
  }
}

// ---------------- host ----------------
extern "C" void kernel_launch(void* const* d_in, const int* in_sizes, int n_in,
                              void* d_out, int out_size) {
  const float* feat  = (const float*)d_in[0];
  const void*  maskraw = d_in[1];
  const float* pe    = (const float*)d_in[2];
  const float* in_w  = (const float*)d_in[3];
  const float* in_b  = (const float*)d_in[4];
  const float* time_w= (const float*)d_in[5];
  const float* time_b= (const float*)d_in[6];
  const float* qkv_w = (const float*)d_in[7];
  const float* qkv_b = (const float*)d_in[8];
  const float* out_w = (const float*)d_in[9];
  const float* out_b = (const float*)d_in[10];
  const float* ln1_g = (const float*)d_in[11];
  const float* ln1_b = (const float*)d_in[12];
  const float* ff1_w = (const float*)d_in[13];
  const float* ff1_b = (const float*)d_in[14];
  const float* ff2_w = (const float*)d_in[15];
  const float* ff2_b = (const float*)d_in[16];
  const float* ln2_g = (const float*)d_in[17];
  const float* ln2_b = (const float*)d_in[18];
  const float* reg1_w= (const float*)d_in[19];
  const float* reg1_b= (const float*)d_in[20];
  const float* reg2_w= (const float*)d_in[21];
  const float* reg2_b= (const float*)d_in[22];
  float* out = (float*)d_out;

  float *px, *pqkv, *po, *pp, *ph;
  cudaGetSymbolAddress((void**)&px,  g_x);
  cudaGetSymbolAddress((void**)&pqkv,g_qkv);
  cudaGetSymbolAddress((void**)&po,  g_o);
  cudaGetSymbolAddress((void**)&pp,  g_p);
  cudaGetSymbolAddress((void**)&ph,  g_h);

  static int smem_set = 0;
  if (!smem_set) {
    cudaFuncSetAttribute(attn_mma, cudaFuncAttributeMaxDynamicSharedMemorySize,
                         ATTN_SMEM_BYTES);
    smem_set = 1;
  }

  // 1: prep (mask dtype + convert + len + time cumsum)
  prep_kernel<<<B_, 1024>>>((const unsigned int*)maskraw, feat);
  // 2: embed as TF32 GEMM with +pe epilogue
  gemm_tc<false,true><<<dim3(D_/64, BL_/128), 256>>>(
      feat, in_w, in_b, px, pe, D_, IN_);

  for (int layer = 0; layer < NL_; layer++) {
    gemm_tc<false,false><<<dim3(3*D_/64, BL_/128), 256>>>(
        px, qkv_w + layer*3*D_*D_, qkv_b + layer*3*D_, pqkv, nullptr, 3*D_, D_);
    attn_mma<<<dim3(L_/128, B_*H_), 256, ATTN_SMEM_BYTES>>>(time_w, time_b);
    gemm_tc<false,false><<<dim3(D_/64, BL_/128), 256>>>(
        po, out_w + layer*D_*D_, out_b + layer*D_, pp, nullptr, D_, D_);
    add_ln_kernel<<<BL_/4, 256>>>(px, pp, ln1_g + layer*D_, ln1_b + layer*D_);
    gemm_tc<true,false><<<dim3(DFF_/64, BL_/128), 256>>>(
        px, ff1_w + layer*DFF_*D_, ff1_b + layer*DFF_, ph, nullptr, DFF_, D_);
    gemm_tc<false,false><<<dim3(D_/64, BL_/128), 256>>>(
        ph, ff2_w + layer*D_*DFF_, ff2_b + layer*D_, pp, nullptr, D_, DFF_);
    add_ln_kernel<<<BL_/4, 256>>>(px, pp, ln2_g + layer*D_, ln2_b + layer*D_);
  }

  head_kernel<<<B_, 256>>>(reg1_w, reg1_b, reg2_w, reg2_b, out, out_size);
}

// round 6
// speedup vs baseline: 6.0486x; 1.0503x over previous
#include <cuda_runtime.h>
#include <math.h>

#define B_   16
#define L_   1024
#define IN_  32
#define D_   256
#define H_   8
#define NL_  2
#define DFF_ 1024
#define DH_  32
#define BL_  (B_*L_)

// ---------------- scratch (device globals; zero-initialized) ----------------
__device__ float g_x[BL_*D_];
__device__ float g_qkv[BL_*3*D_];
__device__ float g_o[BL_*D_];
__device__ float g_p[BL_*D_];
__device__ float g_h[BL_*DFF_];
__device__ float g_t[BL_];
__device__ unsigned char g_mask[BL_];
__device__ int g_len[B_];

// ---------------- tf32 helpers ----------------
__device__ __forceinline__ unsigned tf32c(float f) {
  unsigned u; asm("cvt.rna.tf32.f32 %0, %1;" : "=r"(u) : "f"(f)); return u;
}
__device__ __forceinline__ uint4 cvt4(float4 v) {
  return make_uint4(tf32c(v.x), tf32c(v.y), tf32c(v.z), tf32c(v.w));
}
__device__ __forceinline__ void mma_tf32(float* d, const unsigned* a,
                                         const unsigned* b, const float* c) {
  asm volatile(
    "mma.sync.aligned.m16n8k8.row.col.f32.tf32.tf32.f32 "
    "{%0,%1,%2,%3},{%4,%5,%6,%7},{%8,%9},{%10,%11,%12,%13};"
    : "=f"(d[0]),"=f"(d[1]),"=f"(d[2]),"=f"(d[3])
    : "r"(a[0]),"r"(a[1]),"r"(a[2]),"r"(a[3]),
      "r"(b[0]),"r"(b[1]),
      "f"(c[0]),"f"(c[1]),"f"(c[2]),"f"(c[3]));
}
// read 8 consecutive words (2x LDS.128)
__device__ __forceinline__ void lds8(unsigned* d, const unsigned* p) {
  uint4 a = *(const uint4*)p; uint4 b = *(const uint4*)(p+4);
  d[0]=a.x; d[1]=a.y; d[2]=a.z; d[3]=a.w;
  d[4]=b.x; d[5]=b.y; d[6]=b.z; d[7]=b.w;
}

// ---------------- fused prep ----------------
__global__ __launch_bounds__(1024) void prep_kernel(
    const unsigned int* __restrict__ mraw, const float* __restrict__ feat) {
  __shared__ int bad;
  __shared__ int slen;
  __shared__ float wsum[32];
  int b = blockIdx.x, tid = threadIdx.x;
  int lane = tid & 31, warp = tid >> 5;
  if (tid == 0) { bad = 0; slen = 0; }
  __syncthreads();
  for (int k = tid; k < 4096; k += 1024) {
    unsigned v = mraw[k];
    if (v != 0u && v != 1u && v != 0x3F800000u) atomicOr(&bad, 1);
  }
  __syncthreads();
  int mode4 = !bad;
  int j = b*L_ + tid;
  unsigned char m = mode4 ? (mraw[j] != 0u)
                          : (((const unsigned char*)mraw)[j] != 0);
  g_mask[j] = m;
  if (!m) atomicAdd(&slen, 1);
  float v = feat[(long)j*IN_ + (IN_-2)];
#pragma unroll
  for (int off = 1; off < 32; off <<= 1) {
    float n = __shfl_up_sync(~0u, v, off);
    if (lane >= off) v += n;
  }
  if (lane == 31) wsum[warp] = v;
  __syncthreads();
  if (warp == 0) {
    float w = wsum[lane];
#pragma unroll
    for (int off = 1; off < 32; off <<= 1) {
      float n = __shfl_up_sync(~0u, w, off);
      if (lane >= off) w += n;
    }
    wsum[lane] = w;
  }
  __syncthreads();
  float base = warp ? wsum[warp-1] : 0.f;
  g_t[j] = v + base;
  if (tid == 0) g_len[b] = slen;
}

// ---------------- TF32 GEMM, permuted smem + LDS.128 frags ----------------
// C[M,N] = A[M,K] @ W[N,K]^T + bias (+pe if PE) (+relu if RELU)
// BM=128, BN=64, BK=32; 256 threads = 8 warps (4m x 2n)
template<bool RELU, bool PE>
__global__ __launch_bounds__(256) void gemm_tc(
    const float* __restrict__ A, const float* __restrict__ W,
    const float* __restrict__ bias, float* __restrict__ C,
    const float* __restrict__ pe, int N, int K) {
  int m_blk = blockIdx.y * 128, n_blk = blockIdx.x * 64;
  if ((m_blk & (L_-1)) >= g_len[m_blk >> 10]) return;
  __shared__ unsigned As[128][36];   // permuted cols, stride 36
  __shared__ unsigned Bs[64][36];
  int tid = threadIdx.x, lane = tid & 31, warp = tid >> 5;
  int wm = warp >> 1, wn = warp & 1;
  int gr = lane >> 2, q = lane & 3;
  float acc[2][4][4] = {};
  int lr = tid >> 3, lc8 = tid & 7;            // row 0..31(+p*32), col-group
  const float* Ab = A + (long)(m_blk + lr)*K + lc8*4;
  const float* Wb = W + (long)(n_blk + lr)*K + lc8*4;

  float4 pa[4], pb[2];
#pragma unroll
  for (int p = 0; p < 4; p++) pa[p] = *(const float4*)(Ab + (long)p*32*K);
#pragma unroll
  for (int p = 0; p < 2; p++) pb[p] = *(const float4*)(Wb + (long)p*32*K);

  for (int k0 = 0; k0 < K; k0 += 32) {
#pragma unroll
    for (int p = 0; p < 4; p++) {
      As[lr+p*32][0*8+lc8] = tf32c(pa[p].x);
      As[lr+p*32][1*8+lc8] = tf32c(pa[p].y);
      As[lr+p*32][2*8+lc8] = tf32c(pa[p].z);
      As[lr+p*32][3*8+lc8] = tf32c(pa[p].w);
    }
#pragma unroll
    for (int p = 0; p < 2; p++) {
      Bs[lr+p*32][0*8+lc8] = tf32c(pb[p].x);
      Bs[lr+p*32][1*8+lc8] = tf32c(pb[p].y);
      Bs[lr+p*32][2*8+lc8] = tf32c(pb[p].z);
      Bs[lr+p*32][3*8+lc8] = tf32c(pb[p].w);
    }
    __syncthreads();
    if (k0 + 32 < K) {
#pragma unroll
      for (int p = 0; p < 4; p++) pa[p] = *(const float4*)(Ab + k0+32 + (long)p*32*K);
#pragma unroll
      for (int p = 0; p < 2; p++) pb[p] = *(const float4*)(Wb + k0+32 + (long)p*32*K);
    }
    unsigned aLo[2][8], aHi[2][8];
#pragma unroll
    for (int mt = 0; mt < 2; mt++) {
      int r = wm*32 + mt*16 + gr;
      lds8(aLo[mt], &As[r][q*8]);
      lds8(aHi[mt], &As[r+8][q*8]);
    }
#pragma unroll
    for (int nt = 0; nt < 4; nt++) {
      int rb = wn*32 + nt*8 + gr;
      unsigned bf[8];
      lds8(bf, &Bs[rb][q*8]);
#pragma unroll
      for (int kk = 0; kk < 4; kk++) {
        unsigned bb[2] = { bf[2*kk], bf[2*kk+1] };
#pragma unroll
        for (int mt = 0; mt < 2; mt++) {
          unsigned aa[4] = { aLo[mt][2*kk], aHi[mt][2*kk],
                            aLo[mt][2*kk+1], aHi[mt][2*kk+1] };
          mma_tf32(acc[mt][nt], aa, bb, acc[mt][nt]);
        }
      }
    }
    __syncthreads();
  }
#pragma unroll
  for (int mt = 0; mt < 2; mt++) {
    int r0 = m_blk + wm*32 + mt*16 + gr;
#pragma unroll
    for (int nt = 0; nt < 4; nt++) {
      int c0 = n_blk + wn*32 + nt*8 + 2*q;
      float b0v = bias[c0], b1v = bias[c0+1];
      float v0 = acc[mt][nt][0] + b0v, v1 = acc[mt][nt][1] + b1v;
      float v2 = acc[mt][nt][2] + b0v, v3 = acc[mt][nt][3] + b1v;
      if (PE) {
        v0 += pe[(long)(r0 & (L_-1))*D_ + c0];
        v1 += pe[(long)(r0 & (L_-1))*D_ + c0 + 1];
        v2 += pe[(long)((r0+8) & (L_-1))*D_ + c0];
        v3 += pe[(long)((r0+8) & (L_-1))*D_ + c0 + 1];
      }
      if (RELU) { v0=fmaxf(v0,0.f); v1=fmaxf(v1,0.f); v2=fmaxf(v2,0.f); v3=fmaxf(v3,0.f); }
      *(float2*)(C + (long)r0*N + c0)     = make_float2(v0, v1);
      *(float2*)(C + (long)(r0+8)*N + c0) = make_float2(v2, v3);
    }
  }
}

// ---------------- flash attention: 4 warps x 32 queries, perm layouts ------
// smem (words): QP[128][68] @0, Ks[64][36] @8704, Vs[64][40] @11008,
//               tq[128] @13568, ts[64] @13696, ms @13760
#define ATT_SMEM (13792*4)
__global__ __launch_bounds__(128, 3) void attn_mma(
    const float* __restrict__ tw_p, const float* __restrict__ tb_p) {
  extern __shared__ unsigned smem[];
  unsigned (*QP)[68] = (unsigned(*)[68])(smem);          // Q then P (warp-private rows)
  unsigned (*Ks)[36] = (unsigned(*)[36])(smem + 8704);
  unsigned (*Vs)[40] = (unsigned(*)[40])(smem + 11008);
  float* tq = (float*)(smem + 13568);
  float* ts = (float*)(smem + 13696);
  unsigned char* ms = (unsigned char*)(smem + 13760);

  int bh = blockIdx.y, b = bh >> 3, h = bh & 7;
  int tid = threadIdx.x, lane = tid & 31, warp = tid >> 5;
  int gr = lane >> 2, q = lane & 3;
  int i0 = blockIdx.x * 128;
  int len = g_len[b];
  if (i0 >= len) return;
  int njt = (len + 63) >> 6;

  float tw = -fabsf(tw_p[0]);
  float tb = tb_p[0];
  const float scale = 0.17677669529663687f;   // 1/sqrt(32)

  // ---- load Q (perm) + query times ----
#pragma unroll
  for (int p = 0; p < 8; p++) {
    int fid = p*128 + tid, row = fid >> 3, c8 = fid & 7;
    float4 v = *(const float4*)(g_qkv + (long)(b*L_ + i0 + row)*(3*D_) + h*DH_ + c8*4);
    QP[row][0*8+c8] = tf32c(v.x); QP[row][1*8+c8] = tf32c(v.y);
    QP[row][2*8+c8] = tf32c(v.z); QP[row][3*8+c8] = tf32c(v.w);
  }
  tq[tid] = g_t[b*L_ + i0 + tid];
  __syncthreads();

  // Q fragments (warp-private rows [warp*32, warp*32+32))
  unsigned qlo[2][8], qhi[2][8];
  float tiv[2][2];
#pragma unroll
  for (int mt = 0; mt < 2; mt++) {
    int r = warp*32 + mt*16 + gr;
    lds8(qlo[mt], &QP[r][q*8]);
    lds8(qhi[mt], &QP[r+8][q*8]);
    tiv[mt][0] = tq[r];
    tiv[mt][1] = tq[r+8];
  }
  __syncwarp();

  float mrow[2][2] = {{-1e30f,-1e30f},{-1e30f,-1e30f}};
  float lrow[2][2] = {};
  float oacc[2][4][4] = {};

  // ---- prefetch tile 0 ----
  float4 pk[4], pv[4];
  float pts = 0.f; unsigned char pms = 0;
  {
#pragma unroll
    for (int p = 0; p < 4; p++) {
      int fid = p*128 + tid, row = fid >> 3, c8 = fid & 7;
      long base = (long)(b*L_ + row)*(3*D_) + h*DH_ + c8*4;
      pk[p] = *(const float4*)(g_qkv + base + D_);
      pv[p] = *(const float4*)(g_qkv + base + 2*D_);
    }
    if (tid < 64) { pts = g_t[b*L_ + tid]; pms = g_mask[b*L_ + tid]; }
  }

  for (int jt = 0; jt < njt; jt++) {
    // ---- store prefetched K (perm) / V (plain) ----
#pragma unroll
    for (int p = 0; p < 4; p++) {
      int fid = p*128 + tid, row = fid >> 3, c8 = fid & 7;
      Ks[row][0*8+c8] = tf32c(pk[p].x); Ks[row][1*8+c8] = tf32c(pk[p].y);
      Ks[row][2*8+c8] = tf32c(pk[p].z); Ks[row][3*8+c8] = tf32c(pk[p].w);
      *(uint4*)&Vs[row][c8*4] = cvt4(pv[p]);
    }
    if (tid < 64) { ts[tid] = pts; ms[tid] = pms; }
    __syncthreads();
    // ---- prefetch tile jt+1 ----
    if (jt + 1 < njt) {
      int j0n = (jt+1) * 64;
#pragma unroll
      for (int p = 0; p < 4; p++) {
        int fid = p*128 + tid, row = fid >> 3, c8 = fid & 7;
        long base = (long)(b*L_ + j0n + row)*(3*D_) + h*DH_ + c8*4;
        pk[p] = *(const float4*)(g_qkv + base + D_);
        pv[p] = *(const float4*)(g_qkv + base + 2*D_);
      }
      if (tid < 64) { pts = g_t[b*L_ + j0n + tid]; pms = g_mask[b*L_ + j0n + tid]; }
    }

    // ---- S = Q K^T + softmax + P store, per m-tile ----
#pragma unroll
    for (int mt = 0; mt < 2; mt++) {
      float sA[8][4] = {};
#pragma unroll
      for (int nt = 0; nt < 8; nt++) {
        unsigned kf[8];
        lds8(kf, &Ks[nt*8+gr][q*8]);
#pragma unroll
        for (int kk = 0; kk < 4; kk++) {
          unsigned bb[2] = { kf[2*kk], kf[2*kk+1] };
          unsigned aa[4] = { qlo[mt][2*kk], qhi[mt][2*kk],
                            qlo[mt][2*kk+1], qhi[mt][2*kk+1] };
          mma_tf32(sA[nt], aa, bb, sA[nt]);
        }
      }
      float ti0 = tiv[mt][0], ti1 = tiv[mt][1];
      float tmax0 = -1e30f, tmax1 = -1e30f;
#pragma unroll
      for (int nt = 0; nt < 8; nt++) {
        int jc = nt*8 + 2*q;
        float tj0 = ts[jc], tj1 = ts[jc+1];
        bool m0 = ms[jc], m1 = ms[jc+1];
        float b00 = tw*__logf(1.f + fabsf(ti0 - tj0)) + tb;
        float b01 = tw*__logf(1.f + fabsf(ti0 - tj1)) + tb;
        float b10 = tw*__logf(1.f + fabsf(ti1 - tj0)) + tb;
        float b11 = tw*__logf(1.f + fabsf(ti1 - tj1)) + tb;
        sA[nt][0] = m0 ? -1e30f : sA[nt][0]*scale + b00;
        sA[nt][1] = m1 ? -1e30f : sA[nt][1]*scale + b01;
        sA[nt][2] = m0 ? -1e30f : sA[nt][2]*scale + b10;
        sA[nt][3] = m1 ? -1e30f : sA[nt][3]*scale + b11;
        tmax0 = fmaxf(tmax0, fmaxf(sA[nt][0], sA[nt][1]));
        tmax1 = fmaxf(tmax1, fmaxf(sA[nt][2], sA[nt][3]));
      }
      tmax0 = fmaxf(tmax0, __shfl_xor_sync(~0u, tmax0, 1));
      tmax0 = fmaxf(tmax0, __shfl_xor_sync(~0u, tmax0, 2));
      tmax1 = fmaxf(tmax1, __shfl_xor_sync(~0u, tmax1, 1));
      tmax1 = fmaxf(tmax1, __shfl_xor_sync(~0u, tmax1, 2));
      float mn0 = fmaxf(mrow[mt][0], tmax0), mn1 = fmaxf(mrow[mt][1], tmax1);
      float al0 = __expf(mrow[mt][0] - mn0), al1 = __expf(mrow[mt][1] - mn1);
      mrow[mt][0] = mn0; mrow[mt][1] = mn1;

      int pr = warp*32 + mt*16 + gr;
      float rs0 = 0.f, rs1 = 0.f;
#pragma unroll
      for (int nt = 0; nt < 8; nt++) {
        float p0 = __expf(sA[nt][0] - mn0), p1 = __expf(sA[nt][1] - mn0);
        float p2 = __expf(sA[nt][2] - mn1), p3 = __expf(sA[nt][3] - mn1);
        rs0 += p0 + p1; rs1 += p2 + p3;
        // P store: global col c = nt*8 + 2q + e; panel = nt>>2
        int c0 = 2*q, c1 = 2*q + 1;
        int colp0 = (nt>>2)*32 + (c0&3)*8 + (nt&3)*2 + ((c0>>2)&1);
        int colp1 = (nt>>2)*32 + (c1&3)*8 + (nt&3)*2 + ((c1>>2)&1);
        QP[pr][colp0]   = tf32c(p0); QP[pr][colp1]   = tf32c(p1);
        QP[pr+8][colp0] = tf32c(p2); QP[pr+8][colp1] = tf32c(p3);
      }
      rs0 += __shfl_xor_sync(~0u, rs0, 1); rs0 += __shfl_xor_sync(~0u, rs0, 2);
      rs1 += __shfl_xor_sync(~0u, rs1, 1); rs1 += __shfl_xor_sync(~0u, rs1, 2);
      lrow[mt][0] = lrow[mt][0]*al0 + rs0;
      lrow[mt][1] = lrow[mt][1]*al1 + rs1;
#pragma unroll
      for (int nt = 0; nt < 4; nt++) {
        oacc[mt][nt][0] *= al0; oacc[mt][nt][1] *= al0;
        oacc[mt][nt][2] *= al1; oacc[mt][nt][3] *= al1;
      }
    }
    __syncwarp();

    // ---- O += P V ----
#pragma unroll
    for (int panel = 0; panel < 2; panel++) {
      unsigned palo[2][8], pahi[2][8];
#pragma unroll
      for (int mt = 0; mt < 2; mt++) {
        int r = warp*32 + mt*16 + gr;
        lds8(palo[mt], &QP[r][panel*32 + q*8]);
        lds8(pahi[mt], &QP[r+8][panel*32 + q*8]);
      }
#pragma unroll
      for (int nt = 0; nt < 4; nt++) {
        int nc = nt*8 + gr;
        unsigned vb[4][2];
#pragma unroll
        for (int k2 = 0; k2 < 4; k2++) {
          int kr = (panel*4 + k2)*8 + q;
          vb[k2][0] = Vs[kr][nc];
          vb[k2][1] = Vs[kr+4][nc];
        }
#pragma unroll
        for (int k2 = 0; k2 < 4; k2++) {
#pragma unroll
          for (int mt = 0; mt < 2; mt++) {
            unsigned aa[4] = { palo[mt][2*k2], pahi[mt][2*k2],
                              palo[mt][2*k2+1], pahi[mt][2*k2+1] };
            mma_tf32(oacc[mt][nt], aa, vb[k2], oacc[mt][nt]);
          }
        }
      }
    }
    __syncthreads();
  }

#pragma unroll
  for (int mt = 0; mt < 2; mt++) {
    float inv0 = 1.f / lrow[mt][0], inv1 = 1.f / lrow[mt][1];
    int rr = i0 + warp*32 + mt*16 + gr;
#pragma unroll
    for (int nt = 0; nt < 4; nt++) {
      int c = h*DH_ + nt*8 + 2*q;
      *(float2*)(g_o + (long)(b*L_ + rr)*D_ + c) =
          make_float2(oacc[mt][nt][0]*inv0, oacc[mt][nt][1]*inv0);
      *(float2*)(g_o + (long)(b*L_ + rr + 8)*D_ + c) =
          make_float2(oacc[mt][nt][2]*inv1, oacc[mt][nt][3]*inv1);
    }
  }
}

// ---------------- x = LN(x + r) * g + b : 4 rows / CTA ----------------
__global__ __launch_bounds__(256) void add_ln_kernel(
    float* __restrict__ x, const float* __restrict__ r,
    const float* __restrict__ g, const float* __restrict__ bt) {
  int row0 = blockIdx.x * 4;
  if ((row0 & (L_-1)) >= g_len[row0 >> 10]) return;
  int tid = threadIdx.x;
  int sub = tid >> 6, t = tid & 63;
  int row = row0 + sub;
  int lane = tid & 31, warp = tid >> 5;
  bool valid = (row & (L_-1)) < g_len[row >> 10];
  __shared__ float red[8];

  float4 xv = *(const float4*)(x + (long)row*D_ + t*4);
  float4 rv = *(const float4*)(r + (long)row*D_ + t*4);
  float4 v = make_float4(xv.x+rv.x, xv.y+rv.y, xv.z+rv.z, xv.w+rv.w);
  float s = v.x + v.y + v.z + v.w;
#pragma unroll
  for (int off = 16; off; off >>= 1) s += __shfl_xor_sync(~0u, s, off);
  if (lane == 0) red[warp] = s;
  __syncthreads();
  float mean = (red[sub*2] + red[sub*2+1]) * (1.f/D_);
  float4 c = make_float4(v.x-mean, v.y-mean, v.z-mean, v.w-mean);
  float s2 = c.x*c.x + c.y*c.y + c.z*c.z + c.w*c.w;
  __syncthreads();
#pragma unroll
  for (int off = 16; off; off >>= 1) s2 += __shfl_xor_sync(~0u, s2, off);
  if (lane == 0) red[warp] = s2;
  __syncthreads();
  float rstd = rsqrtf((red[sub*2] + red[sub*2+1]) * (1.f/D_) + 1e-5f);
  float4 gv = *(const float4*)(g + t*4);
  float4 bv = *(const float4*)(bt + t*4);
  if (valid) {
    *(float4*)(x + (long)row*D_ + t*4) = make_float4(
        c.x*rstd*gv.x + bv.x, c.y*rstd*gv.y + bv.y,
        c.z*rstd*gv.z + bv.z, c.w*rstd*gv.w + bv.w);
  }
}

// ---------------- final head ----------------
__global__ __launch_bounds__(256) void head_kernel(
    const float* __restrict__ w1, const float* __restrict__ b1,
    const float* __restrict__ w2, const float* __restrict__ b2,
    float* __restrict__ out, int out_size) {
  int b = blockIdx.x, tid = threadIdx.x;
  int idx = g_len[b] - 1;
  __shared__ float ls[D_];
  float xv = g_x[(long)(b*L_+idx)*D_ + tid];
  ls[tid] = xv;
  if (16 + b*D_ + tid < out_size)
    out[16 + b*D_ + tid] = xv;
  __syncthreads();
  __shared__ float hh[128];
  if (tid < 128) {
    float s = b1[tid];
    const float4* wp = (const float4*)(w1 + tid*D_);
#pragma unroll 8
    for (int k4 = 0; k4 < D_/4; k4++) {
      float4 w = wp[k4];
      s += ls[k4*4+0]*w.x + ls[k4*4+1]*w.y + ls[k4*4+2]*w.z + ls[k4*4+3]*w.w;
    }
    hh[tid] = fmaxf(s, 0.f);
  }
  __syncthreads();
  if (tid < 32) {
    float s = 0.f;
    for (int j = tid; j < 128; j += 32) s += hh[j]*w2[j];
#pragma unroll
    for (int off = 16; off; off >>= 1) s += __shfl_xor_sync(~0u, s, off);
    if (tid == 0) out[b] = s + b2[0];
  }
}

// ---------------- host ----------------
extern "C" void kernel_launch(void* const* d_in, const int* in_sizes, int n_in,
                              void* d_out, int out_size) {
  const float* feat  = (const float*)d_in[0];
  const void*  maskraw = d_in[1];
  const float* pe    = (const float*)d_in[2];
  const float* in_w  = (const float*)d_in[3];
  const float* in_b  = (const float*)d_in[4];
  const float* time_w= (const float*)d_in[5];
  const float* time_b= (const float*)d_in[6];
  const float* qkv_w = (const float*)d_in[7];
  const float* qkv_b = (const float*)d_in[8];
  const float* out_w = (const float*)d_in[9];
  const float* out_b = (const float*)d_in[10];
  const float* ln1_g = (const float*)d_in[11];
  const float* ln1_b = (const float*)d_in[12];
  const float* ff1_w = (const float*)d_in[13];
  const float* ff1_b = (const float*)d_in[14];
  const float* ff2_w = (const float*)d_in[15];
  const float* ff2_b = (const float*)d_in[16];
  const float* ln2_g = (const float*)d_in[17];
  const float* ln2_b = (const float*)d_in[18];
  const float* reg1_w= (const float*)d_in[19];
  const float* reg1_b= (const float*)d_in[20];
  const float* reg2_w= (const float*)d_in[21];
  const float* reg2_b= (const float*)d_in[22];
  float* out = (float*)d_out;

  float *px, *pqkv, *po, *pp, *ph;
  cudaGetSymbolAddress((void**)&px,  g_x);
  cudaGetSymbolAddress((void**)&pqkv,g_qkv);
  cudaGetSymbolAddress((void**)&po,  g_o);
  cudaGetSymbolAddress((void**)&pp,  g_p);
  cudaGetSymbolAddress((void**)&ph,  g_h);

  static int smem_set = 0;
  if (!smem_set) {
    cudaFuncSetAttribute(attn_mma, cudaFuncAttributeMaxDynamicSharedMemorySize,
                         ATT_SMEM);
    smem_set = 1;
  }

  prep_kernel<<<B_, 1024>>>((const unsigned int*)maskraw, feat);
  gemm_tc<false,true><<<dim3(D_/64, BL_/128), 256>>>(
      feat, in_w, in_b, px, pe, D_, IN_);

  for (int layer = 0; layer < NL_; layer++) {
    gemm_tc<false,false><<<dim3(3*D_/64, BL_/128), 256>>>(
        px, qkv_w + layer*3*D_*D_, qkv_b + layer*3*D_, pqkv, nullptr, 3*D_, D_);
    attn_mma<<<dim3(L_/128, B_*H_), 128, ATT_SMEM>>>(time_w, time_b);
    gemm_tc<false,false><<<dim3(D_/64, BL_/128), 256>>>(
        po, out_w + layer*D_*D_, out_b + layer*D_, pp, nullptr, D_, D_);
    add_ln_kernel<<<BL_/4, 256>>>(px, pp, ln1_g + layer*D_, ln1_b + layer*D_);
    gemm_tc<true,false><<<dim3(DFF_/64, BL_/128), 256>>>(
        px, ff1_w + layer*DFF_*D_, ff1_b + layer*DFF_, ph, nullptr, DFF_, D_);
    gemm_tc<false,false><<<dim3(D_/64, BL_/128), 256>>>(
        ph, ff2_w + layer*D_*DFF_, ff2_b + layer*D_, pp, nullptr, D_, DFF_);
    add_ln_kernel<<<BL_/4, 256>>>(px, pp, ln2_g + layer*D_, ln2_b + layer*D_);
  }

  head_kernel<<<B_, 256>>>(reg1_w, reg1_b, reg2_w, reg2_b, out, out_size);
}

// round 8
// speedup vs baseline: 6.8556x; 1.1334x over previous
#include <cuda_runtime.h>
#include <math.h>

#define B_   16
#define L_   1024
#define IN_  32
#define D_   256
#define H_   8
#define NL_  2
#define DFF_ 1024
#define DH_  32
#define BL_  (B_*L_)

// ---------------- rounded-operand scratch layout ----------------
#define OFF_INW  0
#define SZ_INW   (D_*IN_)
#define OFF_QKVW (OFF_INW+SZ_INW)
#define SZ_QKVW  (NL_*3*D_*D_)
#define OFF_OUTW (OFF_QKVW+SZ_QKVW)
#define SZ_OUTW  (NL_*D_*D_)
#define OFF_FF1W (OFF_OUTW+SZ_OUTW)
#define SZ_FF1W  (NL_*DFF_*D_)
#define OFF_FF2W (OFF_FF1W+SZ_FF1W)
#define SZ_FF2W  (NL_*D_*DFF_)
#define WR_TOTAL (OFF_FF2W+SZ_FF2W)

// ---------------- scratch (device globals; zero-initialized) ----------------
__device__ float g_x[BL_*D_];        // exact activations (residual / outputs)
__device__ float g_xr[BL_*D_];       // rna-tf32-rounded copy (MMA A operand)
__device__ float g_qkv[BL_*3*D_];    // rounded (sole consumer: attention MMA)
__device__ float g_o[BL_*D_];        // rounded (sole consumer: out-proj MMA)
__device__ float g_p[BL_*D_];        // exact (residual only)
__device__ float g_h[BL_*DFF_];      // rounded (sole consumer: FF2 MMA)
__device__ float g_t[BL_];
__device__ unsigned char g_mask[BL_];
__device__ int g_len[B_];
__device__ float g_wr[WR_TOTAL];     // rounded weights
__device__ float g_fr[BL_*IN_];      // rounded features

// ---------------- helpers ----------------
__device__ __forceinline__ unsigned tf32c(float f) {
  unsigned u; asm("cvt.rna.tf32.f32 %0, %1;" : "=r"(u) : "f"(f)); return u;
}
__device__ __forceinline__ float rndf(float f) { return __uint_as_float(tf32c(f)); }
__device__ __forceinline__ void mma_tf32(float* d, const unsigned* a,
                                         const unsigned* b, const float* c) {
  asm volatile(
    "mma.sync.aligned.m16n8k8.row.col.f32.tf32.tf32.f32 "
    "{%0,%1,%2,%3},{%4,%5,%6,%7},{%8,%9},{%10,%11,%12,%13};"
    : "=f"(d[0]),"=f"(d[1]),"=f"(d[2]),"=f"(d[3])
    : "r"(a[0]),"r"(a[1]),"r"(a[2]),"r"(a[3]),
      "r"(b[0]),"r"(b[1]),
      "f"(c[0]),"f"(c[1]),"f"(c[2]),"f"(c[3]));
}
__device__ __forceinline__ void cp16(unsigned* smem_ptr, const void* gptr) {
  unsigned s = (unsigned)__cvta_generic_to_shared(smem_ptr);
  asm volatile("cp.async.ca.shared.global [%0], [%1], 16;" :: "r"(s), "l"(gptr));
}
#define CP_COMMIT asm volatile("cp.async.commit_group;")
#define CP_WAIT1  asm volatile("cp.async.wait_group 1;")
#define CP_WAIT0  asm volatile("cp.async.wait_group 0;")
__device__ __forceinline__ float lg2f(float x) {
  float r; asm("lg2.approx.f32 %0, %1;" : "=f"(r) : "f"(x)); return r;
}
__device__ __forceinline__ float ex2f(float x) {
  float r; asm("ex2.approx.f32 %0, %1;" : "=f"(r) : "f"(x)); return r;
}

// ---------------- weight/feature rounding (one pass) ----------------
__global__ __launch_bounds__(256) void wconv_kernel(
    const float* __restrict__ feat, const float* __restrict__ in_w,
    const float* __restrict__ qkv_w, const float* __restrict__ out_w,
    const float* __restrict__ ff1_w, const float* __restrict__ ff2_w) {
  int g = blockIdx.x*blockDim.x + threadIdx.x;
  int stride = gridDim.x*blockDim.x;
  for (int i = g; i < BL_*IN_; i += stride) g_fr[i] = rndf(feat[i]);
  for (int i = g; i < SZ_INW;  i += stride) g_wr[OFF_INW+i]  = rndf(in_w[i]);
  for (int i = g; i < SZ_QKVW; i += stride) g_wr[OFF_QKVW+i] = rndf(qkv_w[i]);
  for (int i = g; i < SZ_OUTW; i += stride) g_wr[OFF_OUTW+i] = rndf(out_w[i]);
  for (int i = g; i < SZ_FF1W; i += stride) g_wr[OFF_FF1W+i] = rndf(ff1_w[i]);
  for (int i = g; i < SZ_FF2W; i += stride) g_wr[OFF_FF2W+i] = rndf(ff2_w[i]);
}

// ---------------- fused prep ----------------
__global__ __launch_bounds__(1024) void prep_kernel(
    const unsigned int* __restrict__ mraw, const float* __restrict__ feat) {
  __shared__ int bad;
  __shared__ int slen;
  __shared__ float wsum[32];
  int b = blockIdx.x, tid = threadIdx.x;
  int lane = tid & 31, warp = tid >> 5;
  if (tid == 0) { bad = 0; slen = 0; }
  __syncthreads();
  for (int k = tid; k < 4096; k += 1024) {
    unsigned v = mraw[k];
    if (v != 0u && v != 1u && v != 0x3F800000u) atomicOr(&bad, 1);
  }
  __syncthreads();
  int mode4 = !bad;
  int j = b*L_ + tid;
  unsigned char m = mode4 ? (mraw[j] != 0u)
                          : (((const unsigned char*)mraw)[j] != 0);
  g_mask[j] = m;
  if (!m) atomicAdd(&slen, 1);
  float v = feat[(long)j*IN_ + (IN_-2)];
#pragma unroll
  for (int off = 1; off < 32; off <<= 1) {
    float n = __shfl_up_sync(~0u, v, off);
    if (lane >= off) v += n;
  }
  if (lane == 31) wsum[warp] = v;
  __syncthreads();
  if (warp == 0) {
    float w = wsum[lane];
#pragma unroll
    for (int off = 1; off < 32; off <<= 1) {
      float n = __shfl_up_sync(~0u, w, off);
      if (lane >= off) w += n;
    }
    wsum[lane] = w;
  }
  __syncthreads();
  float base = warp ? wsum[warp-1] : 0.f;
  g_t[j] = v + base;
  if (tid == 0) g_len[b] = slen;
}

// ---------------- TF32 GEMM, cp.async double-buffered, pre-rounded inputs --
// WMODE: 0 = C exact fp32; 1 = C rounded; 2 = C exact + C2 rounded
#define GEMM_SMEM (13824*4)
template<int WMODE, bool RELU, bool PE>
__global__ __launch_bounds__(256, 2) void gemm_tc(
    const float* __restrict__ A, const float* __restrict__ W,
    const float* __restrict__ bias, float* __restrict__ C,
    float* __restrict__ C2, const float* __restrict__ pe, int N, int K) {
  int m_blk = blockIdx.y * 128, n_blk = blockIdx.x * 64;
  if ((m_blk & (L_-1)) >= g_len[m_blk >> 10]) return;
  extern __shared__ unsigned gsm[];
  int tid = threadIdx.x, lane = tid & 31, warp = tid >> 5;
  int wm = warp >> 1, wn = warp & 1;
  int gr = lane >> 2, q = lane & 3;
  float acc[2][4][4] = {};

  auto ld_stage = [&](int s, int k0) {
    unsigned* As = gsm + s*4608;
#pragma unroll
    for (int p = 0; p < 4; p++) {
      int id = p*256 + tid, row = id >> 3, c8 = id & 7;
      cp16(As + row*36 + c8*4, A + (long)(m_blk + row)*K + k0 + c8*4);
    }
    unsigned* Bs = gsm + 9216 + s*2304;
#pragma unroll
    for (int p = 0; p < 2; p++) {
      int id = p*256 + tid, row = id >> 3, c8 = id & 7;
      cp16(Bs + row*36 + c8*4, W + (long)(n_blk + row)*K + k0 + c8*4);
    }
  };

  ld_stage(0, 0); CP_COMMIT;
  int st = 0;
  for (int k0 = 0; k0 < K; k0 += 32) {
    if (k0 + 32 < K) { ld_stage(st^1, k0+32); CP_COMMIT; CP_WAIT1; }
    else CP_WAIT0;
    __syncthreads();
    const unsigned* Ac = gsm + st*4608;
    const unsigned* Bc = gsm + 9216 + st*2304;
#pragma unroll
    for (int kk = 0; kk < 4; kk++) {
      int ac = kk*8 + q;
      unsigned a[2][4], bf[4][2];
#pragma unroll
      for (int mt = 0; mt < 2; mt++) {
        int r = wm*32 + mt*16 + gr;
        a[mt][0] = Ac[r*36+ac];     a[mt][1] = Ac[(r+8)*36+ac];
        a[mt][2] = Ac[r*36+ac+4];   a[mt][3] = Ac[(r+8)*36+ac+4];
      }
#pragma unroll
      for (int nt = 0; nt < 4; nt++) {
        int rb = wn*32 + nt*8 + gr;
        bf[nt][0] = Bc[rb*36+ac];   bf[nt][1] = Bc[rb*36+ac+4];
      }
#pragma unroll
      for (int mt = 0; mt < 2; mt++)
#pragma unroll
        for (int nt = 0; nt < 4; nt++)
          mma_tf32(acc[mt][nt], a[mt], bf[nt], acc[mt][nt]);
    }
    __syncthreads();
    st ^= 1;
  }
#pragma unroll
  for (int mt = 0; mt < 2; mt++) {
    int r0 = m_blk + wm*32 + mt*16 + gr;
#pragma unroll
    for (int nt = 0; nt < 4; nt++) {
      int c0 = n_blk + wn*32 + nt*8 + 2*q;
      float b0v = bias[c0], b1v = bias[c0+1];
      float v0 = acc[mt][nt][0] + b0v, v1 = acc[mt][nt][1] + b1v;
      float v2 = acc[mt][nt][2] + b0v, v3 = acc[mt][nt][3] + b1v;
      if (PE) {
        v0 += pe[(long)(r0 & (L_-1))*D_ + c0];
        v1 += pe[(long)(r0 & (L_-1))*D_ + c0 + 1];
        v2 += pe[(long)((r0+8) & (L_-1))*D_ + c0];
        v3 += pe[(long)((r0+8) & (L_-1))*D_ + c0 + 1];
      }
      if (RELU) { v0=fmaxf(v0,0.f); v1=fmaxf(v1,0.f); v2=fmaxf(v2,0.f); v3=fmaxf(v3,0.f); }
      if (WMODE == 0) {
        *(float2*)(C + (long)r0*N + c0)     = make_float2(v0, v1);
        *(float2*)(C + (long)(r0+8)*N + c0) = make_float2(v2, v3);
      } else if (WMODE == 1) {
        *(float2*)(C + (long)r0*N + c0)     = make_float2(rndf(v0), rndf(v1));
        *(float2*)(C + (long)(r0+8)*N + c0) = make_float2(rndf(v2), rndf(v3));
      } else {
        *(float2*)(C + (long)r0*N + c0)      = make_float2(v0, v1);
        *(float2*)(C + (long)(r0+8)*N + c0)  = make_float2(v2, v3);
        *(float2*)(C2 + (long)r0*N + c0)     = make_float2(rndf(v0), rndf(v1));
        *(float2*)(C2 + (long)(r0+8)*N + c0) = make_float2(rndf(v2), rndf(v3));
      }
    }
  }
}

// ---------------- flash attention: persistent CTAs, cp.async, log2 softmax -
// smem words: Pb[128][68] @0 (Q cols 0..31, then P cols 0..63),
//   K 2x[64][36] @8704, V 2x[64][40] @13312,
//   tq[128] @18432, ts 2x64 @18560, ms 2x16w @18688.  total 18720 w.
#define ATT_SMEM (18720*4)
#define N_WORK   (B_*H_*(L_/128))     // 1024 work items
__global__ __launch_bounds__(128, 3) void attn_mma(
    const float* __restrict__ tw_p, const float* __restrict__ tb_p) {
  extern __shared__ unsigned smem[];
  unsigned* Pb = smem;
  float* tq = (float*)(smem + 18432);

  int tid = threadIdx.x, lane = tid & 31, warp = tid >> 5;
  int gr = lane >> 2, q = lane & 3;

  const float LOG2E = 1.4426950408889634f;
  float tw = -fabsf(tw_p[0]);
  float tbL = tb_p[0] * LOG2E;
  const float scaleL = 0.17677669529663687f * LOG2E;

  for (int w = blockIdx.x; w < N_WORK; w += gridDim.x) {
    int iblk = w & 7, bh = w >> 3;
    int b = bh >> 3, h = bh & 7;
    int i0 = iblk * 128;
    int len = g_len[b];
    if (i0 >= len) continue;
    int njt = (len + 63) >> 6;

    auto ld_kv = [&](int s, int j0) {
      unsigned* Kb = smem + 8704 + s*2304;
      unsigned* Vb = smem + 13312 + s*2560;
#pragma unroll
      for (int p = 0; p < 4; p++) {
        int id = p*128 + tid, row = id >> 3, c8 = id & 7;
        long base = (long)(b*L_ + j0 + row)*(3*D_) + h*DH_ + c8*4;
        cp16(Kb + row*36 + c8*4, g_qkv + base + D_);
        cp16(Vb + row*40 + c8*4, g_qkv + base + 2*D_);
      }
      if (tid < 16)      cp16(smem + 18560 + s*64 + tid*4, g_t + b*L_ + j0 + tid*4);
      else if (tid < 20) cp16(smem + 18688 + s*16 + (tid-16)*4,
                              g_mask + b*L_ + j0 + (tid-16)*16);
    };

    // group 1: Q tile + query times
#pragma unroll
    for (int p = 0; p < 8; p++) {
      int id = p*128 + tid, row = id >> 3, c8 = id & 7;
      cp16(Pb + row*68 + c8*4,
           g_qkv + (long)(b*L_ + i0 + row)*(3*D_) + h*DH_ + c8*4);
    }
    if (tid < 32) cp16((unsigned*)tq + tid*4, g_t + b*L_ + i0 + tid*4);
    CP_COMMIT;
    ld_kv(0, 0); CP_COMMIT;
    CP_WAIT1;
    __syncthreads();

    unsigned qf[2][4][4];
    float tiv[2][2];
#pragma unroll
    for (int mt = 0; mt < 2; mt++) {
      int r = warp*32 + mt*16 + gr;
#pragma unroll
      for (int kk = 0; kk < 4; kk++) {
        int ac = kk*8 + q;
        qf[mt][kk][0] = Pb[r*68+ac];     qf[mt][kk][1] = Pb[(r+8)*68+ac];
        qf[mt][kk][2] = Pb[r*68+ac+4];   qf[mt][kk][3] = Pb[(r+8)*68+ac+4];
      }
      tiv[mt][0] = tq[r];
      tiv[mt][1] = tq[r+8];
    }
    __syncwarp();

    float mrow[2][2] = {{-1e30f,-1e30f},{-1e30f,-1e30f}};
    float lrow[2][2] = {};
    float oacc[2][4][4] = {};

    for (int jt = 0; jt < njt; jt++) {
      int cur = jt & 1;
      if (jt + 1 < njt) { ld_kv(cur^1, (jt+1)*64); CP_COMMIT; CP_WAIT1; }
      else CP_WAIT0;
      __syncthreads();
      const unsigned* Kc = smem + 8704 + cur*2304;
      const unsigned* Vc = smem + 13312 + cur*2560;
      const float* tsf = (const float*)(smem + 18560 + cur*64);
      const unsigned char* msf = (const unsigned char*)(smem + 18688 + cur*16);

#pragma unroll
      for (int mt = 0; mt < 2; mt++) {
        float sA[8][4] = {};
#pragma unroll
        for (int nt = 0; nt < 8; nt++) {
          int kr = nt*8 + gr;
#pragma unroll
          for (int kk = 0; kk < 4; kk++) {
            unsigned bb[2] = { Kc[kr*36 + kk*8 + q], Kc[kr*36 + kk*8 + q + 4] };
            mma_tf32(sA[nt], qf[mt][kk], bb, sA[nt]);
          }
        }
        float ti0 = tiv[mt][0], ti1 = tiv[mt][1];
        float tmax0 = -1e30f, tmax1 = -1e30f;
#pragma unroll
        for (int nt = 0; nt < 8; nt++) {
          int jc = nt*8 + 2*q;
          float tj0 = tsf[jc], tj1 = tsf[jc+1];
          bool m0 = msf[jc], m1 = msf[jc+1];
          float l00 = lg2f(1.f + fabsf(ti0 - tj0));
          float l01 = lg2f(1.f + fabsf(ti0 - tj1));
          float l10 = lg2f(1.f + fabsf(ti1 - tj0));
          float l11 = lg2f(1.f + fabsf(ti1 - tj1));
          sA[nt][0] = m0 ? -1e30f : fmaf(sA[nt][0], scaleL, fmaf(tw, l00, tbL));
          sA[nt][1] = m1 ? -1e30f : fmaf(sA[nt][1], scaleL, fmaf(tw, l01, tbL));
          sA[nt][2] = m0 ? -1e30f : fmaf(sA[nt][2], scaleL, fmaf(tw, l10, tbL));
          sA[nt][3] = m1 ? -1e30f : fmaf(sA[nt][3], scaleL, fmaf(tw, l11, tbL));
          tmax0 = fmaxf(tmax0, fmaxf(sA[nt][0], sA[nt][1]));
          tmax1 = fmaxf(tmax1, fmaxf(sA[nt][2], sA[nt][3]));
        }
        tmax0 = fmaxf(tmax0, __shfl_xor_sync(~0u, tmax0, 1));
        tmax0 = fmaxf(tmax0, __shfl_xor_sync(~0u, tmax0, 2));
        tmax1 = fmaxf(tmax1, __shfl_xor_sync(~0u, tmax1, 1));
        tmax1 = fmaxf(tmax1, __shfl_xor_sync(~0u, tmax1, 2));
        float mn0 = fmaxf(mrow[mt][0], tmax0), mn1 = fmaxf(mrow[mt][1], tmax1);
        float al0 = ex2f(mrow[mt][0] - mn0), al1 = ex2f(mrow[mt][1] - mn1);
        mrow[mt][0] = mn0; mrow[mt][1] = mn1;

        int pr = warp*32 + mt*16 + gr;
        float rs0 = 0.f, rs1 = 0.f;
#pragma unroll
        for (int nt = 0; nt < 8; nt++) {
          int jc = nt*8 + 2*q;
          float p0 = ex2f(sA[nt][0] - mn0), p1 = ex2f(sA[nt][1] - mn0);
          float p2 = ex2f(sA[nt][2] - mn1), p3 = ex2f(sA[nt][3] - mn1);
          rs0 += p0 + p1; rs1 += p2 + p3;
          Pb[pr*68 + jc]       = tf32c(p0);
          Pb[pr*68 + jc + 1]   = tf32c(p1);
          Pb[(pr+8)*68 + jc]   = tf32c(p2);
          Pb[(pr+8)*68 + jc+1] = tf32c(p3);
        }
        rs0 += __shfl_xor_sync(~0u, rs0, 1); rs0 += __shfl_xor_sync(~0u, rs0, 2);
        rs1 += __shfl_xor_sync(~0u, rs1, 1); rs1 += __shfl_xor_sync(~0u, rs1, 2);
        lrow[mt][0] = lrow[mt][0]*al0 + rs0;
        lrow[mt][1] = lrow[mt][1]*al1 + rs1;
#pragma unroll
        for (int nt = 0; nt < 4; nt++) {
          oacc[mt][nt][0] *= al0; oacc[mt][nt][1] *= al0;
          oacc[mt][nt][2] *= al1; oacc[mt][nt][3] *= al1;
        }
        __syncwarp();

        // O += P V
#pragma unroll
        for (int kk = 0; kk < 8; kk++) {
          int ac = kk*8 + q;
          unsigned pa[4];
          pa[0] = Pb[pr*68+ac];     pa[1] = Pb[(pr+8)*68+ac];
          pa[2] = Pb[pr*68+ac+4];   pa[3] = Pb[(pr+8)*68+ac+4];
#pragma unroll
          for (int nt = 0; nt < 4; nt++) {
            unsigned vb[2] = { Vc[(kk*8+q)*40 + nt*8 + gr],
                               Vc[(kk*8+q+4)*40 + nt*8 + gr] };
            mma_tf32(oacc[mt][nt], pa, vb, oacc[mt][nt]);
          }
        }
      }
      __syncthreads();
    }

#pragma unroll
    for (int mt = 0; mt < 2; mt++) {
      float inv0 = 1.f / lrow[mt][0], inv1 = 1.f / lrow[mt][1];
      int rr = i0 + warp*32 + mt*16 + gr;
#pragma unroll
      for (int nt = 0; nt < 4; nt++) {
        int c = h*DH_ + nt*8 + 2*q;
        *(float2*)(g_o + (long)(b*L_ + rr)*D_ + c) =
            make_float2(rndf(oacc[mt][nt][0]*inv0), rndf(oacc[mt][nt][1]*inv0));
        *(float2*)(g_o + (long)(b*L_ + rr + 8)*D_ + c) =
            make_float2(rndf(oacc[mt][nt][2]*inv1), rndf(oacc[mt][nt][3]*inv1));
      }
    }
  }
}

// ---------------- x = LN(x + r) * g + b : exact + rounded outputs ----------
__global__ __launch_bounds__(256) void add_ln_kernel(
    float* __restrict__ x, const float* __restrict__ r,
    const float* __restrict__ g, const float* __restrict__ bt) {
  int row0 = blockIdx.x * 4;
  if ((row0 & (L_-1)) >= g_len[row0 >> 10]) return;
  int tid = threadIdx.x;
  int sub = tid >> 6, t = tid & 63;
  int row = row0 + sub;
  int lane = tid & 31, warp = tid >> 5;
  bool valid = (row & (L_-1)) < g_len[row >> 10];
  __shared__ float red[8];

  float4 xv = *(const float4*)(x + (long)row*D_ + t*4);
  float4 rv = *(const float4*)(r + (long)row*D_ + t*4);
  float4 v = make_float4(xv.x+rv.x, xv.y+rv.y, xv.z+rv.z, xv.w+rv.w);
  float s = v.x + v.y + v.z + v.w;
#pragma unroll
  for (int off = 16; off; off >>= 1) s += __shfl_xor_sync(~0u, s, off);
  if (lane == 0) red[warp] = s;
  __syncthreads();
  float mean = (red[sub*2] + red[sub*2+1]) * (1.f/D_);
  float4 c = make_float4(v.x-mean, v.y-mean, v.z-mean, v.w-mean);
  float s2 = c.x*c.x + c.y*c.y + c.z*c.z + c.w*c.w;
  __syncthreads();
#pragma unroll
  for (int off = 16; off; off >>= 1) s2 += __shfl_xor_sync(~0u, s2, off);
  if (lane == 0) red[warp] = s2;
  __syncthreads();
  float rstd = rsqrtf((red[sub*2] + red[sub*2+1]) * (1.f/D_) + 1e-5f);
  float4 gv = *(const float4*)(g + t*4);
  float4 bv = *(const float4*)(bt + t*4);
  if (valid) {
    float o0 = c.x*rstd*gv.x + bv.x, o1 = c.y*rstd*gv.y + bv.y;
    float o2 = c.z*rstd*gv.z + bv.z, o3 = c.w*rstd*gv.w + bv.w;
    *(float4*)(x + (long)row*D_ + t*4) = make_float4(o0, o1, o2, o3);
    *(float4*)(g_xr + (long)row*D_ + t*4) =
        make_float4(rndf(o0), rndf(o1), rndf(o2), rndf(o3));
  }
}

// ---------------- final head ----------------
__global__ __launch_bounds__(256) void head_kernel(
    const float* __restrict__ w1, const float* __restrict__ b1,
    const float* __restrict__ w2, const float* __restrict__ b2,
    float* __restrict__ out, int out_size) {
  int b = blockIdx.x, tid = threadIdx.x;
  int idx = g_len[b] - 1;
  __shared__ float ls[D_];
  float xv = g_x[(long)(b*L_+idx)*D_ + tid];
  ls[tid] = xv;
  if (16 + b*D_ + tid < out_size)
    out[16 + b*D_ + tid] = xv;
  __syncthreads();
  __shared__ float hh[128];
  if (tid < 128) {
    float s = b1[tid];
    const float4* wp = (const float4*)(w1 + tid*D_);
#pragma unroll 8
    for (int k4 = 0; k4 < D_/4; k4++) {
      float4 w = wp[k4];
      s += ls[k4*4+0]*w.x + ls[k4*4+1]*w.y + ls[k4*4+2]*w.z + ls[k4*4+3]*w.w;
    }
    hh[tid] = fmaxf(s, 0.f);
  }
  __syncthreads();
  if (tid < 32) {
    float s = 0.f;
    for (int j = tid; j < 128; j += 32) s += hh[j]*w2[j];
#pragma unroll
    for (int off = 16; off; off >>= 1) s += __shfl_xor_sync(~0u, s, off);
    if (tid == 0) out[b] = s + b2[0];
  }
}

// ---------------- host ----------------
extern "C" void kernel_launch(void* const* d_in, const int* in_sizes, int n_in,
                              void* d_out, int out_size) {
  const float* feat  = (const float*)d_in[0];
  const void*  maskraw = d_in[1];
  const float* pe    = (const float*)d_in[2];
  const float* in_w  = (const float*)d_in[3];
  const float* in_b  = (const float*)d_in[4];
  const float* time_w= (const float*)d_in[5];
  const float* time_b= (const float*)d_in[6];
  const float* qkv_w = (const float*)d_in[7];
  const float* qkv_b = (const float*)d_in[8];
  const float* out_w = (const float*)d_in[9];
  const float* out_b = (const float*)d_in[10];
  const float* ln1_g = (const float*)d_in[11];
  const float* ln1_b = (const float*)d_in[12];
  const float* ff1_w = (const float*)d_in[13];
  const float* ff1_b = (const float*)d_in[14];
  const float* ff2_w = (const float*)d_in[15];
  const float* ff2_b = (const float*)d_in[16];
  const float* ln2_g = (const float*)d_in[17];
  const float* ln2_b = (const float*)d_in[18];
  const float* reg1_w= (const float*)d_in[19];
  const float* reg1_b= (const float*)d_in[20];
  const float* reg2_w= (const float*)d_in[21];
  const float* reg2_b= (const float*)d_in[22];
  float* out = (float*)d_out;

  float *px, *pxr, *pqkv, *po, *pp, *ph, *pwr, *pfr;
  cudaGetSymbolAddress((void**)&px,  g_x);
  cudaGetSymbolAddress((void**)&pxr, g_xr);
  cudaGetSymbolAddress((void**)&pqkv,g_qkv);
  cudaGetSymbolAddress((void**)&po,  g_o);
  cudaGetSymbolAddress((void**)&pp,  g_p);
  cudaGetSymbolAddress((void**)&ph,  g_h);
  cudaGetSymbolAddress((void**)&pwr, g_wr);
  cudaGetSymbolAddress((void**)&pfr, g_fr);

  static int smem_set = 0;
  if (!smem_set) {
    cudaFuncSetAttribute(attn_mma, cudaFuncAttributeMaxDynamicSharedMemorySize, ATT_SMEM);
    cudaFuncSetAttribute(gemm_tc<2,false,true>,  cudaFuncAttributeMaxDynamicSharedMemorySize, GEMM_SMEM);
    cudaFuncSetAttribute(gemm_tc<1,false,false>, cudaFuncAttributeMaxDynamicSharedMemorySize, GEMM_SMEM);
    cudaFuncSetAttribute(gemm_tc<0,false,false>, cudaFuncAttributeMaxDynamicSharedMemorySize, GEMM_SMEM);
    cudaFuncSetAttribute(gemm_tc<1,true,false>,  cudaFuncAttributeMaxDynamicSharedMemorySize, GEMM_SMEM);
    smem_set = 1;
  }

  prep_kernel<<<B_, 1024>>>((const unsigned int*)maskraw, feat);
  wconv_kernel<<<1024, 256>>>(feat, in_w, qkv_w, out_w, ff1_w, ff2_w);
  // embed: rounded feat @ rounded in_w, writes exact g_x + rounded g_xr
  gemm_tc<2,false,true><<<dim3(D_/64, BL_/128), 256, GEMM_SMEM>>>(
      pfr, pwr + OFF_INW, in_b, px, pxr, pe, D_, IN_);

  for (int layer = 0; layer < NL_; layer++) {
    gemm_tc<1,false,false><<<dim3(3*D_/64, BL_/128), 256, GEMM_SMEM>>>(
        pxr, pwr + OFF_QKVW + layer*3*D_*D_, qkv_b + layer*3*D_, pqkv,
        nullptr, nullptr, 3*D_, D_);
    attn_mma<<<444, 128, ATT_SMEM>>>(time_w, time_b);
    gemm_tc<0,false,false><<<dim3(D_/64, BL_/128), 256, GEMM_SMEM>>>(
        po, pwr + OFF_OUTW + layer*D_*D_, out_b + layer*D_, pp,
        nullptr, nullptr, D_, D_);
    add_ln_kernel<<<BL_/4, 256>>>(px, pp, ln1_g + layer*D_, ln1_b + layer*D_);
    gemm_tc<1,true,false><<<dim3(DFF_/64, BL_/128), 256, GEMM_SMEM>>>(
        pxr, pwr + OFF_FF1W + layer*DFF_*D_, ff1_b + layer*DFF_, ph,
        nullptr, nullptr, DFF_, D_);
    gemm_tc<0,false,false><<<dim3(D_/64, BL_/128), 256, GEMM_SMEM>>>(
        ph, pwr + OFF_FF2W + layer*D_*DFF_, ff2_b + layer*D_, pp,
        nullptr, nullptr, D_, DFF_);
    add_ln_kernel<<<BL_/4, 256>>>(px, pp, ln2_g + layer*D_, ln2_b + layer*D_);
  }

  head_kernel<<<B_, 256>>>(reg1_w, reg1_b, reg2_w, reg2_b, out, out_size);
}

// round 10
// speedup vs baseline: 8.8806x; 1.2954x over previous
#include <cuda_runtime.h>
#include <cuda_fp16.h>
#include <math.h>

#define B_   16
#define L_   1024
#define IN_  32
#define D_   256
#define H_   8
#define NL_  2
#define DFF_ 1024
#define DH_  32
#define BL_  (B_*L_)

// ---------------- rounded/half-operand weight layout ----------------
#define OFF_INW  0
#define SZ_INW   (D_*IN_)
#define OFF_QKVW (OFF_INW+SZ_INW)
#define SZ_QKVW  (NL_*3*D_*D_)
#define OFF_OUTW (OFF_QKVW+SZ_QKVW)
#define SZ_OUTW  (NL_*D_*D_)
#define OFF_FF1W (OFF_OUTW+SZ_OUTW)
#define SZ_FF1W  (NL_*DFF_*D_)
#define OFF_FF2W (OFF_FF1W+SZ_FF1W)
#define SZ_FF2W  (NL_*D_*DFF_)
#define WR_TOTAL (OFF_FF2W+SZ_FF2W)

// ---------------- scratch (device globals; zero-initialized) ----------------
__device__ float g_x[BL_*D_];         // exact activations (residual / outputs)
__device__ __half g_xr[BL_*D_];       // half copy (MMA A operand)
__device__ __half g_qkvh[BL_*2*D_];   // Q|K half [BL][512]
__device__ float  g_vf[BL_*D_];       // V fp32 rna-rounded (PV tf32 operand)
__device__ __half g_o[BL_*D_];        // attention out (half, out-proj A)
__device__ float g_p[BL_*D_];         // exact residual
__device__ __half g_h[BL_*DFF_];      // ff hidden half
__device__ float g_t[BL_];
__device__ unsigned char g_mask[BL_];
__device__ int g_len[B_];
__device__ __half g_wh[WR_TOTAL];     // half weights
__device__ __half g_fr[BL_*IN_];      // half features

// ---------------- helpers ----------------
__device__ __forceinline__ unsigned tf32c(float f) {
  unsigned u; asm("cvt.rna.tf32.f32 %0, %1;" : "=r"(u) : "f"(f)); return u;
}
__device__ __forceinline__ float rndf(float f) { return __uint_as_float(tf32c(f)); }
__device__ __forceinline__ void mma_tf32(float* d, const unsigned* a,
                                         const unsigned* b, const float* c) {
  asm volatile(
    "mma.sync.aligned.m16n8k8.row.col.f32.tf32.tf32.f32 "
    "{%0,%1,%2,%3},{%4,%5,%6,%7},{%8,%9},{%10,%11,%12,%13};"
    : "=f"(d[0]),"=f"(d[1]),"=f"(d[2]),"=f"(d[3])
    : "r"(a[0]),"r"(a[1]),"r"(a[2]),"r"(a[3]),
      "r"(b[0]),"r"(b[1]),
      "f"(c[0]),"f"(c[1]),"f"(c[2]),"f"(c[3]));
}
__device__ __forceinline__ void mma_f16(float* d, const unsigned* a,
                                        const unsigned* b, const float* c) {
  asm volatile(
    "mma.sync.aligned.m16n8k16.row.col.f32.f16.f16.f32 "
    "{%0,%1,%2,%3},{%4,%5,%6,%7},{%8,%9},{%10,%11,%12,%13};"
    : "=f"(d[0]),"=f"(d[1]),"=f"(d[2]),"=f"(d[3])
    : "r"(a[0]),"r"(a[1]),"r"(a[2]),"r"(a[3]),
      "r"(b[0]),"r"(b[1]),
      "f"(c[0]),"f"(c[1]),"f"(c[2]),"f"(c[3]));
}
__device__ __forceinline__ void cp16(unsigned* smem_ptr, const void* gptr) {
  unsigned s = (unsigned)__cvta_generic_to_shared(smem_ptr);
  asm volatile("cp.async.ca.shared.global [%0], [%1], 16;" :: "r"(s), "l"(gptr));
}
#define CP_COMMIT asm volatile("cp.async.commit_group;")
#define CP_WAIT1  asm volatile("cp.async.wait_group 1;")
#define CP_WAIT0  asm volatile("cp.async.wait_group 0;")
__device__ __forceinline__ float lg2f(float x) {
  float r; asm("lg2.approx.f32 %0, %1;" : "=f"(r) : "f"(x)); return r;
}
__device__ __forceinline__ float ex2f(float x) {
  float r; asm("ex2.approx.f32 %0, %1;" : "=f"(r) : "f"(x)); return r;
}

// ---------------- weight/feature conversion to half (one pass) ----------------
__global__ __launch_bounds__(256) void wconv_kernel(
    const float* __restrict__ feat, const float* __restrict__ in_w,
    const float* __restrict__ qkv_w, const float* __restrict__ out_w,
    const float* __restrict__ ff1_w, const float* __restrict__ ff2_w) {
  int g = blockIdx.x*blockDim.x + threadIdx.x;
  int stride = gridDim.x*blockDim.x;
  for (int i = g; i < BL_*IN_; i += stride) g_fr[i] = __float2half_rn(feat[i]);
  for (int i = g; i < SZ_INW;  i += stride) g_wh[OFF_INW+i]  = __float2half_rn(in_w[i]);
  for (int i = g; i < SZ_QKVW; i += stride) g_wh[OFF_QKVW+i] = __float2half_rn(qkv_w[i]);
  for (int i = g; i < SZ_OUTW; i += stride) g_wh[OFF_OUTW+i] = __float2half_rn(out_w[i]);
  for (int i = g; i < SZ_FF1W; i += stride) g_wh[OFF_FF1W+i] = __float2half_rn(ff1_w[i]);
  for (int i = g; i < SZ_FF2W; i += stride) g_wh[OFF_FF2W+i] = __float2half_rn(ff2_w[i]);
}

// ---------------- fused prep ----------------
__global__ __launch_bounds__(1024) void prep_kernel(
    const unsigned int* __restrict__ mraw, const float* __restrict__ feat) {
  __shared__ int bad;
  __shared__ int slen;
  __shared__ float wsum[32];
  int b = blockIdx.x, tid = threadIdx.x;
  int lane = tid & 31, warp = tid >> 5;
  if (tid == 0) { bad = 0; slen = 0; }
  __syncthreads();
  for (int k = tid; k < 4096; k += 1024) {
    unsigned v = mraw[k];
    if (v != 0u && v != 1u && v != 0x3F800000u) atomicOr(&bad, 1);
  }
  __syncthreads();
  int mode4 = !bad;
  int j = b*L_ + tid;
  unsigned char m = mode4 ? (mraw[j] != 0u)
                          : (((const unsigned char*)mraw)[j] != 0);
  g_mask[j] = m;
  if (!m) atomicAdd(&slen, 1);
  float v = feat[(long)j*IN_ + (IN_-2)];
#pragma unroll
  for (int off = 1; off < 32; off <<= 1) {
    float n = __shfl_up_sync(~0u, v, off);
    if (lane >= off) v += n;
  }
  if (lane == 31) wsum[warp] = v;
  __syncthreads();
  if (warp == 0) {
    float w = wsum[lane];
#pragma unroll
    for (int off = 1; off < 32; off <<= 1) {
      float n = __shfl_up_sync(~0u, w, off);
      if (lane >= off) w += n;
    }
    wsum[lane] = w;
  }
  __syncthreads();
  float base = warp ? wsum[warp-1] : 0.f;
  g_t[j] = v + base;
  if (tid == 0) g_len[b] = slen;
}

// ---------------- FP16 GEMM, cp.async double-buffered ----------------
// C[M,N] = A[M,K] @ W[N,K]^T + bias. A,W half; accum fp32.
// BM=128, BN=64, BK=32(elem)=16 half2-words; 256 thr = 8 warps (4m x 2n)
// smem words: A 2x(128*20=2560) @0, B 2x(64*20=1280) @5120. total 7680 w.
// WMODE: 0 = Cf fp32; 1 = Ch half; 2 = Cf + Ch; 3 = QKV split (Ch n<512, Cv fp32 rounded)
#define GEMM_SMEM (7680*4)
template<int WMODE, bool RELU, bool PE>
__global__ __launch_bounds__(256, 3) void gemm_tc(
    const __half* __restrict__ A, const __half* __restrict__ W,
    const float* __restrict__ bias, float* __restrict__ Cf,
    __half* __restrict__ Ch, float* __restrict__ Cv,
    const float* __restrict__ pe, int N, int K) {
  int m_blk = blockIdx.y * 128, n_blk = blockIdx.x * 64;
  if ((m_blk & (L_-1)) >= g_len[m_blk >> 10]) return;
  extern __shared__ unsigned gsm[];
  int tid = threadIdx.x, lane = tid & 31, warp = tid >> 5;
  int wm = warp >> 1, wn = warp & 1;
  int gr = lane >> 2, q = lane & 3;
  float acc[2][4][4] = {};

  auto ld_stage = [&](int s, int k0) {
    unsigned* As = gsm + s*2560;
#pragma unroll
    for (int p = 0; p < 2; p++) {
      int id = p*256 + tid, row = id >> 2, c4 = id & 3;
      cp16(As + row*20 + c4*4, A + (long)(m_blk + row)*K + k0 + c4*8);
    }
    unsigned* Bs = gsm + 5120 + s*1280;
    {
      int row = tid >> 2, c4 = tid & 3;
      cp16(Bs + row*20 + c4*4, W + (long)(n_blk + row)*K + k0 + c4*8);
    }
  };

  ld_stage(0, 0); CP_COMMIT;
  int st = 0;
  for (int k0 = 0; k0 < K; k0 += 32) {
    if (k0 + 32 < K) { ld_stage(st^1, k0+32); CP_COMMIT; CP_WAIT1; }
    else CP_WAIT0;
    __syncthreads();
    const unsigned* Ac = gsm + st*2560;
    const unsigned* Bc = gsm + 5120 + st*1280;
#pragma unroll
    for (int kk = 0; kk < 2; kk++) {
      int ac = kk*8 + q;
      unsigned a[2][4], bf[4][2];
#pragma unroll
      for (int mt = 0; mt < 2; mt++) {
        int r = wm*32 + mt*16 + gr;
        a[mt][0] = Ac[r*20+ac];     a[mt][1] = Ac[(r+8)*20+ac];
        a[mt][2] = Ac[r*20+ac+4];   a[mt][3] = Ac[(r+8)*20+ac+4];
      }
#pragma unroll
      for (int nt = 0; nt < 4; nt++) {
        int rb = wn*32 + nt*8 + gr;
        bf[nt][0] = Bc[rb*20+ac];   bf[nt][1] = Bc[rb*20+ac+4];
      }
#pragma unroll
      for (int mt = 0; mt < 2; mt++)
#pragma unroll
        for (int nt = 0; nt < 4; nt++)
          mma_f16(acc[mt][nt], a[mt], bf[nt], acc[mt][nt]);
    }
    __syncthreads();
    st ^= 1;
  }
#pragma unroll
  for (int mt = 0; mt < 2; mt++) {
    int r0 = m_blk + wm*32 + mt*16 + gr;
#pragma unroll
    for (int nt = 0; nt < 4; nt++) {
      int c0 = n_blk + wn*32 + nt*8 + 2*q;
      float b0v = bias[c0], b1v = bias[c0+1];
      float v0 = acc[mt][nt][0] + b0v, v1 = acc[mt][nt][1] + b1v;
      float v2 = acc[mt][nt][2] + b0v, v3 = acc[mt][nt][3] + b1v;
      if (PE) {
        v0 += pe[(long)(r0 & (L_-1))*D_ + c0];
        v1 += pe[(long)(r0 & (L_-1))*D_ + c0 + 1];
        v2 += pe[(long)((r0+8) & (L_-1))*D_ + c0];
        v3 += pe[(long)((r0+8) & (L_-1))*D_ + c0 + 1];
      }
      if (RELU) { v0=fmaxf(v0,0.f); v1=fmaxf(v1,0.f); v2=fmaxf(v2,0.f); v3=fmaxf(v3,0.f); }
      if (WMODE == 3) {
        if (n_blk < 512) {
          *(half2*)(Ch + (long)r0*512 + c0)     = __floats2half2_rn(v0, v1);
          *(half2*)(Ch + (long)(r0+8)*512 + c0) = __floats2half2_rn(v2, v3);
        } else {
          *(float2*)(Cv + (long)r0*256 + c0-512)     = make_float2(rndf(v0), rndf(v1));
          *(float2*)(Cv + (long)(r0+8)*256 + c0-512) = make_float2(rndf(v2), rndf(v3));
        }
      } else {
        if (WMODE == 0 || WMODE == 2) {
          *(float2*)(Cf + (long)r0*N + c0)     = make_float2(v0, v1);
          *(float2*)(Cf + (long)(r0+8)*N + c0) = make_float2(v2, v3);
        }
        if (WMODE == 1 || WMODE == 2) {
          *(half2*)(Ch + (long)r0*N + c0)     = __floats2half2_rn(v0, v1);
          *(half2*)(Ch + (long)(r0+8)*N + c0) = __floats2half2_rn(v2, v3);
        }
      }
    }
  }
}

// ---------------- flash attention: fp16 S, tf32 PV, persistent CTAs -------
// smem words: Pb[128][68] @0 (Q half: 16 words/row; P tf32: 64 words/row),
//   K 2x(64*20=1280) @8704, V 2x(64*40=2560) @11264,
//   tq[128] @16384, ts 2x64 @16512, ms 2x16w @16640.  total 16672 w.
#define ATT_SMEM (16672*4)
#define N_WORK   (B_*H_*(L_/128))
__global__ __launch_bounds__(128, 3) void attn_mma(
    const float* __restrict__ tw_p, const float* __restrict__ tb_p) {
  extern __shared__ unsigned smem[];
  unsigned* Pb = smem;
  float* tq = (float*)(smem + 16384);

  int tid = threadIdx.x, lane = tid & 31, warp = tid >> 5;
  int gr = lane >> 2, q = lane & 3;

  const float LOG2E = 1.4426950408889634f;
  float tw = -fabsf(tw_p[0]);
  float tbL = tb_p[0] * LOG2E;
  const float scaleL = 0.17677669529663687f * LOG2E;

  for (int w = blockIdx.x; w < N_WORK; w += gridDim.x) {
    int iblk = w & 7, bh = w >> 3;
    int b = bh >> 3, h = bh & 7;
    int i0 = iblk * 128;
    int len = g_len[b];
    if (i0 >= len) continue;
    int njt = (len + 63) >> 6;

    auto ld_kv = [&](int s, int j0) {
      unsigned* Kb = smem + 8704 + s*1280;
      unsigned* Vb = smem + 11264 + s*2560;
      // K half: 64 rows x 4 cp16 (32 halves/row)
#pragma unroll
      for (int p = 0; p < 2; p++) {
        int id = p*128 + tid, row = id >> 2, c4 = id & 3;
        cp16(Kb + row*20 + c4*4,
             g_qkvh + (long)(b*L_ + j0 + row)*(2*D_) + D_ + h*DH_ + c4*8);
      }
      // V fp32: 64 rows x 8 cp16 (32 floats/row)
#pragma unroll
      for (int p = 0; p < 4; p++) {
        int id = p*128 + tid, row = id >> 3, c8 = id & 7;
        cp16(Vb + row*40 + c8*4,
             g_vf + (long)(b*L_ + j0 + row)*D_ + h*DH_ + c8*4);
      }
      if (tid < 16)      cp16(smem + 16512 + s*64 + tid*4, g_t + b*L_ + j0 + tid*4);
      else if (tid < 20) cp16(smem + 16640 + s*16 + (tid-16)*4,
                              g_mask + b*L_ + j0 + (tid-16)*16);
    };

    // group 1: Q (half) + query times
#pragma unroll
    for (int p = 0; p < 4; p++) {
      int id = p*128 + tid, row = id >> 2, c4 = id & 3;
      cp16(Pb + row*68 + c4*4,
           g_qkvh + (long)(b*L_ + i0 + row)*(2*D_) + h*DH_ + c4*8);
    }
    if (tid < 32) cp16((unsigned*)tq + tid*4, g_t + b*L_ + i0 + tid*4);
    CP_COMMIT;
    ld_kv(0, 0); CP_COMMIT;
    CP_WAIT1;
    __syncthreads();

    unsigned qf[2][2][4];
    float tiv[2][2];
#pragma unroll
    for (int mt = 0; mt < 2; mt++) {
      int r = warp*32 + mt*16 + gr;
#pragma unroll
      for (int kk = 0; kk < 2; kk++) {
        int ac = kk*8 + q;
        qf[mt][kk][0] = Pb[r*68+ac];     qf[mt][kk][1] = Pb[(r+8)*68+ac];
        qf[mt][kk][2] = Pb[r*68+ac+4];   qf[mt][kk][3] = Pb[(r+8)*68+ac+4];
      }
      tiv[mt][0] = tq[r];
      tiv[mt][1] = tq[r+8];
    }
    __syncwarp();

    float mrow[2][2] = {{-1e30f,-1e30f},{-1e30f,-1e30f}};
    float lrow[2][2] = {};
    float oacc[2][4][4] = {};

    for (int jt = 0; jt < njt; jt++) {
      int cur = jt & 1;
      if (jt + 1 < njt) { ld_kv(cur^1, (jt+1)*64); CP_COMMIT; CP_WAIT1; }
      else CP_WAIT0;
      __syncthreads();
      const unsigned* Kc = smem + 8704 + cur*1280;
      const unsigned* Vc = smem + 11264 + cur*2560;
      const float* tsf = (const float*)(smem + 16512 + cur*64);
      const unsigned char* msf = (const unsigned char*)(smem + 16640 + cur*16);

#pragma unroll
      for (int mt = 0; mt < 2; mt++) {
        // ---- S = Q K^T (fp16 mma, 16x64) ----
        float sA[8][4] = {};
#pragma unroll
        for (int nt = 0; nt < 8; nt++) {
          int kr = nt*8 + gr;
#pragma unroll
          for (int kk = 0; kk < 2; kk++) {
            unsigned bb[2] = { Kc[kr*20 + kk*8 + q], Kc[kr*20 + kk*8 + q + 4] };
            mma_f16(sA[nt], qf[mt][kk], bb, sA[nt]);
          }
        }
        float ti0 = tiv[mt][0], ti1 = tiv[mt][1];
        float tmax0 = -1e30f, tmax1 = -1e30f;
#pragma unroll
        for (int nt = 0; nt < 8; nt++) {
          int jc = nt*8 + 2*q;
          float tj0 = tsf[jc], tj1 = tsf[jc+1];
          bool m0 = msf[jc], m1 = msf[jc+1];
          float l00 = lg2f(1.f + fabsf(ti0 - tj0));
          float l01 = lg2f(1.f + fabsf(ti0 - tj1));
          float l10 = lg2f(1.f + fabsf(ti1 - tj0));
          float l11 = lg2f(1.f + fabsf(ti1 - tj1));
          sA[nt][0] = m0 ? -1e30f : fmaf(sA[nt][0], scaleL, fmaf(tw, l00, tbL));
          sA[nt][1] = m1 ? -1e30f : fmaf(sA[nt][1], scaleL, fmaf(tw, l01, tbL));
          sA[nt][2] = m0 ? -1e30f : fmaf(sA[nt][2], scaleL, fmaf(tw, l10, tbL));
          sA[nt][3] = m1 ? -1e30f : fmaf(sA[nt][3], scaleL, fmaf(tw, l11, tbL));
          tmax0 = fmaxf(tmax0, fmaxf(sA[nt][0], sA[nt][1]));
          tmax1 = fmaxf(tmax1, fmaxf(sA[nt][2], sA[nt][3]));
        }
        tmax0 = fmaxf(tmax0, __shfl_xor_sync(~0u, tmax0, 1));
        tmax0 = fmaxf(tmax0, __shfl_xor_sync(~0u, tmax0, 2));
        tmax1 = fmaxf(tmax1, __shfl_xor_sync(~0u, tmax1, 1));
        tmax1 = fmaxf(tmax1, __shfl_xor_sync(~0u, tmax1, 2));
        float mn0 = fmaxf(mrow[mt][0], tmax0), mn1 = fmaxf(mrow[mt][1], tmax1);
        float al0 = ex2f(mrow[mt][0] - mn0), al1 = ex2f(mrow[mt][1] - mn1);
        mrow[mt][0] = mn0; mrow[mt][1] = mn1;

        int pr = warp*32 + mt*16 + gr;
        float rs0 = 0.f, rs1 = 0.f;
#pragma unroll
        for (int nt = 0; nt < 8; nt++) {
          int jc = nt*8 + 2*q;
          float p0 = ex2f(sA[nt][0] - mn0), p1 = ex2f(sA[nt][1] - mn0);
          float p2 = ex2f(sA[nt][2] - mn1), p3 = ex2f(sA[nt][3] - mn1);
          rs0 += p0 + p1; rs1 += p2 + p3;
          Pb[pr*68 + jc]       = tf32c(p0);
          Pb[pr*68 + jc + 1]   = tf32c(p1);
          Pb[(pr+8)*68 + jc]   = tf32c(p2);
          Pb[(pr+8)*68 + jc+1] = tf32c(p3);
        }
        rs0 += __shfl_xor_sync(~0u, rs0, 1); rs0 += __shfl_xor_sync(~0u, rs0, 2);
        rs1 += __shfl_xor_sync(~0u, rs1, 1); rs1 += __shfl_xor_sync(~0u, rs1, 2);
        lrow[mt][0] = lrow[mt][0]*al0 + rs0;
        lrow[mt][1] = lrow[mt][1]*al1 + rs1;
#pragma unroll
        for (int nt = 0; nt < 4; nt++) {
          oacc[mt][nt][0] *= al0; oacc[mt][nt][1] *= al0;
          oacc[mt][nt][2] *= al1; oacc[mt][nt][3] *= al1;
        }
        __syncwarp();

        // ---- O += P V (tf32 mma) ----
#pragma unroll
        for (int kk = 0; kk < 8; kk++) {
          int ac = kk*8 + q;
          unsigned pa[4];
          pa[0] = Pb[pr*68+ac];     pa[1] = Pb[(pr+8)*68+ac];
          pa[2] = Pb[pr*68+ac+4];   pa[3] = Pb[(pr+8)*68+ac+4];
#pragma unroll
          for (int nt = 0; nt < 4; nt++) {
            unsigned vb[2] = { Vc[(kk*8+q)*40 + nt*8 + gr],
                               Vc[(kk*8+q+4)*40 + nt*8 + gr] };
            mma_tf32(oacc[mt][nt], pa, vb, oacc[mt][nt]);
          }
        }
      }
      __syncthreads();
    }

#pragma unroll
    for (int mt = 0; mt < 2; mt++) {
      float inv0 = 1.f / lrow[mt][0], inv1 = 1.f / lrow[mt][1];
      int rr = i0 + warp*32 + mt*16 + gr;
#pragma unroll
      for (int nt = 0; nt < 4; nt++) {
        int c = h*DH_ + nt*8 + 2*q;
        *(half2*)(g_o + (long)(b*L_ + rr)*D_ + c) =
            __floats2half2_rn(oacc[mt][nt][0]*inv0, oacc[mt][nt][1]*inv0);
        *(half2*)(g_o + (long)(b*L_ + rr + 8)*D_ + c) =
            __floats2half2_rn(oacc[mt][nt][2]*inv1, oacc[mt][nt][3]*inv1);
      }
    }
  }
}

// ---------------- x = LN(x + r) * g + b : exact fp32 + half copies --------
__global__ __launch_bounds__(256) void add_ln_kernel(
    float* __restrict__ x, const float* __restrict__ r,
    const float* __restrict__ g, const float* __restrict__ bt) {
  int row0 = blockIdx.x * 4;
  if ((row0 & (L_-1)) >= g_len[row0 >> 10]) return;
  int tid = threadIdx.x;
  int sub = tid >> 6, t = tid & 63;
  int row = row0 + sub;
  int lane = tid & 31, warp = tid >> 5;
  bool valid = (row & (L_-1)) < g_len[row >> 10];
  __shared__ float red[8];

  float4 xv = *(const float4*)(x + (long)row*D_ + t*4);
  float4 rv = *(const float4*)(r + (long)row*D_ + t*4);
  float4 v = make_float4(xv.x+rv.x, xv.y+rv.y, xv.z+rv.z, xv.w+rv.w);
  float s = v.x + v.y + v.z + v.w;
#pragma unroll
  for (int off = 16; off; off >>= 1) s += __shfl_xor_sync(~0u, s, off);
  if (lane == 0) red[warp] = s;
  __syncthreads();
  float mean = (red[sub*2] + red[sub*2+1]) * (1.f/D_);
  float4 c = make_float4(v.x-mean, v.y-mean, v.z-mean, v.w-mean);
  float s2 = c.x*c.x + c.y*c.y + c.z*c.z + c.w*c.w;
  __syncthreads();
#pragma unroll
  for (int off = 16; off; off >>= 1) s2 += __shfl_xor_sync(~0u, s2, off);
  if (lane == 0) red[warp] = s2;
  __syncthreads();
  float rstd = rsqrtf((red[sub*2] + red[sub*2+1]) * (1.f/D_) + 1e-5f);
  float4 gv = *(const float4*)(g + t*4);
  float4 bv = *(const float4*)(bt + t*4);
  if (valid) {
    float o0 = c.x*rstd*gv.x + bv.x, o1 = c.y*rstd*gv.y + bv.y;
    float o2 = c.z*rstd*gv.z + bv.z, o3 = c.w*rstd*gv.w + bv.w;
    *(float4*)(x + (long)row*D_ + t*4) = make_float4(o0, o1, o2, o3);
    half2* xr2 = (half2*)(g_xr + (long)row*D_ + t*4);
    xr2[0] = __floats2half2_rn(o0, o1);
    xr2[1] = __floats2half2_rn(o2, o3);
  }
}

// ---------------- final head ----------------
__global__ __launch_bounds__(256) void head_kernel(
    const float* __restrict__ w1, const float* __restrict__ b1,
    const float* __restrict__ w2, const float* __restrict__ b2,
    float* __restrict__ out, int out_size) {
  int b = blockIdx.x, tid = threadIdx.x;
  int idx = g_len[b] - 1;
  __shared__ float ls[D_];
  float xv = g_x[(long)(b*L_+idx)*D_ + tid];
  ls[tid] = xv;
  if (16 + b*D_ + tid < out_size)
    out[16 + b*D_ + tid] = xv;
  __syncthreads();
  __shared__ float hh[128];
  if (tid < 128) {
    float s = b1[tid];
    const float4* wp = (const float4*)(w1 + tid*D_);
#pragma unroll 8
    for (int k4 = 0; k4 < D_/4; k4++) {
      float4 w = wp[k4];
      s += ls[k4*4+0]*w.x + ls[k4*4+1]*w.y + ls[k4*4+2]*w.z + ls[k4*4+3]*w.w;
    }
    hh[tid] = fmaxf(s, 0.f);
  }
  __syncthreads();
  if (tid < 32) {
    float s = 0.f;
    for (int j = tid; j < 128; j += 32) s += hh[j]*w2[j];
#pragma unroll
    for (int off = 16; off; off >>= 1) s += __shfl_xor_sync(~0u, s, off);
    if (tid == 0) out[b] = s + b2[0];
  }
}

// ---------------- host ----------------
extern "C" void kernel_launch(void* const* d_in, const int* in_sizes, int n_in,
                              void* d_out, int out_size) {
  const float* feat  = (const float*)d_in[0];
  const void*  maskraw = d_in[1];
  const float* pe    = (const float*)d_in[2];
  const float* in_w  = (const float*)d_in[3];
  const float* in_b  = (const float*)d_in[4];
  const float* time_w= (const float*)d_in[5];
  const float* time_b= (const float*)d_in[6];
  const float* qkv_w = (const float*)d_in[7];
  const float* qkv_b = (const float*)d_in[8];
  const float* out_w = (const float*)d_in[9];
  const float* out_b = (const float*)d_in[10];
  const float* ln1_g = (const float*)d_in[11];
  const float* ln1_b = (const float*)d_in[12];
  const float* ff1_w = (const float*)d_in[13];
  const float* ff1_b = (const float*)d_in[14];
  const float* ff2_w = (const float*)d_in[15];
  const float* ff2_b = (const float*)d_in[16];
  const float* ln2_g = (const float*)d_in[17];
  const float* ln2_b = (const float*)d_in[18];
  const float* reg1_w= (const float*)d_in[19];
  const float* reg1_b= (const float*)d_in[20];
  const float* reg2_w= (const float*)d_in[21];
  const float* reg2_b= (const float*)d_in[22];
  float* out = (float*)d_out;

  float *px, *pp, *pvf;
  __half *pxr, *pqkvh, *poh, *phh, *pwh, *pfr;
  cudaGetSymbolAddress((void**)&px,   g_x);
  cudaGetSymbolAddress((void**)&pxr,  g_xr);
  cudaGetSymbolAddress((void**)&pqkvh,g_qkvh);
  cudaGetSymbolAddress((void**)&pvf,  g_vf);
  cudaGetSymbolAddress((void**)&poh,  g_o);
  cudaGetSymbolAddress((void**)&pp,   g_p);
  cudaGetSymbolAddress((void**)&phh,  g_h);
  cudaGetSymbolAddress((void**)&pwh,  g_wh);
  cudaGetSymbolAddress((void**)&pfr,  g_fr);

  static int smem_set = 0;
  if (!smem_set) {
    cudaFuncSetAttribute(attn_mma, cudaFuncAttributeMaxDynamicSharedMemorySize, ATT_SMEM);
    cudaFuncSetAttribute(gemm_tc<2,false,true>,  cudaFuncAttributeMaxDynamicSharedMemorySize, GEMM_SMEM);
    cudaFuncSetAttribute(gemm_tc<3,false,false>, cudaFuncAttributeMaxDynamicSharedMemorySize, GEMM_SMEM);
    cudaFuncSetAttribute(gemm_tc<0,false,false>, cudaFuncAttributeMaxDynamicSharedMemorySize, GEMM_SMEM);
    cudaFuncSetAttribute(gemm_tc<1,true,false>,  cudaFuncAttributeMaxDynamicSharedMemorySize, GEMM_SMEM);
    smem_set = 1;
  }

  prep_kernel<<<B_, 1024>>>((const unsigned int*)maskraw, feat);
  wconv_kernel<<<1024, 256>>>(feat, in_w, qkv_w, out_w, ff1_w, ff2_w);
  // embed: half feat @ half in_w -> exact g_x + half g_xr, +pe
  gemm_tc<2,false,true><<<dim3(D_/64, BL_/128), 256, GEMM_SMEM>>>(
      pfr, pwh + OFF_INW, in_b, px, pxr, nullptr, pe, D_, IN_);

  for (int layer = 0; layer < NL_; layer++) {
    // QKV: Q,K half -> g_qkvh; V rounded fp32 -> g_vf
    gemm_tc<3,false,false><<<dim3(3*D_/64, BL_/128), 256, GEMM_SMEM>>>(
        pxr, pwh + OFF_QKVW + layer*3*D_*D_, qkv_b + layer*3*D_,
        nullptr, pqkvh, pvf, nullptr, 3*D_, D_);
    attn_mma<<<444, 128, ATT_SMEM>>>(time_w, time_b);
    gemm_tc<0,false,false><<<dim3(D_/64, BL_/128), 256, GEMM_SMEM>>>(
        poh, pwh + OFF_OUTW + layer*D_*D_, out_b + layer*D_,
        pp, nullptr, nullptr, nullptr, D_, D_);
    add_ln_kernel<<<BL_/4, 256>>>(px, pp, ln1_g + layer*D_, ln1_b + layer*D_);
    gemm_tc<1,true,false><<<dim3(DFF_/64, BL_/128), 256, GEMM_SMEM>>>(
        pxr, pwh + OFF_FF1W + layer*DFF_*D_, ff1_b + layer*DFF_,
        nullptr, phh, nullptr, nullptr, DFF_, D_);
    gemm_tc<0,false,false><<<dim3(D_/64, BL_/128), 256, GEMM_SMEM>>>(
        phh, pwh + OFF_FF2W + layer*D_*DFF_, ff2_b + layer*D_,
        pp, nullptr, nullptr, nullptr, D_, DFF_);
    add_ln_kernel<<<BL_/4, 256>>>(px, pp, ln2_g + layer*D_, ln2_b + layer*D_);
  }

  head_kernel<<<B_, 256>>>(reg1_w, reg1_b, reg2_w, reg2_b, out, out_size);
}

// round 11
// speedup vs baseline: 10.2352x; 1.1525x over previous
#include <cuda_runtime.h>
#include <cuda_fp16.h>
#include <math.h>

#define B_   16
#define L_   1024
#define IN_  32
#define D_   256
#define H_   8
#define NL_  2
#define DFF_ 1024
#define DH_  32
#define BL_  (B_*L_)

// ---------------- half-operand weight layout ----------------
#define OFF_INW  0
#define SZ_INW   (D_*IN_)
#define OFF_QKVW (OFF_INW+SZ_INW)
#define SZ_QKVW  (NL_*3*D_*D_)
#define OFF_OUTW (OFF_QKVW+SZ_QKVW)
#define SZ_OUTW  (NL_*D_*D_)
#define OFF_FF1W (OFF_OUTW+SZ_OUTW)
#define SZ_FF1W  (NL_*DFF_*D_)
#define OFF_FF2W (OFF_FF1W+SZ_FF1W)
#define SZ_FF2W  (NL_*D_*DFF_)
#define WR_TOTAL (OFF_FF2W+SZ_FF2W)

// ---------------- scratch (device globals; zero-initialized) ----------------
__device__ float g_x[BL_*D_];         // exact activations (residual / outputs)
__device__ __half g_xr[BL_*D_];       // half copy (MMA A operand)
__device__ __half g_qkvh[BL_*3*D_];   // Q|K|V half [BL][768]
__device__ __half g_o[BL_*D_];        // attention out (half, out-proj A)
__device__ float g_p[BL_*D_];         // exact residual
__device__ __half g_h[BL_*DFF_];      // ff hidden half
__device__ float g_t[BL_];
__device__ unsigned char g_mask[BL_];
__device__ int g_len[B_];
__device__ __half g_wh[WR_TOTAL];     // half weights
__device__ __half g_fr[BL_*IN_];      // half features

// ---------------- helpers ----------------
__device__ __forceinline__ void mma_f16(float* d, const unsigned* a,
                                        const unsigned* b, const float* c) {
  asm volatile(
    "mma.sync.aligned.m16n8k16.row.col.f32.f16.f16.f32 "
    "{%0,%1,%2,%3},{%4,%5,%6,%7},{%8,%9},{%10,%11,%12,%13};"
    : "=f"(d[0]),"=f"(d[1]),"=f"(d[2]),"=f"(d[3])
    : "r"(a[0]),"r"(a[1]),"r"(a[2]),"r"(a[3]),
      "r"(b[0]),"r"(b[1]),
      "f"(c[0]),"f"(c[1]),"f"(c[2]),"f"(c[3]));
}
__device__ __forceinline__ void ldm4(unsigned* r, unsigned saddr) {
  asm volatile("ldmatrix.sync.aligned.m8n8.x4.shared.b16 {%0,%1,%2,%3}, [%4];"
    : "=r"(r[0]),"=r"(r[1]),"=r"(r[2]),"=r"(r[3]) : "r"(saddr));
}
__device__ __forceinline__ void ldm4t(unsigned* r, unsigned saddr) {
  asm volatile("ldmatrix.sync.aligned.m8n8.x4.trans.shared.b16 {%0,%1,%2,%3}, [%4];"
    : "=r"(r[0]),"=r"(r[1]),"=r"(r[2]),"=r"(r[3]) : "r"(saddr));
}
__device__ __forceinline__ void cp16(unsigned* smem_ptr, const void* gptr) {
  unsigned s = (unsigned)__cvta_generic_to_shared(smem_ptr);
  asm volatile("cp.async.ca.shared.global [%0], [%1], 16;" :: "r"(s), "l"(gptr));
}
#define CP_COMMIT asm volatile("cp.async.commit_group;")
#define CP_WAIT1  asm volatile("cp.async.wait_group 1;")
#define CP_WAIT0  asm volatile("cp.async.wait_group 0;")
__device__ __forceinline__ float lg2f(float x) {
  float r; asm("lg2.approx.f32 %0, %1;" : "=f"(r) : "f"(x)); return r;
}
__device__ __forceinline__ float ex2f(float x) {
  float r; asm("ex2.approx.f32 %0, %1;" : "=f"(r) : "f"(x)); return r;
}
__device__ __forceinline__ unsigned h2u(half2 h) {
  return *reinterpret_cast<unsigned*>(&h);
}

// ---------------- weight/feature conversion to half ----------------
__global__ __launch_bounds__(256) void wconv_kernel(
    const float* __restrict__ feat, const float* __restrict__ in_w,
    const float* __restrict__ qkv_w, const float* __restrict__ out_w,
    const float* __restrict__ ff1_w, const float* __restrict__ ff2_w) {
  int g = blockIdx.x*blockDim.x + threadIdx.x;
  int stride = gridDim.x*blockDim.x;
  for (int i = g; i < BL_*IN_; i += stride) g_fr[i] = __float2half_rn(feat[i]);
  for (int i = g; i < SZ_INW;  i += stride) g_wh[OFF_INW+i]  = __float2half_rn(in_w[i]);
  for (int i = g; i < SZ_QKVW; i += stride) g_wh[OFF_QKVW+i] = __float2half_rn(qkv_w[i]);
  for (int i = g; i < SZ_OUTW; i += stride) g_wh[OFF_OUTW+i] = __float2half_rn(out_w[i]);
  for (int i = g; i < SZ_FF1W; i += stride) g_wh[OFF_FF1W+i] = __float2half_rn(ff1_w[i]);
  for (int i = g; i < SZ_FF2W; i += stride) g_wh[OFF_FF2W+i] = __float2half_rn(ff2_w[i]);
}

// ---------------- fused prep ----------------
__global__ __launch_bounds__(1024) void prep_kernel(
    const unsigned int* __restrict__ mraw, const float* __restrict__ feat) {
  __shared__ int bad;
  __shared__ int slen;
  __shared__ float wsum[32];
  int b = blockIdx.x, tid = threadIdx.x;
  int lane = tid & 31, warp = tid >> 5;
  if (tid == 0) { bad = 0; slen = 0; }
  __syncthreads();
  for (int k = tid; k < 4096; k += 1024) {
    unsigned v = mraw[k];
    if (v != 0u && v != 1u && v != 0x3F800000u) atomicOr(&bad, 1);
  }
  __syncthreads();
  int mode4 = !bad;
  int j = b*L_ + tid;
  unsigned char m = mode4 ? (mraw[j] != 0u)
                          : (((const unsigned char*)mraw)[j] != 0);
  g_mask[j] = m;
  if (!m) atomicAdd(&slen, 1);
  float v = feat[(long)j*IN_ + (IN_-2)];
#pragma unroll
  for (int off = 1; off < 32; off <<= 1) {
    float n = __shfl_up_sync(~0u, v, off);
    if (lane >= off) v += n;
  }
  if (lane == 31) wsum[warp] = v;
  __syncthreads();
  if (warp == 0) {
    float w = wsum[lane];
#pragma unroll
    for (int off = 1; off < 32; off <<= 1) {
      float n = __shfl_up_sync(~0u, w, off);
      if (lane >= off) w += n;
    }
    wsum[lane] = w;
  }
  __syncthreads();
  float base = warp ? wsum[warp-1] : 0.f;
  g_t[j] = v + base;
  if (tid == 0) g_len[b] = slen;
}

// ---------------- FP16 GEMM, cp.async double-buffered, ldmatrix frags -----
// C[M,N] = A[M,K] @ W[N,K]^T + bias. BM=128, BN=64, BK=32; 8 warps (4m x 2n)
// smem words: A 2x(128*20=2560) @0, B 2x(64*20=1280) @5120. total 7680 w.
// WMODE: 0 = Cf fp32; 1 = Ch half; 2 = Cf + Ch
#define GEMM_SMEM (7680*4)
template<int WMODE, bool RELU, bool PE>
__global__ __launch_bounds__(256, 3) void gemm_tc(
    const __half* __restrict__ A, const __half* __restrict__ W,
    const float* __restrict__ bias, float* __restrict__ Cf,
    __half* __restrict__ Ch, const float* __restrict__ pe, int N, int K) {
  int m_blk = blockIdx.y * 128, n_blk = blockIdx.x * 64;
  if ((m_blk & (L_-1)) >= g_len[m_blk >> 10]) return;
  extern __shared__ unsigned gsm[];
  unsigned sbase = (unsigned)__cvta_generic_to_shared(gsm);
  int tid = threadIdx.x, lane = tid & 31, warp = tid >> 5;
  int wm = warp >> 1, wn = warp & 1;
  int gr = lane >> 2, q = lane & 3;
  int l15 = lane & 15, lhi = (lane >> 4) << 2;
  float acc[2][4][4] = {};

  auto ld_stage = [&](int s, int k0) {
    unsigned* As = gsm + s*2560;
#pragma unroll
    for (int p = 0; p < 2; p++) {
      int id = p*256 + tid, row = id >> 2, c4 = id & 3;
      cp16(As + row*20 + c4*4, A + (long)(m_blk + row)*K + k0 + c4*8);
    }
    unsigned* Bs = gsm + 5120 + s*1280;
    {
      int row = tid >> 2, c4 = tid & 3;
      cp16(Bs + row*20 + c4*4, W + (long)(n_blk + row)*K + k0 + c4*8);
    }
  };

  ld_stage(0, 0); CP_COMMIT;
  int st = 0;
  for (int k0 = 0; k0 < K; k0 += 32) {
    if (k0 + 32 < K) { ld_stage(st^1, k0+32); CP_COMMIT; CP_WAIT1; }
    else CP_WAIT0;
    __syncthreads();
#pragma unroll
    for (int kk = 0; kk < 2; kk++) {
      unsigned coff = kk*8 + lhi;
      unsigned afr[2][4];
#pragma unroll
      for (int mt = 0; mt < 2; mt++)
        ldm4(afr[mt], sbase + ((st*2560 + (wm*32 + mt*16 + l15)*20 + coff) << 2));
      unsigned bfr[4][2];
#pragma unroll
      for (int p2 = 0; p2 < 2; p2++) {
        unsigned t[4];
        ldm4(t, sbase + ((5120 + st*1280 + (wn*32 + p2*16 + l15)*20 + coff) << 2));
        bfr[p2*2][0]=t[0];   bfr[p2*2][1]=t[2];
        bfr[p2*2+1][0]=t[1]; bfr[p2*2+1][1]=t[3];
      }
#pragma unroll
      for (int mt = 0; mt < 2; mt++)
#pragma unroll
        for (int nt = 0; nt < 4; nt++)
          mma_f16(acc[mt][nt], afr[mt], bfr[nt], acc[mt][nt]);
    }
    __syncthreads();
    st ^= 1;
  }
#pragma unroll
  for (int mt = 0; mt < 2; mt++) {
    int r0 = m_blk + wm*32 + mt*16 + gr;
#pragma unroll
    for (int nt = 0; nt < 4; nt++) {
      int c0 = n_blk + wn*32 + nt*8 + 2*q;
      float b0v = bias[c0], b1v = bias[c0+1];
      float v0 = acc[mt][nt][0] + b0v, v1 = acc[mt][nt][1] + b1v;
      float v2 = acc[mt][nt][2] + b0v, v3 = acc[mt][nt][3] + b1v;
      if (PE) {
        v0 += pe[(long)(r0 & (L_-1))*D_ + c0];
        v1 += pe[(long)(r0 & (L_-1))*D_ + c0 + 1];
        v2 += pe[(long)((r0+8) & (L_-1))*D_ + c0];
        v3 += pe[(long)((r0+8) & (L_-1))*D_ + c0 + 1];
      }
      if (RELU) { v0=fmaxf(v0,0.f); v1=fmaxf(v1,0.f); v2=fmaxf(v2,0.f); v3=fmaxf(v3,0.f); }
      if (WMODE == 0 || WMODE == 2) {
        *(float2*)(Cf + (long)r0*N + c0)     = make_float2(v0, v1);
        *(float2*)(Cf + (long)(r0+8)*N + c0) = make_float2(v2, v3);
      }
      if (WMODE == 1 || WMODE == 2) {
        *(half2*)(Ch + (long)r0*N + c0)     = __floats2half2_rn(v0, v1);
        *(half2*)(Ch + (long)(r0+8)*N + c0) = __floats2half2_rn(v2, v3);
      }
    }
  }
}

// ---------------- flash attention: full fp16 mma, ldmatrix, persistent ----
// smem words: Pb[128][36] @0 (Q halves 0..31 = words 0..15; P halves 0..63 = words 0..31),
//   K 2x(64*20) @4608, V 2x(64*20) @7168,
//   tq[128] @9728, ts 2x64 @9856, ms 2x16w @9984.  total 10016 w = 40064 B.
#define ATT_SMEM (10016*4)
#define N_WORK   (B_*H_*(L_/128))
__global__ __launch_bounds__(128, 3) void attn_mma(
    const float* __restrict__ tw_p, const float* __restrict__ tb_p) {
  extern __shared__ unsigned smem[];
  unsigned* Pb = smem;
  unsigned sbase = (unsigned)__cvta_generic_to_shared(smem);
  float* tq = (float*)(smem + 9728);

  int tid = threadIdx.x, lane = tid & 31, warp = tid >> 5;
  int gr = lane >> 2, q = lane & 3;
  int l15 = lane & 15, lhi = (lane >> 4) << 2;

  const float LOG2E = 1.4426950408889634f;
  float tw = -fabsf(tw_p[0]);
  float tbL = tb_p[0] * LOG2E;
  const float scaleL = 0.17677669529663687f * LOG2E;

  for (int w = blockIdx.x; w < N_WORK; w += gridDim.x) {
    int iblk = w & 7, bh = w >> 3;
    int b = bh >> 3, h = bh & 7;
    int i0 = iblk * 128;
    int len = g_len[b];
    if (i0 >= len) continue;
    int njt = (len + 63) >> 6;

    auto ld_kv = [&](int s, int j0) {
      unsigned* Kb = smem + 4608 + s*1280;
      unsigned* Vb = smem + 7168 + s*1280;
#pragma unroll
      for (int p = 0; p < 2; p++) {
        int id = p*128 + tid, row = id >> 2, c4 = id & 3;
        long base = (long)(b*L_ + j0 + row)*768 + h*DH_ + c4*8;
        cp16(Kb + row*20 + c4*4, g_qkvh + base + 256);
        cp16(Vb + row*20 + c4*4, g_qkvh + base + 512);
      }
      if (tid < 16)      cp16(smem + 9856 + s*64 + tid*4, g_t + b*L_ + j0 + tid*4);
      else if (tid < 20) cp16(smem + 9984 + s*16 + (tid-16)*4,
                              g_mask + b*L_ + j0 + (tid-16)*16);
    };

    // group 1: Q (half) + query times
#pragma unroll
    for (int p = 0; p < 4; p++) {
      int id = p*128 + tid, row = id >> 2, c4 = id & 3;
      cp16(Pb + row*36 + c4*4,
           g_qkvh + (long)(b*L_ + i0 + row)*768 + h*DH_ + c4*8);
    }
    if (tid < 32) cp16((unsigned*)tq + tid*4, g_t + b*L_ + i0 + tid*4);
    CP_COMMIT;
    ld_kv(0, 0); CP_COMMIT;
    CP_WAIT1;
    __syncthreads();

    unsigned qf[2][2][4];
    float tiv[2][2];
#pragma unroll
    for (int mt = 0; mt < 2; mt++) {
      int r = warp*32 + mt*16;
#pragma unroll
      for (int kk = 0; kk < 2; kk++)
        ldm4(qf[mt][kk], sbase + (((r + l15)*36 + kk*8 + lhi) << 2));
      tiv[mt][0] = tq[r + gr];
      tiv[mt][1] = tq[r + gr + 8];
    }
    __syncwarp();

    float mrow[2][2] = {{-1e30f,-1e30f},{-1e30f,-1e30f}};
    float lrow[2][2] = {};
    float oacc[2][4][4] = {};

    for (int jt = 0; jt < njt; jt++) {
      int cur = jt & 1;
      if (jt + 1 < njt) { ld_kv(cur^1, (jt+1)*64); CP_COMMIT; CP_WAIT1; }
      else CP_WAIT0;
      __syncthreads();
      unsigned kbase = 4608 + cur*1280;
      unsigned vbase = 7168 + cur*1280;
      const float* tsf = (const float*)(smem + 9856 + cur*64);
      const unsigned char* msf = (const unsigned char*)(smem + 9984 + cur*16);

#pragma unroll
      for (int mt = 0; mt < 2; mt++) {
        // ---- S = Q K^T (fp16 mma + ldmatrix) ----
        float sA[8][4] = {};
#pragma unroll
        for (int kk = 0; kk < 2; kk++) {
          unsigned coff = kk*8 + lhi;
#pragma unroll
          for (int p2 = 0; p2 < 4; p2++) {
            unsigned t[4];
            ldm4(t, sbase + ((kbase + (p2*16 + l15)*20 + coff) << 2));
            unsigned b0[2] = { t[0], t[2] };
            unsigned b1[2] = { t[1], t[3] };
            mma_f16(sA[2*p2],   qf[mt][kk], b0, sA[2*p2]);
            mma_f16(sA[2*p2+1], qf[mt][kk], b1, sA[2*p2+1]);
          }
        }
        float ti0 = tiv[mt][0], ti1 = tiv[mt][1];
        float tmax0 = -1e30f, tmax1 = -1e30f;
#pragma unroll
        for (int nt = 0; nt < 8; nt++) {
          int jc = nt*8 + 2*q;
          float tj0 = tsf[jc], tj1 = tsf[jc+1];
          bool m0 = msf[jc], m1 = msf[jc+1];
          float l00 = lg2f(1.f + fabsf(ti0 - tj0));
          float l01 = lg2f(1.f + fabsf(ti0 - tj1));
          float l10 = lg2f(1.f + fabsf(ti1 - tj0));
          float l11 = lg2f(1.f + fabsf(ti1 - tj1));
          sA[nt][0] = m0 ? -1e30f : fmaf(sA[nt][0], scaleL, fmaf(tw, l00, tbL));
          sA[nt][1] = m1 ? -1e30f : fmaf(sA[nt][1], scaleL, fmaf(tw, l01, tbL));
          sA[nt][2] = m0 ? -1e30f : fmaf(sA[nt][2], scaleL, fmaf(tw, l10, tbL));
          sA[nt][3] = m1 ? -1e30f : fmaf(sA[nt][3], scaleL, fmaf(tw, l11, tbL));
          tmax0 = fmaxf(tmax0, fmaxf(sA[nt][0], sA[nt][1]));
          tmax1 = fmaxf(tmax1, fmaxf(sA[nt][2], sA[nt][3]));
        }
        tmax0 = fmaxf(tmax0, __shfl_xor_sync(~0u, tmax0, 1));
        tmax0 = fmaxf(tmax0, __shfl_xor_sync(~0u, tmax0, 2));
        tmax1 = fmaxf(tmax1, __shfl_xor_sync(~0u, tmax1, 1));
        tmax1 = fmaxf(tmax1, __shfl_xor_sync(~0u, tmax1, 2));
        float mn0 = fmaxf(mrow[mt][0], tmax0), mn1 = fmaxf(mrow[mt][1], tmax1);
        float al0 = ex2f(mrow[mt][0] - mn0), al1 = ex2f(mrow[mt][1] - mn1);
        mrow[mt][0] = mn0; mrow[mt][1] = mn1;

        int pr = warp*32 + mt*16 + gr;
        float rs0 = 0.f, rs1 = 0.f;
#pragma unroll
        for (int nt = 0; nt < 8; nt++) {
          float p0 = ex2f(sA[nt][0] - mn0), p1 = ex2f(sA[nt][1] - mn0);
          float p2 = ex2f(sA[nt][2] - mn1), p3 = ex2f(sA[nt][3] - mn1);
          rs0 += p0 + p1; rs1 += p2 + p3;
          Pb[pr*36 + nt*4 + q]     = h2u(__floats2half2_rn(p0, p1));
          Pb[(pr+8)*36 + nt*4 + q] = h2u(__floats2half2_rn(p2, p3));
        }
        rs0 += __shfl_xor_sync(~0u, rs0, 1); rs0 += __shfl_xor_sync(~0u, rs0, 2);
        rs1 += __shfl_xor_sync(~0u, rs1, 1); rs1 += __shfl_xor_sync(~0u, rs1, 2);
        lrow[mt][0] = lrow[mt][0]*al0 + rs0;
        lrow[mt][1] = lrow[mt][1]*al1 + rs1;
#pragma unroll
        for (int nt = 0; nt < 4; nt++) {
          oacc[mt][nt][0] *= al0; oacc[mt][nt][1] *= al0;
          oacc[mt][nt][2] *= al1; oacc[mt][nt][3] *= al1;
        }
        __syncwarp();

        // ---- O += P V (fp16 mma; P via ldmatrix, V via ldmatrix.trans) ----
        int pr0 = warp*32 + mt*16;
#pragma unroll
        for (int kk2 = 0; kk2 < 4; kk2++) {
          unsigned pa[4];
          ldm4(pa, sbase + (((pr0 + l15)*36 + kk2*8 + lhi) << 2));
#pragma unroll
          for (int p2 = 0; p2 < 2; p2++) {
            unsigned t[4];
            ldm4t(t, sbase + ((vbase + (kk2*16 + l15)*20 + p2*8 + lhi) << 2));
            unsigned v0[2] = { t[0], t[1] };
            unsigned v1[2] = { t[2], t[3] };
            mma_f16(oacc[mt][2*p2],   pa, v0, oacc[mt][2*p2]);
            mma_f16(oacc[mt][2*p2+1], pa, v1, oacc[mt][2*p2+1]);
          }
        }
      }
      __syncthreads();
    }

#pragma unroll
    for (int mt = 0; mt < 2; mt++) {
      float inv0 = 1.f / lrow[mt][0], inv1 = 1.f / lrow[mt][1];
      int rr = i0 + warp*32 + mt*16 + gr;
#pragma unroll
      for (int nt = 0; nt < 4; nt++) {
        int c = h*DH_ + nt*8 + 2*q;
        *(half2*)(g_o + (long)(b*L_ + rr)*D_ + c) =
            __floats2half2_rn(oacc[mt][nt][0]*inv0, oacc[mt][nt][1]*inv0);
        *(half2*)(g_o + (long)(b*L_ + rr + 8)*D_ + c) =
            __floats2half2_rn(oacc[mt][nt][2]*inv1, oacc[mt][nt][3]*inv1);
      }
    }
  }
}

// ---------------- x = LN(x + r) * g + b : exact fp32 + half copies --------
__global__ __launch_bounds__(256) void add_ln_kernel(
    float* __restrict__ x, const float* __restrict__ r,
    const float* __restrict__ g, const float* __restrict__ bt) {
  int row0 = blockIdx.x * 4;
  if ((row0 & (L_-1)) >= g_len[row0 >> 10]) return;
  int tid = threadIdx.x;
  int sub = tid >> 6, t = tid & 63;
  int row = row0 + sub;
  int lane = tid & 31, warp = tid >> 5;
  bool valid = (row & (L_-1)) < g_len[row >> 10];
  __shared__ float red[8];

  float4 xv = *(const float4*)(x + (long)row*D_ + t*4);
  float4 rv = *(const float4*)(r + (long)row*D_ + t*4);
  float4 v = make_float4(xv.x+rv.x, xv.y+rv.y, xv.z+rv.z, xv.w+rv.w);
  float s = v.x + v.y + v.z + v.w;
#pragma unroll
  for (int off = 16; off; off >>= 1) s += __shfl_xor_sync(~0u, s, off);
  if (lane == 0) red[warp] = s;
  __syncthreads();
  float mean = (red[sub*2] + red[sub*2+1]) * (1.f/D_);
  float4 c = make_float4(v.x-mean, v.y-mean, v.z-mean, v.w-mean);
  float s2 = c.x*c.x + c.y*c.y + c.z*c.z + c.w*c.w;
  __syncthreads();
#pragma unroll
  for (int off = 16; off; off >>= 1) s2 += __shfl_xor_sync(~0u, s2, off);
  if (lane == 0) red[warp] = s2;
  __syncthreads();
  float rstd = rsqrtf((red[sub*2] + red[sub*2+1]) * (1.f/D_) + 1e-5f);
  float4 gv = *(const float4*)(g + t*4);
  float4 bv = *(const float4*)(bt + t*4);
  if (valid) {
    float o0 = c.x*rstd*gv.x + bv.x, o1 = c.y*rstd*gv.y + bv.y;
    float o2 = c.z*rstd*gv.z + bv.z, o3 = c.w*rstd*gv.w + bv.w;
    *(float4*)(x + (long)row*D_ + t*4) = make_float4(o0, o1, o2, o3);
    half2* xr2 = (half2*)(g_xr + (long)row*D_ + t*4);
    xr2[0] = __floats2half2_rn(o0, o1);
    xr2[1] = __floats2half2_rn(o2, o3);
  }
}

// ---------------- final head ----------------
__global__ __launch_bounds__(256) void head_kernel(
    const float* __restrict__ w1, const float* __restrict__ b1,
    const float* __restrict__ w2, const float* __restrict__ b2,
    float* __restrict__ out, int out_size) {
  int b = blockIdx.x, tid = threadIdx.x;
  int idx = g_len[b] - 1;
  __shared__ float ls[D_];
  float xv = g_x[(long)(b*L_+idx)*D_ + tid];
  ls[tid] = xv;
  if (16 + b*D_ + tid < out_size)
    out[16 + b*D_ + tid] = xv;
  __syncthreads();
  __shared__ float hh[128];
  if (tid < 128) {
    float s = b1[tid];
    const float4* wp = (const float4*)(w1 + tid*D_);
#pragma unroll 8
    for (int k4 = 0; k4 < D_/4; k4++) {
      float4 w = wp[k4];
      s += ls[k4*4+0]*w.x + ls[k4*4+1]*w.y + ls[k4*4+2]*w.z + ls[k4*4+3]*w.w;
    }
    hh[tid] = fmaxf(s, 0.f);
  }
  __syncthreads();
  if (tid < 32) {
    float s = 0.f;
    for (int j = tid; j < 128; j += 32) s += hh[j]*w2[j];
#pragma unroll
    for (int off = 16; off; off >>= 1) s += __shfl_xor_sync(~0u, s, off);
    if (tid == 0) out[b] = s + b2[0];
  }
}

// ---------------- host ----------------
extern "C" void kernel_launch(void* const* d_in, const int* in_sizes, int n_in,
                              void* d_out, int out_size) {
  const float* feat  = (const float*)d_in[0];
  const void*  maskraw = d_in[1];
  const float* pe    = (const float*)d_in[2];
  const float* in_w  = (const float*)d_in[3];
  const float* in_b  = (const float*)d_in[4];
  const float* time_w= (const float*)d_in[5];
  const float* time_b= (const float*)d_in[6];
  const float* qkv_w = (const float*)d_in[7];
  const float* qkv_b = (const float*)d_in[8];
  const float* out_w = (const float*)d_in[9];
  const float* out_b = (const float*)d_in[10];
  const float* ln1_g = (const float*)d_in[11];
  const float* ln1_b = (const float*)d_in[12];
  const float* ff1_w = (const float*)d_in[13];
  const float* ff1_b = (const float*)d_in[14];
  const float* ff2_w = (const float*)d_in[15];
  const float* ff2_b = (const float*)d_in[16];
  const float* ln2_g = (const float*)d_in[17];
  const float* ln2_b = (const float*)d_in[18];
  const float* reg1_w= (const float*)d_in[19];
  const float* reg1_b= (const float*)d_in[20];
  const float* reg2_w= (const float*)d_in[21];
  const float* reg2_b= (const float*)d_in[22];
  float* out = (float*)d_out;

  float *px, *pp;
  __half *pxr, *pqkvh, *poh, *phh, *pwh, *pfr;
  cudaGetSymbolAddress((void**)&px,   g_x);
  cudaGetSymbolAddress((void**)&pxr,  g_xr);
  cudaGetSymbolAddress((void**)&pqkvh,g_qkvh);
  cudaGetSymbolAddress((void**)&poh,  g_o);
  cudaGetSymbolAddress((void**)&pp,   g_p);
  cudaGetSymbolAddress((void**)&phh,  g_h);
  cudaGetSymbolAddress((void**)&pwh,  g_wh);
  cudaGetSymbolAddress((void**)&pfr,  g_fr);

  static int smem_set = 0;
  if (!smem_set) {
    cudaFuncSetAttribute(attn_mma, cudaFuncAttributeMaxDynamicSharedMemorySize, ATT_SMEM);
    cudaFuncSetAttribute(gemm_tc<2,false,true>,  cudaFuncAttributeMaxDynamicSharedMemorySize, GEMM_SMEM);
    cudaFuncSetAttribute(gemm_tc<1,false,false>, cudaFuncAttributeMaxDynamicSharedMemorySize, GEMM_SMEM);
    cudaFuncSetAttribute(gemm_tc<0,false,false>, cudaFuncAttributeMaxDynamicSharedMemorySize, GEMM_SMEM);
    cudaFuncSetAttribute(gemm_tc<1,true,false>,  cudaFuncAttributeMaxDynamicSharedMemorySize, GEMM_SMEM);
    smem_set = 1;
  }

  prep_kernel<<<B_, 1024>>>((const unsigned int*)maskraw, feat);
  wconv_kernel<<<1024, 256>>>(feat, in_w, qkv_w, out_w, ff1_w, ff2_w);
  // embed: half feat @ half in_w -> exact g_x + half g_xr, +pe
  gemm_tc<2,false,true><<<dim3(D_/64, BL_/128), 256, GEMM_SMEM>>>(
      pfr, pwh + OFF_INW, in_b, px, pxr, pe, D_, IN_);

  for (int layer = 0; layer < NL_; layer++) {
    // QKV: all half -> g_qkvh [row][768]
    gemm_tc<1,false,false><<<dim3(3*D_/64, BL_/128), 256, GEMM_SMEM>>>(
        pxr, pwh + OFF_QKVW + layer*3*D_*D_, qkv_b + layer*3*D_,
        nullptr, pqkvh, nullptr, 3*D_, D_);
    attn_mma<<<444, 128, ATT_SMEM>>>(time_w, time_b);
    gemm_tc<0,false,false><<<dim3(D_/64, BL_/128), 256, GEMM_SMEM>>>(
        poh, pwh + OFF_OUTW + layer*D_*D_, out_b + layer*D_,
        pp, nullptr, nullptr, D_, D_);
    add_ln_kernel<<<BL_/4, 256>>>(px, pp, ln1_g + layer*D_, ln1_b + layer*D_);
    gemm_tc<1,true,false><<<dim3(DFF_/64, BL_/128), 256, GEMM_SMEM>>>(
        pxr, pwh + OFF_FF1W + layer*DFF_*D_, ff1_b + layer*DFF_,
        nullptr, phh, nullptr, DFF_, D_);
    gemm_tc<0,false,false><<<dim3(D_/64, BL_/128), 256, GEMM_SMEM>>>(
        phh, pwh + OFF_FF2W + layer*D_*DFF_, ff2_b + layer*D_,
        pp, nullptr, nullptr, D_, DFF_);
    add_ln_kernel<<<BL_/4, 256>>>(px, pp, ln2_g + layer*D_, ln2_b + layer*D_);
  }

  head_kernel<<<B_, 256>>>(reg1_w, reg1_b, reg2_w, reg2_b, out, out_size);
}